// round 1
// baseline (speedup 1.0000x reference)
#include <cuda_runtime.h>
#include <math.h>

#define N_  4096
#define H_  64
#define T_  6
#define G_  16
#define TH_ 192    // 3*H
#define TD_ 384    // T*H

// ---------------- device scratch (no allocation allowed) ----------------
__device__ float g_A[H_ * TH_];          // A[m][r] = Wc[r][m], Wc = W_qkv @ W_readout
__device__ float g_W2[H_ * H_ * H_];     // W2[i][j][k] = W_tp[k][i][j]
__device__ float g_qr[N_ * TD_];         // q after silu+rope+scale, [n][t*64+d]
__device__ float g_kr[N_ * TD_];         // k after silu+rope,       [n][t*64+d]
__device__ float g_v [N_ * H_];          // v,                        [n][e]
__device__ float g_kvg[G_ * TD_ * H_];   // kv_graph [g][t*64+d][e]
__device__ float g_upd[N_ * H_];         // update   [n][e]
__device__ float g_part[2 * N_ * H_];    // two i-half partials of final GEMM
__device__ int   g_seg[G_ + 1];          // segment starts (batch is sorted)

// ---------------- K0: Wc combine: A[m][r] = sum_u W_qkv[r,u]*W_readout[u,m] ----
__global__ void k_wc(const float* __restrict__ Wqkv, const float* __restrict__ Wro) {
    int r = blockIdx.x;          // 0..191
    int m = threadIdx.x;         // 0..63
    __shared__ float srow[H_];
    srow[m] = Wqkv[r * H_ + m];
    __syncthreads();
    float s = 0.f;
#pragma unroll 8
    for (int u = 0; u < H_; u++) s += srow[u] * Wro[u * H_ + m];
    g_A[m * TH_ + r] = s;
}

// ---------------- K1: W2[i][j][k] = W_tp[k][i][j] (tiled transpose) -----------
__global__ void k_w2(const float* __restrict__ Wtp) {
    int i = blockIdx.x;          // 0..63
    __shared__ float s[64 * 65];
    int tid = threadIdx.x;       // 256
#pragma unroll
    for (int p = 0; p < 16; p++) {
        int l = p * 256 + tid;
        int k = l >> 6, j = l & 63;
        s[k * 65 + j] = Wtp[k * 4096 + i * 64 + j];   // coalesced in j
    }
    __syncthreads();
#pragma unroll
    for (int p = 0; p < 16; p++) {
        int l = p * 256 + tid;
        int j = l >> 6, k = l & 63;
        g_W2[i * 4096 + j * 64 + k] = s[k * 65 + j];  // coalesced in k
    }
}

// ---------------- K2: segment starts via binary search (batch sorted) ---------
__global__ void k_seg(const int* __restrict__ batch) {
    int g = threadIdx.x;
    if (g > G_) return;
    int lo = 0, hi = N_;
    while (lo < hi) {
        int mid = (lo + hi) >> 1;
        if (batch[mid] < g) lo = mid + 1; else hi = mid;
    }
    g_seg[g] = lo;
}

// ---------------- K3: qkv GEMV + silu + rope, per node ------------------------
__global__ void k_qkv(const float* __restrict__ node_feat,
                      const float* __restrict__ positions,
                      const float* __restrict__ kvecs,
                      const int*   __restrict__ batch) {
    int n = blockIdx.x;
    int tid = threadIdx.x;       // 192 threads
    __shared__ float s_nf[H_];
    __shared__ float s_qkv[TH_];
    __shared__ float s_c[8], s_s[8];

    if (tid < H_) s_nf[tid] = node_feat[n * H_ + tid];
    __syncthreads();

    float sum = 0.f;
#pragma unroll 8
    for (int m = 0; m < H_; m++) sum += g_A[m * TH_ + tid] * s_nf[m];

    float val = sum;
    if (tid < 2 * H_) val = val / (1.f + __expf(-val));   // silu on q,k only
    s_qkv[tid] = val;

    if (tid < T_) {
        int g = batch[n];
        const float* kv = kvecs + (g * T_ + tid) * 3;
        float ph = positions[n * 3 + 0] * kv[0]
                 + positions[n * 3 + 1] * kv[1]
                 + positions[n * 3 + 2] * kv[2];
        float sv, cv;
        sincosf(ph, &sv, &cv);
        s_c[tid] = cv; s_s[tid] = sv;
    }
    __syncthreads();

#pragma unroll
    for (int p = 0; p < 2; p++) {
        int idx = tid + 192 * p;          // 0..383
        int t = idx >> 6, d = idx & 63;
        int m2 = (d & 31) * 2;
        float c = s_c[t], s2 = s_s[t];
        float qa = s_qkv[m2],       qb = s_qkv[m2 + 1];
        float ka = s_qkv[64 + m2],  kb = s_qkv[64 + m2 + 1];
        float qv, kv;
        if (d < 32) { qv = qa * c - qb * s2;  kv = ka * c - kb * s2; }
        else        { qv = qa * s2 + qb * c;  kv = ka * s2 + kb * c; }
        g_qr[n * TD_ + idx] = qv * 0.125f;    // scale_q = 1/sqrt(64)
        g_kr[n * TD_ + idx] = kv;
    }
    if (tid < H_) g_v[n * H_ + tid] = s_qkv[128 + tid];
}

// ---------------- K4: kv_graph[g][t][d][e] = sum_{n in seg(g)} k[n,t,d]*v[n,e] -
__global__ void k_kvg() {
    int bid = blockIdx.x;        // 0..95
    int g = bid / T_, t = bid % T_;
    int tid = threadIdx.x;       // 256
    int td = tid >> 4, te = tid & 15;    // 16x16 thread grid
    int d0 = td * 4, e0 = te * 4;

    __shared__ float s_k[8][64];
    __shared__ float s_v[8][64];

    int s = g_seg[g], e = g_seg[g + 1];
    float acc[4][4];
#pragma unroll
    for (int q = 0; q < 4; q++)
#pragma unroll
        for (int c = 0; c < 4; c++) acc[q][c] = 0.f;

    for (int nb = s; nb < e; nb += 8) {
#pragma unroll
        for (int l = tid; l < 512; l += 256) {
            int r = l >> 6, c = l & 63;
            int n = nb + r;
            bool ok = n < e;
            s_k[r][c] = ok ? g_kr[n * TD_ + t * 64 + c] : 0.f;
            s_v[r][c] = ok ? g_v [n * H_ + c]           : 0.f;
        }
        __syncthreads();
#pragma unroll
        for (int r = 0; r < 8; r++) {
            float4 kd = *(const float4*)&s_k[r][d0];
            float4 ve = *(const float4*)&s_v[r][e0];
            acc[0][0] += kd.x * ve.x; acc[0][1] += kd.x * ve.y; acc[0][2] += kd.x * ve.z; acc[0][3] += kd.x * ve.w;
            acc[1][0] += kd.y * ve.x; acc[1][1] += kd.y * ve.y; acc[1][2] += kd.y * ve.z; acc[1][3] += kd.y * ve.w;
            acc[2][0] += kd.z * ve.x; acc[2][1] += kd.z * ve.y; acc[2][2] += kd.z * ve.z; acc[2][3] += kd.z * ve.w;
            acc[3][0] += kd.w * ve.x; acc[3][1] += kd.w * ve.y; acc[3][2] += kd.w * ve.z; acc[3][3] += kd.w * ve.w;
        }
        __syncthreads();
    }

    float* outb = g_kvg + (g * TD_ + t * 64) * H_;
#pragma unroll
    for (int q = 0; q < 4; q++) {
        float4 st = make_float4(acc[q][0], acc[q][1], acc[q][2], acc[q][3]);
        *(float4*)&outb[(d0 + q) * H_ + e0] = st;
    }
}

// ---------------- K5: update[n][e] = sum_{t,d} q[n,t,d]*kvg[g][t,d][e] --------
__global__ void k_upd(const int* __restrict__ batch) {
    int n0 = blockIdx.x * 16;    // 256 blocks
    int tid = threadIdx.x;       // 256
    __shared__ float s_q[16 * TD_];   // 24KB
    __shared__ int   s_b[16];

#pragma unroll
    for (int l = tid; l < 16 * TD_; l += 256) s_q[l] = g_qr[n0 * TD_ + l];
    if (tid < 16) s_b[tid] = batch[n0 + tid];
    __syncthreads();

    int nl = tid >> 4, teq = tid & 15;
    int gn = s_b[nl];
    const float* kvbase = g_kvg + gn * (TD_ * H_) + teq * 4;
    const float* qrow = s_q + nl * TD_;
    float4 acc = make_float4(0.f, 0.f, 0.f, 0.f);
#pragma unroll 4
    for (int kk = 0; kk < TD_; kk++) {
        float qv = qrow[kk];
        float4 kv = *(const float4*)(kvbase + kk * H_);
        acc.x += qv * kv.x; acc.y += qv * kv.y;
        acc.z += qv * kv.z; acc.w += qv * kv.w;
    }
    *(float4*)&g_upd[(n0 + nl) * H_ + teq * 4] = acc;
}

// ---------------- K6: out[n][k] = sum_{i,j} nfsr[n,i]*upd[n,j]*W2[i][j][k] ----
// GEMM with on-the-fly rank-1 A operand. grid (64 node-tiles, 2 i-halves).
__global__ void __launch_bounds__(256, 1) k_tp(const float* __restrict__ nfsr) {
    __shared__ float s_updT[64 * 68];   // [j][n], pad 68 keeps LDS.128 aligned
    __shared__ float s_nf  [32 * 68];   // [ii][n]
    __shared__ float s_w   [64 * 64];   // [j][k]

    int tid = threadIdx.x;              // 256
    int tn = tid >> 4, tk = tid & 15;   // thread tile: 4 n x 4 k
    int n0 = blockIdx.x * 64;
    int i0 = blockIdx.y * 32;

#pragma unroll
    for (int l = tid; l < 4096; l += 256) {
        int nl = l >> 6, j = l & 63;
        s_updT[j * 68 + nl] = g_upd[(n0 + nl) * H_ + j];
    }
#pragma unroll
    for (int l = tid; l < 2048; l += 256) {
        int nl = l >> 5, ii = l & 31;
        s_nf[ii * 68 + nl] = nfsr[(n0 + nl) * H_ + i0 + ii];
    }
    __syncthreads();

    float acc[16];
#pragma unroll
    for (int q = 0; q < 16; q++) acc[q] = 0.f;

    for (int ii = 0; ii < 32; ii++) {
        const float* wsrc = g_W2 + (i0 + ii) * 4096;
#pragma unroll
        for (int p = 0; p < 16; p++) {
            int l = p * 256 + tid;
            s_w[l] = wsrc[l];           // [j][k], coalesced, conflict-free STS
        }
        __syncthreads();

        float4 a = *(const float4*)&s_nf[ii * 68 + 4 * tn];
#pragma unroll 8
        for (int j = 0; j < 64; j++) {
            float4 u = *(const float4*)&s_updT[j * 68 + 4 * tn];
            float4 w = *(const float4*)&s_w[j * 64 + 4 * tk];
            float m0 = a.x * u.x, m1 = a.y * u.y, m2 = a.z * u.z, m3 = a.w * u.w;
            acc[ 0] += m0 * w.x; acc[ 1] += m0 * w.y; acc[ 2] += m0 * w.z; acc[ 3] += m0 * w.w;
            acc[ 4] += m1 * w.x; acc[ 5] += m1 * w.y; acc[ 6] += m1 * w.z; acc[ 7] += m1 * w.w;
            acc[ 8] += m2 * w.x; acc[ 9] += m2 * w.y; acc[10] += m2 * w.z; acc[11] += m2 * w.w;
            acc[12] += m3 * w.x; acc[13] += m3 * w.y; acc[14] += m3 * w.z; acc[15] += m3 * w.w;
        }
        __syncthreads();
    }

    float* part = g_part + blockIdx.y * (N_ * H_);
#pragma unroll
    for (int q = 0; q < 4; q++) {
        int n = n0 + 4 * tn + q;
        float4 st = make_float4(acc[q * 4 + 0], acc[q * 4 + 1], acc[q * 4 + 2], acc[q * 4 + 3]);
        *(float4*)&part[n * H_ + 4 * tk] = st;
    }
}

// ---------------- K7: sum the two i-half partials -----------------------------
__global__ void k_sum(float* __restrict__ out) {
    int idx = (blockIdx.x * 256 + threadIdx.x) * 4;
    float4 a = *(const float4*)&g_part[idx];
    float4 b = *(const float4*)&g_part[N_ * H_ + idx];
    float4 r = make_float4(a.x + b.x, a.y + b.y, a.z + b.z, a.w + b.w);
    *(float4*)&out[idx] = r;
}

// ---------------- launch -------------------------------------------------------
extern "C" void kernel_launch(void* const* d_in, const int* in_sizes, int n_in,
                              void* d_out, int out_size) {
    const float* node_feat    = (const float*)d_in[0];
    const float* node_feat_sr = (const float*)d_in[1];
    const float* positions    = (const float*)d_in[2];
    const float* kvecs        = (const float*)d_in[3];
    const int*   batch        = (const int*)  d_in[4];
    const float* W_readout    = (const float*)d_in[5];
    const float* W_qkv        = (const float*)d_in[6];
    const float* W_tp         = (const float*)d_in[7];
    float* out = (float*)d_out;

    k_wc <<<TH_, H_>>>(W_qkv, W_readout);
    k_w2 <<<H_, 256>>>(W_tp);
    k_seg<<<1, 32>>>(batch);
    k_qkv<<<N_, TH_>>>(node_feat, positions, kvecs, batch);
    k_kvg<<<G_ * T_, 256>>>();
    k_upd<<<N_ / 16, 256>>>(batch);
    k_tp <<<dim3(N_ / 64, 2), 256>>>(node_feat_sr);
    k_sum<<<(N_ * H_) / (256 * 4), 256>>>(out);
}

// round 2
// speedup vs baseline: 1.0403x; 1.0403x over previous
#include <cuda_runtime.h>
#include <math.h>

#define N_  4096
#define H_  64
#define T_  6
#define G_  16
#define TH_ 192    // 3*H
#define TD_ 384    // T*H

typedef unsigned long long ull;

// ---------------- packed f32x2 helpers ----------------
__device__ __forceinline__ ull pk2(float lo, float hi) {
    ull r; asm("mov.b64 %0, {%1,%2};" : "=l"(r) : "f"(lo), "f"(hi)); return r;
}
__device__ __forceinline__ float2 upk2(ull v) {
    float2 f; asm("mov.b64 {%0,%1}, %2;" : "=f"(f.x), "=f"(f.y) : "l"(v)); return f;
}
__device__ __forceinline__ ull mul2(ull a, ull b) {
    ull d; asm("mul.rn.f32x2 %0, %1, %2;" : "=l"(d) : "l"(a), "l"(b)); return d;
}
__device__ __forceinline__ ull fma2(ull a, ull b, ull c) {
    ull d; asm("fma.rn.f32x2 %0, %1, %2, %3;" : "=l"(d) : "l"(a), "l"(b), "l"(c)); return d;
}

// ---------------- device scratch ----------------
__device__ float g_A[H_ * TH_];          // A[m][r] = Wc[r][m]
__device__ float g_W2[H_ * H_ * H_];     // W2[i][j][k] = W_tp[k][i][j]
__device__ float g_qr[N_ * TD_];         // q (silu+rope+scale), [n][t*64+d]
__device__ float g_kr[N_ * TD_];         // k (silu+rope),       [n][t*64+d]
__device__ float g_v [N_ * H_];          // v [n][e]
__device__ float g_kvg[G_ * TD_ * H_];   // kv_graph [g][t*64+d][e]
__device__ float g_updT[H_ * N_];        // update TRANSPOSED [j][n]
__device__ float g_part[4 * N_ * H_];    // four i-quarter partials
__device__ int   g_seg[G_ + 1];
__device__ int   g_tblg[256];            // k_upd block table: graph id
__device__ int   g_tbln[256];            // k_upd block table: node start
__device__ int   g_nblk;

// ---------------- K0: A[m][r] = sum_u W_qkv[r,u]*W_readout[u,m] ----------------
__global__ void k_wc(const float* __restrict__ Wqkv, const float* __restrict__ Wro) {
    int r = blockIdx.x;          // 0..191
    int m = threadIdx.x;         // 0..63
    __shared__ float srow[H_];
    srow[m] = Wqkv[r * H_ + m];
    __syncthreads();
    float s = 0.f;
#pragma unroll 8
    for (int u = 0; u < H_; u++) s += srow[u] * Wro[u * H_ + m];
    g_A[m * TH_ + r] = s;
}

// ---------------- K1: W2[i][j][k] = W_tp[k][i][j] ----------------
__global__ void k_w2(const float* __restrict__ Wtp) {
    int i = blockIdx.x;
    __shared__ float s[64 * 65];
    int tid = threadIdx.x;       // 256
#pragma unroll
    for (int p = 0; p < 16; p++) {
        int l = p * 256 + tid;
        int k = l >> 6, j = l & 63;
        s[k * 65 + j] = Wtp[k * 4096 + i * 64 + j];
    }
    __syncthreads();
#pragma unroll
    for (int p = 0; p < 16; p++) {
        int l = p * 256 + tid;
        int j = l >> 6, k = l & 63;
        g_W2[i * 4096 + j * 64 + k] = s[k * 65 + j];
    }
}

// ---------------- K2: segment starts + k_upd block table ----------------
__global__ void k_seg(const int* __restrict__ batch) {
    int g = threadIdx.x;
    if (g <= G_) {
        int lo = 0, hi = N_;
        while (lo < hi) {
            int mid = (lo + hi) >> 1;
            if (batch[mid] < g) lo = mid + 1; else hi = mid;
        }
        g_seg[g] = lo;
    }
    __syncthreads();
    if (threadIdx.x == 0) {
        int b = 0;
        for (int gg = 0; gg < G_; gg++) {
            for (int s = g_seg[gg]; s < g_seg[gg + 1]; s += 32) {
                g_tblg[b] = gg;
                g_tbln[b] = s;
                b++;
            }
        }
        g_nblk = b;
    }
}

// ---------------- K3: qkv GEMM (8 nodes/block) + silu + rope ----------------
__global__ void k_qkv(const float* __restrict__ node_feat,
                      const float* __restrict__ positions,
                      const float* __restrict__ kvecs,
                      const int*   __restrict__ batch) {
    int n0 = blockIdx.x * 8;
    int tid = threadIdx.x;       // 192 threads: one r each
    __shared__ float s_nf[8][64];
    __shared__ float s_qkv[8][200];
    __shared__ float s_c[8][8], s_s[8][8];

    // load 8 node feature rows
    for (int l = tid; l < 512; l += TH_) {
        int nn = l >> 6, m = l & 63;
        s_nf[nn][m] = node_feat[(n0 + nn) * H_ + m];
    }
    __syncthreads();

    float acc[8];
#pragma unroll
    for (int nn = 0; nn < 8; nn++) acc[nn] = 0.f;

#pragma unroll 4
    for (int m = 0; m < H_; m += 4) {
        float a0 = g_A[(m + 0) * TH_ + tid];
        float a1 = g_A[(m + 1) * TH_ + tid];
        float a2 = g_A[(m + 2) * TH_ + tid];
        float a3 = g_A[(m + 3) * TH_ + tid];
#pragma unroll
        for (int nn = 0; nn < 8; nn++) {
            float4 f = *(const float4*)&s_nf[nn][m];
            acc[nn] += a0 * f.x + a1 * f.y + a2 * f.z + a3 * f.w;
        }
    }

#pragma unroll
    for (int nn = 0; nn < 8; nn++) {
        float v = acc[nn];
        if (tid < 2 * H_) v = v / (1.f + __expf(-v));   // silu on q,k
        s_qkv[nn][tid] = v;
    }

    if (tid < 48) {
        int nn = tid / 6, t = tid % 6;
        int g = batch[n0 + nn];
        const float* kv = kvecs + (g * T_ + t) * 3;
        float ph = positions[(n0 + nn) * 3 + 0] * kv[0]
                 + positions[(n0 + nn) * 3 + 1] * kv[1]
                 + positions[(n0 + nn) * 3 + 2] * kv[2];
        float sv, cv;
        sincosf(ph, &sv, &cv);
        s_c[nn][t] = cv; s_s[nn][t] = sv;
    }
    __syncthreads();

    for (int l = tid; l < 8 * TD_; l += TH_) {
        int nn = l / TD_;
        int idx = l - nn * TD_;
        int t = idx >> 6, d = idx & 63;
        int m2 = (d & 31) * 2;
        float c = s_c[nn][t], s2v = s_s[nn][t];
        float qa = s_qkv[nn][m2],      qb = s_qkv[nn][m2 + 1];
        float ka = s_qkv[nn][64 + m2], kb = s_qkv[nn][64 + m2 + 1];
        float qv, kvv;
        if (d < 32) { qv = qa * c   - qb * s2v;  kvv = ka * c   - kb * s2v; }
        else        { qv = qa * s2v + qb * c;    kvv = ka * s2v + kb * c;   }
        int n = n0 + nn;
        g_qr[n * TD_ + idx] = qv * 0.125f;
        g_kr[n * TD_ + idx] = kvv;
    }
    for (int l = tid; l < 8 * H_; l += TH_) {
        int nn = l >> 6, m = l & 63;
        g_v[(n0 + nn) * H_ + m] = s_qkv[nn][128 + m];
    }
}

// ---------------- K4: kv_graph, e-split (grid 96 x 2) ----------------
__global__ void k_kvg() {
    int bid = blockIdx.x;        // 0..95
    int g = bid / T_, t = bid % T_;
    int eh = blockIdx.y;         // e-half: 0/1
    int tid = threadIdx.x;       // 256
    int td = tid >> 4, te = tid & 15;
    int d0 = td * 4, e0 = te * 2;

    __shared__ float s_k[8][64];
    __shared__ float s_v[8][32];

    int s = g_seg[g], e = g_seg[g + 1];
    float acc[4][2];
#pragma unroll
    for (int q = 0; q < 4; q++) { acc[q][0] = 0.f; acc[q][1] = 0.f; }

    for (int nb = s; nb < e; nb += 8) {
        for (int l = tid; l < 512; l += 256) {
            int r = l >> 6, c = l & 63;
            int n = nb + r;
            s_k[r][c] = (n < e) ? g_kr[n * TD_ + t * 64 + c] : 0.f;
        }
        {
            int r = tid >> 5, c = tid & 31;
            int n = nb + r;
            s_v[r][c] = (n < e) ? g_v[n * H_ + eh * 32 + c] : 0.f;
        }
        __syncthreads();
#pragma unroll
        for (int r = 0; r < 8; r++) {
            float4 kd = *(const float4*)&s_k[r][d0];
            float2 ve = *(const float2*)&s_v[r][e0];
            acc[0][0] += kd.x * ve.x; acc[0][1] += kd.x * ve.y;
            acc[1][0] += kd.y * ve.x; acc[1][1] += kd.y * ve.y;
            acc[2][0] += kd.z * ve.x; acc[2][1] += kd.z * ve.y;
            acc[3][0] += kd.w * ve.x; acc[3][1] += kd.w * ve.y;
        }
        __syncthreads();
    }

    float* outb = g_kvg + (g * TD_ + t * 64) * H_ + eh * 32;
#pragma unroll
    for (int q = 0; q < 4; q++)
        *(float2*)&outb[(d0 + q) * H_ + e0] = make_float2(acc[q][0], acc[q][1]);
}

// ---------------- K5: update (segment-tiled GEMM), writes g_updT ----------------
__global__ void k_upd() {
    int b = blockIdx.x;
    if (b >= g_nblk) return;
    int g  = g_tblg[b];
    int ns = g_tbln[b];
    int ne = min(ns + 32, g_seg[g + 1]);

    int tid = threadIdx.x;       // 256
    int tn = tid >> 4, te = tid & 15;   // 2 n x 4 e per thread

    __shared__ float s_q[32][65];
    __shared__ float s_kv[64][64];

    float acc[2][4];
#pragma unroll
    for (int r = 0; r < 2; r++)
#pragma unroll
        for (int c = 0; c < 4; c++) acc[r][c] = 0.f;

    const float* kvg = g_kvg + g * (TD_ * H_);
    for (int ch = 0; ch < 6; ch++) {
        int kk0 = ch * 64;
#pragma unroll
        for (int p = 0; p < 16; p++) {
            int l = p * 256 + tid;
            int kl = l >> 6, ee = l & 63;
            s_kv[kl][ee] = kvg[(kk0 + kl) * H_ + ee];
        }
#pragma unroll
        for (int p = 0; p < 8; p++) {
            int l = p * 256 + tid;
            int nl = l >> 6, kl = l & 63;
            int n = ns + nl;
            s_q[nl][kl] = (n < ne) ? g_qr[n * TD_ + kk0 + kl] : 0.f;
        }
        __syncthreads();
#pragma unroll 8
        for (int kk = 0; kk < 64; kk++) {
            float q0 = s_q[tn * 2][kk];
            float q1 = s_q[tn * 2 + 1][kk];
            float4 kv = *(const float4*)&s_kv[kk][te * 4];
            acc[0][0] += q0 * kv.x; acc[0][1] += q0 * kv.y; acc[0][2] += q0 * kv.z; acc[0][3] += q0 * kv.w;
            acc[1][0] += q1 * kv.x; acc[1][1] += q1 * kv.y; acc[1][2] += q1 * kv.z; acc[1][3] += q1 * kv.w;
        }
        __syncthreads();
    }

#pragma unroll
    for (int r = 0; r < 2; r++) {
        int n = ns + tn * 2 + r;
        if (n < ne) {
#pragma unroll
            for (int c = 0; c < 4; c++)
                g_updT[(te * 4 + c) * N_ + n] = acc[r][c];
        }
    }
}

// ---------------- K6: tensor-product GEMM with f32x2 packed math -------------
// out[n][k] = sum_i nfsr[n,i] * sum_j upd[n,j] * W2[i][j][k]
// n-tile 128, i-quarter 16 per block; grid (32, 4) = 128 blocks.
__global__ void __launch_bounds__(256) k_tp(const float* __restrict__ nfsr) {
    __shared__ float s_u[64 * 128];     // [j][n-local]  32KB
    __shared__ float s_w[64 * 64];      // [j][k]        16KB

    int tid = threadIdx.x;
    int tn = tid >> 4, tk = tid & 15;
    int tn4 = tn * 4, tk4 = tk * 4;
    int n0 = blockIdx.x * 128;
    int i0 = blockIdx.y * 16;

    for (int l = tid; l < 8192; l += 256) {
        int j = l >> 7, nl = l & 127;
        s_u[l] = g_updT[j * N_ + n0 + nl];     // coalesced
    }

    ull acc[4][4];
#pragma unroll
    for (int p = 0; p < 4; p++)
#pragma unroll
        for (int c = 0; c < 4; c++) acc[p][c] = 0ULL;

    for (int ii = 0; ii < 16; ii++) {
        __syncthreads();
        const float4* wsrc = (const float4*)(g_W2 + (i0 + ii) * 4096);
        float4* wdst = (float4*)s_w;
#pragma unroll
        for (int p = 0; p < 4; p++) wdst[p * 256 + tid] = wsrc[p * 256 + tid];
        __syncthreads();

        int icol = i0 + ii;
        float a0 = nfsr[(n0 + tn4 + 0) * H_ + icol];
        float a1 = nfsr[(n0 + tn4 + 1) * H_ + icol];
        float a2v = nfsr[(n0 + tn4 + 2) * H_ + icol];
        float a3 = nfsr[(n0 + tn4 + 3) * H_ + icol];
        float b0 = nfsr[(n0 + tn4 + 64) * H_ + icol];
        float b1 = nfsr[(n0 + tn4 + 65) * H_ + icol];
        float b2 = nfsr[(n0 + tn4 + 66) * H_ + icol];
        float b3 = nfsr[(n0 + tn4 + 67) * H_ + icol];
        ull ap0 = pk2(a0, a1), ap1 = pk2(a2v, a3);
        ull ap2 = pk2(b0, b1), ap3 = pk2(b2, b3);

#pragma unroll 8
        for (int j = 0; j < 64; j++) {
            ulonglong2 uA = *(const ulonglong2*)&s_u[j * 128 + tn4];
            ulonglong2 uB = *(const ulonglong2*)&s_u[j * 128 + tn4 + 64];
            ull y0 = mul2(ap0, uA.x);
            ull y1 = mul2(ap1, uA.y);
            ull y2 = mul2(ap2, uB.x);
            ull y3 = mul2(ap3, uB.y);
            float4 w = *(const float4*)&s_w[j * 64 + tk4];
            ull w0 = pk2(w.x, w.x), w1 = pk2(w.y, w.y);
            ull w2 = pk2(w.z, w.z), w3 = pk2(w.w, w.w);
            acc[0][0] = fma2(y0, w0, acc[0][0]); acc[0][1] = fma2(y0, w1, acc[0][1]);
            acc[0][2] = fma2(y0, w2, acc[0][2]); acc[0][3] = fma2(y0, w3, acc[0][3]);
            acc[1][0] = fma2(y1, w0, acc[1][0]); acc[1][1] = fma2(y1, w1, acc[1][1]);
            acc[1][2] = fma2(y1, w2, acc[1][2]); acc[1][3] = fma2(y1, w3, acc[1][3]);
            acc[2][0] = fma2(y2, w0, acc[2][0]); acc[2][1] = fma2(y2, w1, acc[2][1]);
            acc[2][2] = fma2(y2, w2, acc[2][2]); acc[2][3] = fma2(y2, w3, acc[2][3]);
            acc[3][0] = fma2(y3, w0, acc[3][0]); acc[3][1] = fma2(y3, w1, acc[3][1]);
            acc[3][2] = fma2(y3, w2, acc[3][2]); acc[3][3] = fma2(y3, w3, acc[3][3]);
        }
    }

    float* part = g_part + blockIdx.y * (N_ * H_);
#pragma unroll
    for (int p = 0; p < 4; p++) {
        int nbase = (p < 2) ? (tn4 + p * 2) : (tn4 + 64 + (p - 2) * 2);
        float2 f0 = upk2(acc[p][0]), f1 = upk2(acc[p][1]);
        float2 f2 = upk2(acc[p][2]), f3 = upk2(acc[p][3]);
        *(float4*)&part[(n0 + nbase    ) * H_ + tk4] = make_float4(f0.x, f1.x, f2.x, f3.x);
        *(float4*)&part[(n0 + nbase + 1) * H_ + tk4] = make_float4(f0.y, f1.y, f2.y, f3.y);
    }
}

// ---------------- K7: sum the four i-quarter partials ----------------
__global__ void k_sum(float* __restrict__ out) {
    int idx = (blockIdx.x * 256 + threadIdx.x) * 4;
    float4 a = *(const float4*)&g_part[idx];
    float4 b = *(const float4*)&g_part[N_ * H_ + idx];
    float4 c = *(const float4*)&g_part[2 * N_ * H_ + idx];
    float4 d = *(const float4*)&g_part[3 * N_ * H_ + idx];
    *(float4*)&out[idx] = make_float4(a.x + b.x + c.x + d.x,
                                      a.y + b.y + c.y + d.y,
                                      a.z + b.z + c.z + d.z,
                                      a.w + b.w + c.w + d.w);
}

// ---------------- launch ----------------
extern "C" void kernel_launch(void* const* d_in, const int* in_sizes, int n_in,
                              void* d_out, int out_size) {
    const float* node_feat    = (const float*)d_in[0];
    const float* node_feat_sr = (const float*)d_in[1];
    const float* positions    = (const float*)d_in[2];
    const float* kvecs        = (const float*)d_in[3];
    const int*   batch        = (const int*)  d_in[4];
    const float* W_readout    = (const float*)d_in[5];
    const float* W_qkv        = (const float*)d_in[6];
    const float* W_tp         = (const float*)d_in[7];
    float* out = (float*)d_out;

    k_wc <<<TH_, H_>>>(W_qkv, W_readout);
    k_w2 <<<H_, 256>>>(W_tp);
    k_seg<<<1, 32>>>(batch);
    k_qkv<<<N_ / 8, TH_>>>(node_feat, positions, kvecs, batch);
    k_kvg<<<dim3(G_ * T_, 2), 256>>>();
    k_upd<<<160, 256>>>();
    k_tp <<<dim3(N_ / 128, 4), 256>>>(node_feat_sr);
    k_sum<<<(N_ * H_) / (256 * 4), 256>>>(out);
}

// round 4
// speedup vs baseline: 1.3213x; 1.2701x over previous
#include <cuda_runtime.h>
#include <cuda_bf16.h>
#include <math.h>
#include <stdint.h>

#define N_  4096
#define H_  64
#define T_  6
#define G_  16
#define TH_ 192    // 3*H
#define TD_ 384    // T*H

// ---------------- device scratch ----------------
__device__ float g_A[H_ * TH_];            // A[m][r] = Wc[r][m]
__device__ float g_qr[N_ * TD_];           // q (silu+rope+scale), [n][t*64+d]
__device__ float g_kr[N_ * TD_];           // k (silu+rope),       [n][t*64+d]
__device__ float g_v [N_ * H_];            // v [n][e]
__device__ float g_kvg[G_ * TD_ * H_];     // kv_graph [g][t*64+d][e]
__device__ float g_updT[H_ * N_];          // update TRANSPOSED [j][n]
__device__ float g_part[4 * N_ * H_];      // four i-quarter partials
__device__ __nv_bfloat16 g_Bh[H_ * H_ * H_];  // W_tp split hi, [i][j][k]
__device__ __nv_bfloat16 g_Bl[H_ * H_ * H_];  // W_tp split lo, [i][j][k]
__device__ int   g_seg[G_ + 1];
__device__ int   g_tblg[256];
__device__ int   g_tbln[256];
__device__ int   g_nblk;

// ---------------- PTX helpers (baseline ISA only: ldmatrix + mma.sync) --------
__device__ __forceinline__ uint32_t smem_u32(const void* p) {
    uint32_t a;
    asm("{ .reg .u64 t; cvta.to.shared.u64 t, %1; cvt.u32.u64 %0, t; }" : "=r"(a) : "l"(p));
    return a;
}
#define LDSM_X4(r, addr) \
    asm volatile("ldmatrix.sync.aligned.m8n8.x4.shared.b16 {%0,%1,%2,%3}, [%4];" \
        : "=r"((r)[0]), "=r"((r)[1]), "=r"((r)[2]), "=r"((r)[3]) : "r"(addr))
#define LDSM_X4T(r, addr) \
    asm volatile("ldmatrix.sync.aligned.m8n8.x4.trans.shared.b16 {%0,%1,%2,%3}, [%4];" \
        : "=r"((r)[0]), "=r"((r)[1]), "=r"((r)[2]), "=r"((r)[3]) : "r"(addr))

__device__ __forceinline__ void mma16816(float* d, const uint32_t* a, const uint32_t* b) {
    asm volatile(
        "mma.sync.aligned.m16n8k16.row.col.f32.bf16.bf16.f32 "
        "{%0,%1,%2,%3}, {%4,%5,%6,%7}, {%8,%9}, {%0,%1,%2,%3};"
        : "+f"(d[0]), "+f"(d[1]), "+f"(d[2]), "+f"(d[3])
        : "r"(a[0]), "r"(a[1]), "r"(a[2]), "r"(a[3]), "r"(b[0]), "r"(b[1]));
}

// ---------------- K0: A[m][r] = sum_u W_qkv[r,u]*W_readout[u,m] ----------------
__global__ void k_wc(const float* __restrict__ Wqkv, const float* __restrict__ Wro) {
    int r = blockIdx.x;          // 0..191
    int m = threadIdx.x;         // 0..63
    __shared__ float srow[H_];
    srow[m] = Wqkv[r * H_ + m];
    __syncthreads();
    float s = 0.f;
#pragma unroll 8
    for (int u = 0; u < H_; u++) s += srow[u] * Wro[u * H_ + m];
    g_A[m * TH_ + r] = s;
}

// ---------------- K1: split W_tp into bf16 hi/lo, layout [i][j][k] ------------
__global__ void k_bprep(const float* __restrict__ Wtp) {
    int i = blockIdx.x;
    int tid = threadIdx.x;       // 256
    __shared__ float s[64 * 65];
#pragma unroll
    for (int p = 0; p < 16; p++) {
        int l = p * 256 + tid;
        int k = l >> 6, j = l & 63;
        s[k * 65 + j] = Wtp[k * 4096 + i * 64 + j];   // coalesced in j
    }
    __syncthreads();
#pragma unroll
    for (int p = 0; p < 16; p++) {
        int l = p * 256 + tid;
        int j = l >> 6, k = l & 63;
        float w = s[k * 65 + j];
        __nv_bfloat16 hi = __float2bfloat16(w);
        __nv_bfloat16 lo = __float2bfloat16(w - __bfloat162float(hi));
        g_Bh[i * 4096 + j * 64 + k] = hi;             // coalesced in k
        g_Bl[i * 4096 + j * 64 + k] = lo;
    }
}

// ---------------- K2: segment starts + k_upd block table ----------------
__global__ void k_seg(const int* __restrict__ batch) {
    int g = threadIdx.x;
    if (g <= G_) {
        int lo = 0, hi = N_;
        while (lo < hi) {
            int mid = (lo + hi) >> 1;
            if (batch[mid] < g) lo = mid + 1; else hi = mid;
        }
        g_seg[g] = lo;
    }
    __syncthreads();
    if (threadIdx.x == 0) {
        int b = 0;
        for (int gg = 0; gg < G_; gg++)
            for (int s = g_seg[gg]; s < g_seg[gg + 1]; s += 32) {
                g_tblg[b] = gg; g_tbln[b] = s; b++;
            }
        g_nblk = b;
    }
}

// ---------------- K3: qkv GEMM (16 nodes/block) + silu + rope ----------------
__global__ void k_qkv(const float* __restrict__ node_feat,
                      const float* __restrict__ positions,
                      const float* __restrict__ kvecs,
                      const int*   __restrict__ batch) {
    int n0 = blockIdx.x * 16;
    int tid = threadIdx.x;       // 192
    __shared__ float s_nf[16][64];
    __shared__ float s_qkv[16][200];
    __shared__ float s_c[16][8], s_s[16][8];

    for (int l = tid; l < 1024; l += TH_) {
        int nn = l >> 6, m = l & 63;
        s_nf[nn][m] = node_feat[(n0 + nn) * H_ + m];
    }
    __syncthreads();

    float acc[16];
#pragma unroll
    for (int nn = 0; nn < 16; nn++) acc[nn] = 0.f;

#pragma unroll 4
    for (int m = 0; m < H_; m += 4) {
        float a0 = g_A[(m + 0) * TH_ + tid];
        float a1 = g_A[(m + 1) * TH_ + tid];
        float a2 = g_A[(m + 2) * TH_ + tid];
        float a3 = g_A[(m + 3) * TH_ + tid];
#pragma unroll
        for (int nn = 0; nn < 16; nn++) {
            float4 f = *(const float4*)&s_nf[nn][m];   // warp-broadcast LDS
            acc[nn] += a0 * f.x + a1 * f.y + a2 * f.z + a3 * f.w;
        }
    }

#pragma unroll
    for (int nn = 0; nn < 16; nn++) {
        float v = acc[nn];
        if (tid < 2 * H_) v = v / (1.f + __expf(-v));   // silu on q,k
        s_qkv[nn][tid] = v;
    }

    if (tid < 96) {
        int nn = tid / 6, t = tid % 6;
        int g = batch[n0 + nn];
        const float* kv = kvecs + (g * T_ + t) * 3;
        float ph = positions[(n0 + nn) * 3 + 0] * kv[0]
                 + positions[(n0 + nn) * 3 + 1] * kv[1]
                 + positions[(n0 + nn) * 3 + 2] * kv[2];
        float sv, cv;
        sincosf(ph, &sv, &cv);
        s_c[nn][t] = cv; s_s[nn][t] = sv;
    }
    __syncthreads();

    for (int l = tid; l < 16 * TD_; l += TH_) {
        int nn = l / TD_;
        int idx = l - nn * TD_;
        int t = idx >> 6, d = idx & 63;
        int m2 = (d & 31) * 2;
        float c = s_c[nn][t], s2v = s_s[nn][t];
        float qa = s_qkv[nn][m2],      qb = s_qkv[nn][m2 + 1];
        float ka = s_qkv[nn][64 + m2], kb = s_qkv[nn][64 + m2 + 1];
        float qv, kvv;
        if (d < 32) { qv = qa * c   - qb * s2v;  kvv = ka * c   - kb * s2v; }
        else        { qv = qa * s2v + qb * c;    kvv = ka * s2v + kb * c;   }
        int n = n0 + nn;
        g_qr[n * TD_ + idx] = qv * 0.125f;
        g_kr[n * TD_ + idx] = kvv;
    }
    for (int l = tid; l < 16 * H_; l += TH_) {
        int nn = l >> 6, m = l & 63;
        g_v[(n0 + nn) * H_ + m] = s_qkv[nn][128 + m];
    }
}

// ---------------- K4: kv_graph, e-split ----------------
__global__ void k_kvg() {
    int bid = blockIdx.x;
    int g = bid / T_, t = bid % T_;
    int eh = blockIdx.y;
    int tid = threadIdx.x;
    int td = tid >> 4, te = tid & 15;
    int d0 = td * 4, e0 = te * 2;

    __shared__ float s_k[8][64];
    __shared__ float s_v[8][32];

    int s = g_seg[g], e = g_seg[g + 1];
    float acc[4][2];
#pragma unroll
    for (int q = 0; q < 4; q++) { acc[q][0] = 0.f; acc[q][1] = 0.f; }

    for (int nb = s; nb < e; nb += 8) {
        for (int l = tid; l < 512; l += 256) {
            int r = l >> 6, c = l & 63;
            int n = nb + r;
            s_k[r][c] = (n < e) ? g_kr[n * TD_ + t * 64 + c] : 0.f;
        }
        {
            int r = tid >> 5, c = tid & 31;
            int n = nb + r;
            s_v[r][c] = (n < e) ? g_v[n * H_ + eh * 32 + c] : 0.f;
        }
        __syncthreads();
#pragma unroll
        for (int r = 0; r < 8; r++) {
            float4 kd = *(const float4*)&s_k[r][d0];
            float2 ve = *(const float2*)&s_v[r][e0];
            acc[0][0] += kd.x * ve.x; acc[0][1] += kd.x * ve.y;
            acc[1][0] += kd.y * ve.x; acc[1][1] += kd.y * ve.y;
            acc[2][0] += kd.z * ve.x; acc[2][1] += kd.z * ve.y;
            acc[3][0] += kd.w * ve.x; acc[3][1] += kd.w * ve.y;
        }
        __syncthreads();
    }

    float* outb = g_kvg + (g * TD_ + t * 64) * H_ + eh * 32;
#pragma unroll
    for (int q = 0; q < 4; q++)
        *(float2*)&outb[(d0 + q) * H_ + e0] = make_float2(acc[q][0], acc[q][1]);
}

// ---------------- K5: update (segment-tiled GEMM), writes g_updT ----------------
__global__ void k_upd() {
    int b = blockIdx.x;
    if (b >= g_nblk) return;
    int g  = g_tblg[b];
    int ns = g_tbln[b];
    int ne = min(ns + 32, g_seg[g + 1]);

    int tid = threadIdx.x;
    int tn = tid >> 4, te = tid & 15;

    __shared__ float s_q[32][65];
    __shared__ float s_kv[64][64];

    float acc[2][4];
#pragma unroll
    for (int r = 0; r < 2; r++)
#pragma unroll
        for (int c = 0; c < 4; c++) acc[r][c] = 0.f;

    const float* kvg = g_kvg + g * (TD_ * H_);
    for (int ch = 0; ch < 6; ch++) {
        int kk0 = ch * 64;
#pragma unroll
        for (int p = 0; p < 16; p++) {
            int l = p * 256 + tid;
            int kl = l >> 6, ee = l & 63;
            s_kv[kl][ee] = kvg[(kk0 + kl) * H_ + ee];
        }
#pragma unroll
        for (int p = 0; p < 8; p++) {
            int l = p * 256 + tid;
            int nl = l >> 6, kl = l & 63;
            int n = ns + nl;
            s_q[nl][kl] = (n < ne) ? g_qr[n * TD_ + kk0 + kl] : 0.f;
        }
        __syncthreads();
#pragma unroll 8
        for (int kk = 0; kk < 64; kk++) {
            float q0 = s_q[tn * 2][kk];
            float q1 = s_q[tn * 2 + 1][kk];
            float4 kv = *(const float4*)&s_kv[kk][te * 4];
            acc[0][0] += q0 * kv.x; acc[0][1] += q0 * kv.y; acc[0][2] += q0 * kv.z; acc[0][3] += q0 * kv.w;
            acc[1][0] += q1 * kv.x; acc[1][1] += q1 * kv.y; acc[1][2] += q1 * kv.z; acc[1][3] += q1 * kv.w;
        }
        __syncthreads();
    }

#pragma unroll
    for (int r = 0; r < 2; r++) {
        int n = ns + tn * 2 + r;
        if (n < ne) {
#pragma unroll
            for (int c = 0; c < 4; c++)
                g_updT[(te * 4 + c) * N_ + n] = acc[r][c];
        }
    }
}

// ---------------- K6: tensor-product GEMM via mma.sync bf16 3-pass split ------
// D[128 n x 64 k] = sum_{c=0..15} A_c @ B_c^T,  A_c[n][j] = nfsr[n,i0+c]*upd[n,j]
// SMEM (bytes): A_HI 0 (128x72 bf16), A_LO 18432, B_HI 36864 (64x72 bf16),
//               B_LO 46080, NF 55296 (16x128 f32), UPDF 63488 (128x66 f32)
#define A_HI   0
#define A_LO   18432
#define B_HI   36864
#define B_LO   46080
#define SM_NF  55296
#define SM_UPDF 63488
#define SMEM_TOT 97280
#define RSTRIDE 144   // 72 bf16 row stride (bytes)

__global__ void __launch_bounds__(256) k_tpmma(const float* __restrict__ nfsr) {
    extern __shared__ char smem[];
    uint32_t sb = smem_u32(smem);
    int tid = threadIdx.x;
    int wid = tid >> 5, lane = tid & 31;
    int n0 = blockIdx.x * 128;
    int i0 = blockIdx.y * 16;

    float* s_nf   = (float*)(smem + SM_NF);     // [ii][128]
    float* s_updf = (float*)(smem + SM_UPDF);   // [nl][66]

#pragma unroll
    for (int p = 0; p < 8; p++) {
        int l = p * 256 + tid;
        int nl = l >> 4, ii = l & 15;
        s_nf[ii * 128 + nl] = nfsr[(n0 + nl) * H_ + i0 + ii];
    }
#pragma unroll
    for (int p = 0; p < 32; p++) {
        int l = p * 256 + tid;
        int j = l >> 7, nl = l & 127;
        s_updf[nl * 66 + j] = g_updT[j * N_ + n0 + nl];   // coalesced LDG
    }

    // per-thread ldmatrix addresses
    int m0 = wid * 16;
    int rfr = (lane & 7) + ((lane >> 3) & 1) * 8;   // fragment row
    int cfr = (lane >> 4) * 16;                     // fragment col byte
    uint32_t aBaseH = sb + A_HI + (uint32_t)(m0 + rfr) * RSTRIDE + cfr;
    uint32_t aBaseL = aBaseH + (A_LO - A_HI);
    uint32_t bBaseH = sb + B_HI + (uint32_t)rfr * RSTRIDE + cfr;
    uint32_t bBaseL = bBaseH + (B_LO - B_HI);

    float acc[8][4];
#pragma unroll
    for (int nt = 0; nt < 8; nt++)
#pragma unroll
        for (int q = 0; q < 4; q++) acc[nt][q] = 0.f;

    // A-build indices: thread -> row nl, j-half
    int nlb = tid >> 1;
    int j0b = (tid & 1) * 32;
    char* a_hi = smem + A_HI + nlb * RSTRIDE + j0b * 2;
    char* a_lo = smem + A_LO + nlb * RSTRIDE + j0b * 2;

    __syncthreads();

    for (int c = 0; c < 16; c++) {
        // ---- build A hi/lo tiles ----
        float a = s_nf[c * 128 + nlb];
#pragma unroll
        for (int q = 0; q < 4; q++) {
            uint32_t hw[4], lw[4];
#pragma unroll
            for (int w = 0; w < 4; w++) {
                float2 u = *(const float2*)&s_updf[nlb * 66 + j0b + q * 8 + w * 2];
                float p0 = a * u.x, p1 = a * u.y;
                __nv_bfloat16 h0 = __float2bfloat16(p0);
                __nv_bfloat16 h1 = __float2bfloat16(p1);
                __nv_bfloat16 l0 = __float2bfloat16(p0 - __bfloat162float(h0));
                __nv_bfloat16 l1 = __float2bfloat16(p1 - __bfloat162float(h1));
                hw[w] = ((uint32_t)__bfloat16_as_ushort(h1) << 16) | __bfloat16_as_ushort(h0);
                lw[w] = ((uint32_t)__bfloat16_as_ushort(l1) << 16) | __bfloat16_as_ushort(l0);
            }
            *(uint4*)(a_hi + q * 16) = make_uint4(hw[0], hw[1], hw[2], hw[3]);
            *(uint4*)(a_lo + q * 16) = make_uint4(lw[0], lw[1], lw[2], lw[3]);
        }
        // ---- copy B hi/lo tiles (64 rows x 64 bf16, padded rows) ----
        const uint4* bhsrc = (const uint4*)(g_Bh + (i0 + c) * 4096);
        const uint4* blsrc = (const uint4*)(g_Bl + (i0 + c) * 4096);
#pragma unroll
        for (int p = 0; p < 2; p++) {
            int idx = p * 256 + tid;            // 512 x 16B = 8KB per tile
            int j = idx >> 3, q = idx & 7;
            *(uint4*)(smem + B_HI + j * RSTRIDE + q * 16) = bhsrc[idx];
            *(uint4*)(smem + B_LO + j * RSTRIDE + q * 16) = blsrc[idx];
        }
        __syncthreads();

        // ---- MMA: 4 k-steps x (8 n-tiles x 3 passes) ----
#pragma unroll
        for (int ks = 0; ks < 4; ks++) {
            uint32_t ah[4], al[4];
            LDSM_X4(ah, aBaseH + ks * 32);
            LDSM_X4(al, aBaseL + ks * 32);
            uint32_t bh[16], bl[16];
#pragma unroll
            for (int p = 0; p < 4; p++) {
                LDSM_X4T(&bh[p * 4], bBaseH + ks * (16 * RSTRIDE) + p * 32);
                LDSM_X4T(&bl[p * 4], bBaseL + ks * (16 * RSTRIDE) + p * 32);
            }
#pragma unroll
            for (int nt = 0; nt < 8; nt++) {
                const uint32_t* b2h = &bh[(nt >> 1) * 4 + (nt & 1) * 2];
                const uint32_t* b2l = &bl[(nt >> 1) * 4 + (nt & 1) * 2];
                mma16816(acc[nt], ah, b2h);
                mma16816(acc[nt], al, b2h);
                mma16816(acc[nt], ah, b2l);
            }
        }
        __syncthreads();
    }

    // epilogue: write D to partial buffer
    float* part = g_part + blockIdx.y * (N_ * H_);
    int row0 = n0 + m0 + (lane >> 2);
    int colb = 2 * (lane & 3);
#pragma unroll
    for (int nt = 0; nt < 8; nt++) {
        int col = nt * 8 + colb;
        *(float2*)&part[row0 * H_ + col]       = make_float2(acc[nt][0], acc[nt][1]);
        *(float2*)&part[(row0 + 8) * H_ + col] = make_float2(acc[nt][2], acc[nt][3]);
    }
}

// ---------------- K7: sum the four i-quarter partials ----------------
__global__ void k_sum(float* __restrict__ out) {
    int idx = (blockIdx.x * 256 + threadIdx.x) * 4;
    float4 a = *(const float4*)&g_part[idx];
    float4 b = *(const float4*)&g_part[N_ * H_ + idx];
    float4 c = *(const float4*)&g_part[2 * N_ * H_ + idx];
    float4 d = *(const float4*)&g_part[3 * N_ * H_ + idx];
    *(float4*)&out[idx] = make_float4(a.x + b.x + c.x + d.x,
                                      a.y + b.y + c.y + d.y,
                                      a.z + b.z + c.z + d.z,
                                      a.w + b.w + c.w + d.w);
}

// ---------------- launch ----------------
extern "C" void kernel_launch(void* const* d_in, const int* in_sizes, int n_in,
                              void* d_out, int out_size) {
    const float* node_feat    = (const float*)d_in[0];
    const float* node_feat_sr = (const float*)d_in[1];
    const float* positions    = (const float*)d_in[2];
    const float* kvecs        = (const float*)d_in[3];
    const int*   batch        = (const int*)  d_in[4];
    const float* W_readout    = (const float*)d_in[5];
    const float* W_qkv        = (const float*)d_in[6];
    const float* W_tp         = (const float*)d_in[7];
    float* out = (float*)d_out;

    static int attr_done = 0;
    if (!attr_done) {
        cudaFuncSetAttribute(k_tpmma, cudaFuncAttributeMaxDynamicSharedMemorySize, SMEM_TOT);
        attr_done = 1;
    }

    k_wc   <<<TH_, H_>>>(W_qkv, W_readout);
    k_bprep<<<H_, 256>>>(W_tp);
    k_seg  <<<1, 32>>>(batch);
    k_qkv  <<<N_ / 16, TH_>>>(node_feat, positions, kvecs, batch);
    k_kvg  <<<dim3(G_ * T_, 2), 256>>>();
    k_upd  <<<160, 256>>>();
    k_tpmma<<<dim3(N_ / 128, 4), 256, SMEM_TOT>>>(node_feat_sr);
    k_sum  <<<(N_ * H_) / (256 * 4), 256>>>(out);
}

// round 5
// speedup vs baseline: 1.5583x; 1.1794x over previous
#include <cuda_runtime.h>
#include <cuda_bf16.h>
#include <cuda_fp16.h>
#include <math.h>
#include <stdint.h>

#define N_  4096
#define H_  64
#define T_  6
#define G_  16
#define TH_ 192    // 3*H
#define TD_ 384    // T*H

// ---------------- device scratch ----------------
__device__ float g_A[H_ * TH_];            // A[m][r] = Wc[r][m]
__device__ float g_qr[N_ * TD_];           // q (silu+rope+scale), [n][t*64+d]
__device__ float g_kr[N_ * TD_];           // k (silu+rope),       [n][t*64+d]
__device__ float g_v [N_ * H_];            // v [n][e]
__device__ float g_kvg[G_ * TD_ * H_];     // kv_graph [g][t*64+d][e]
__device__ float g_updT[H_ * N_];          // update TRANSPOSED [j][n]
__device__ float g_part[4 * N_ * H_];      // four i-quarter partials
__device__ __half g_B16[H_ * H_ * H_];     // W_tp fp16, [i][j][k]
__device__ int   g_seg[G_ + 1];
__device__ int   g_tblg[256];
__device__ int   g_tbln[256];
__device__ int   g_nblk;

// ---------------- PTX helpers (baseline ISA: ldmatrix + mma.sync) --------
__device__ __forceinline__ uint32_t smem_u32(const void* p) {
    uint32_t a;
    asm("{ .reg .u64 t; cvta.to.shared.u64 t, %1; cvt.u32.u64 %0, t; }" : "=r"(a) : "l"(p));
    return a;
}
#define LDSM_X4(r, addr) \
    asm volatile("ldmatrix.sync.aligned.m8n8.x4.shared.b16 {%0,%1,%2,%3}, [%4];" \
        : "=r"((r)[0]), "=r"((r)[1]), "=r"((r)[2]), "=r"((r)[3]) : "r"(addr))
#define LDSM_X4T(r, addr) \
    asm volatile("ldmatrix.sync.aligned.m8n8.x4.trans.shared.b16 {%0,%1,%2,%3}, [%4];" \
        : "=r"((r)[0]), "=r"((r)[1]), "=r"((r)[2]), "=r"((r)[3]) : "r"(addr))

__device__ __forceinline__ void mma16816h(float* d, const uint32_t* a, const uint32_t* b) {
    asm volatile(
        "mma.sync.aligned.m16n8k16.row.col.f32.f16.f16.f32 "
        "{%0,%1,%2,%3}, {%4,%5,%6,%7}, {%8,%9}, {%0,%1,%2,%3};"
        : "+f"(d[0]), "+f"(d[1]), "+f"(d[2]), "+f"(d[3])
        : "r"(a[0]), "r"(a[1]), "r"(a[2]), "r"(a[3]), "r"(b[0]), "r"(b[1]));
}

// ---------------- K0: fused prep: Wc combine + W_tp fp16 repack + seg table ---
// blocks 0..47: A[m][r] = sum_u Wqkv[r,u]*Wro[u,m], 4 r-rows per block
// blocks 48..111: g_B16[i][j][k] = fp16(W_tp[k][i][j]), i = bid-48
// block 112: segment starts + k_upd block table
__global__ void k_prep(const float* __restrict__ Wqkv, const float* __restrict__ Wro,
                       const float* __restrict__ Wtp, const int* __restrict__ batch) {
    int bid = blockIdx.x;
    int tid = threadIdx.x;       // 256
    if (bid < 48) {
        __shared__ float srow[4][64];
        int rr = tid >> 6, m = tid & 63;
        int r = bid * 4 + rr;
        srow[rr][m] = Wqkv[r * H_ + m];
        __syncthreads();
        float s = 0.f;
#pragma unroll 8
        for (int u = 0; u < H_; u++) s += srow[rr][u] * Wro[u * H_ + m];
        g_A[m * TH_ + r] = s;
    } else if (bid < 112) {
        int i = bid - 48;
        __shared__ float s[64 * 65];
#pragma unroll
        for (int p = 0; p < 16; p++) {
            int l = p * 256 + tid;
            int k = l >> 6, j = l & 63;
            s[k * 65 + j] = Wtp[k * 4096 + i * 64 + j];   // coalesced in j
        }
        __syncthreads();
#pragma unroll
        for (int p = 0; p < 16; p++) {
            int l = p * 256 + tid;
            int j = l >> 6, k = l & 63;
            g_B16[i * 4096 + j * 64 + k] = __float2half_rn(s[k * 65 + j]);
        }
    } else {
        if (tid <= G_) {
            int lo = 0, hi = N_;
            while (lo < hi) {
                int mid = (lo + hi) >> 1;
                if (batch[mid] < tid) lo = mid + 1; else hi = mid;
            }
            g_seg[tid] = lo;
        }
        __syncthreads();
        if (tid == 0) {
            int b = 0;
            for (int gg = 0; gg < G_; gg++)
                for (int s0 = g_seg[gg]; s0 < g_seg[gg + 1]; s0 += 32) {
                    g_tblg[b] = gg; g_tbln[b] = s0; b++;
                }
            g_nblk = b;
        }
    }
}

// ---------------- K1: qkv tiled GEMM (32 nodes/block) + silu + rope -----------
// smem (bytes): s_A 0 (64x192 f32 =49152), s_nfT 49152 (64x36 f32 =9216),
//               s_qkv 58368 (32x200 f32 =25600), s_c 83968, s_s 84992
#define QKV_SA   0
#define QKV_NF   49152
#define QKV_QKV  58368
#define QKV_C    83968
#define QKV_S    84992
#define QKV_SMEM 86016

__global__ void __launch_bounds__(256) k_qkv(const float* __restrict__ node_feat,
                                             const float* __restrict__ positions,
                                             const float* __restrict__ kvecs,
                                             const int*   __restrict__ batch) {
    extern __shared__ char sm[];
    float* s_A   = (float*)(sm + QKV_SA);
    float* s_nfT = (float*)(sm + QKV_NF);
    float* s_qkv = (float*)(sm + QKV_QKV);
    float* s_c   = (float*)(sm + QKV_C);
    float* s_s   = (float*)(sm + QKV_S);
    int tid = threadIdx.x;       // 256
    int n0 = blockIdx.x * 32;

#pragma unroll
    for (int p = 0; p < 48; p++) s_A[p * 256 + tid] = g_A[p * 256 + tid];
#pragma unroll
    for (int p = 0; p < 8; p++) {
        int l = p * 256 + tid;
        int nn = l >> 6, k = l & 63;
        s_nfT[k * 36 + nn] = node_feat[(n0 + nn) * H_ + k];
    }
    __syncthreads();

    int tn = tid >> 5, tr = tid & 31;
    float acc[4][6];
#pragma unroll
    for (int nn = 0; nn < 4; nn++)
#pragma unroll
        for (int u = 0; u < 6; u++) acc[nn][u] = 0.f;

#pragma unroll 4
    for (int k = 0; k < 64; k++) {
        float4 nf4 = *(const float4*)&s_nfT[k * 36 + tn * 4];   // warp-broadcast
        float av[6];
#pragma unroll
        for (int u = 0; u < 6; u++) av[u] = s_A[k * 192 + tr + 32 * u];
#pragma unroll
        for (int u = 0; u < 6; u++) {
            acc[0][u] += nf4.x * av[u];
            acc[1][u] += nf4.y * av[u];
            acc[2][u] += nf4.z * av[u];
            acc[3][u] += nf4.w * av[u];
        }
    }
    __syncthreads();   // s_qkv aliases nothing, but order writes after all reads anyway

#pragma unroll
    for (int nn = 0; nn < 4; nn++) {
        int node = tn * 4 + nn;
#pragma unroll
        for (int u = 0; u < 6; u++) {
            int r = tr + 32 * u;
            float v = acc[nn][u];
            if (r < 2 * H_) v = v / (1.f + __expf(-v));   // silu on q,k
            s_qkv[node * 200 + r] = v;
        }
    }
    if (tid < 192) {
        int nn = tid / 6, t = tid % 6;
        int g = batch[n0 + nn];
        const float* kv = kvecs + (g * T_ + t) * 3;
        float ph = positions[(n0 + nn) * 3 + 0] * kv[0]
                 + positions[(n0 + nn) * 3 + 1] * kv[1]
                 + positions[(n0 + nn) * 3 + 2] * kv[2];
        float sv, cv;
        sincosf(ph, &sv, &cv);
        s_c[nn * 8 + t] = cv; s_s[nn * 8 + t] = sv;
    }
    __syncthreads();

#pragma unroll
    for (int p = 0; p < 48; p++) {
        int l = p * 256 + tid;           // 0..12287
        int nn = l / 384, idx = l - nn * 384;
        int t = idx >> 6, d = idx & 63;
        int m2 = (d & 31) * 2;
        float c = s_c[nn * 8 + t], sv = s_s[nn * 8 + t];
        float qa = s_qkv[nn * 200 + m2],       qb = s_qkv[nn * 200 + m2 + 1];
        float ka = s_qkv[nn * 200 + 64 + m2],  kb = s_qkv[nn * 200 + 64 + m2 + 1];
        float qv, kvv;
        if (d < 32) { qv = qa * c  - qb * sv;  kvv = ka * c  - kb * sv; }
        else        { qv = qa * sv + qb * c;   kvv = ka * sv + kb * c;  }
        int n = n0 + nn;
        g_qr[n * TD_ + idx] = qv * 0.125f;
        g_kr[n * TD_ + idx] = kvv;
    }
#pragma unroll
    for (int p = 0; p < 8; p++) {
        int l = p * 256 + tid;
        int nn = l >> 6, m = l & 63;
        g_v[(n0 + nn) * H_ + m] = s_qkv[nn * 200 + 128 + m];
    }
}

// ---------------- K2: kv_graph, e-split ----------------
__global__ void k_kvg() {
    int bid = blockIdx.x;
    int g = bid / T_, t = bid % T_;
    int eh = blockIdx.y;
    int tid = threadIdx.x;
    int td = tid >> 4, te = tid & 15;
    int d0 = td * 4, e0 = te * 2;

    __shared__ float s_k[8][64];
    __shared__ float s_v[8][32];

    int s = g_seg[g], e = g_seg[g + 1];
    float acc[4][2];
#pragma unroll
    for (int q = 0; q < 4; q++) { acc[q][0] = 0.f; acc[q][1] = 0.f; }

    for (int nb = s; nb < e; nb += 8) {
        for (int l = tid; l < 512; l += 256) {
            int r = l >> 6, c = l & 63;
            int n = nb + r;
            s_k[r][c] = (n < e) ? g_kr[n * TD_ + t * 64 + c] : 0.f;
        }
        {
            int r = tid >> 5, c = tid & 31;
            int n = nb + r;
            s_v[r][c] = (n < e) ? g_v[n * H_ + eh * 32 + c] : 0.f;
        }
        __syncthreads();
#pragma unroll
        for (int r = 0; r < 8; r++) {
            float4 kd = *(const float4*)&s_k[r][d0];
            float2 ve = *(const float2*)&s_v[r][e0];
            acc[0][0] += kd.x * ve.x; acc[0][1] += kd.x * ve.y;
            acc[1][0] += kd.y * ve.x; acc[1][1] += kd.y * ve.y;
            acc[2][0] += kd.z * ve.x; acc[2][1] += kd.z * ve.y;
            acc[3][0] += kd.w * ve.x; acc[3][1] += kd.w * ve.y;
        }
        __syncthreads();
    }

    float* outb = g_kvg + (g * TD_ + t * 64) * H_ + eh * 32;
#pragma unroll
    for (int q = 0; q < 4; q++)
        *(float2*)&outb[(d0 + q) * H_ + e0] = make_float2(acc[q][0], acc[q][1]);
}

// ---------------- K3: update (segment-tiled GEMM), writes g_updT ----------------
__global__ void k_upd() {
    int b = blockIdx.x;
    if (b >= g_nblk) return;
    int g  = g_tblg[b];
    int ns = g_tbln[b];
    int ne = min(ns + 32, g_seg[g + 1]);

    int tid = threadIdx.x;
    int tn = tid >> 4, te = tid & 15;

    __shared__ float s_q[32][65];
    __shared__ float s_kv[64][64];

    float acc[2][4];
#pragma unroll
    for (int r = 0; r < 2; r++)
#pragma unroll
        for (int c = 0; c < 4; c++) acc[r][c] = 0.f;

    const float* kvg = g_kvg + g * (TD_ * H_);
    for (int ch = 0; ch < 6; ch++) {
        int kk0 = ch * 64;
#pragma unroll
        for (int p = 0; p < 16; p++) {
            int l = p * 256 + tid;
            int kl = l >> 6, ee = l & 63;
            s_kv[kl][ee] = kvg[(kk0 + kl) * H_ + ee];
        }
#pragma unroll
        for (int p = 0; p < 8; p++) {
            int l = p * 256 + tid;
            int nl = l >> 6, kl = l & 63;
            int n = ns + nl;
            s_q[nl][kl] = (n < ne) ? g_qr[n * TD_ + kk0 + kl] : 0.f;
        }
        __syncthreads();
#pragma unroll 8
        for (int kk = 0; kk < 64; kk++) {
            float q0 = s_q[tn * 2][kk];
            float q1 = s_q[tn * 2 + 1][kk];
            float4 kv = *(const float4*)&s_kv[kk][te * 4];
            acc[0][0] += q0 * kv.x; acc[0][1] += q0 * kv.y; acc[0][2] += q0 * kv.z; acc[0][3] += q0 * kv.w;
            acc[1][0] += q1 * kv.x; acc[1][1] += q1 * kv.y; acc[1][2] += q1 * kv.z; acc[1][3] += q1 * kv.w;
        }
        __syncthreads();
    }

#pragma unroll
    for (int r = 0; r < 2; r++) {
        int n = ns + tn * 2 + r;
        if (n < ne) {
#pragma unroll
            for (int c = 0; c < 4; c++)
                g_updT[(te * 4 + c) * N_ + n] = acc[r][c];
        }
    }
}

// ---------------- K4: tensor-product GEMM, single-pass fp16 mma.sync ----------
// D[128 n x 64 k] = sum_{c=0..15} A_c @ B_c^T,  A_c[n][j] = nfsr[n,i0+c]*upd[n,j]
// smem: A 0 (128x72 fp16 =18432), B 18432 (64x72 fp16 =9216),
//       NF 27648 (16x128 f32 =8192), UPDF 35840 (128x66 f32 =33792)
#define TP_A    0
#define TP_B    18432
#define TP_NF   27648
#define TP_UPDF 35840
#define TP_SMEM 69632
#define RSTRIDE 144   // 72 fp16 row stride (bytes)

__global__ void __launch_bounds__(256) k_tpmma(const float* __restrict__ nfsr) {
    extern __shared__ char smem[];
    uint32_t sb = smem_u32(smem);
    int tid = threadIdx.x;
    int wid = tid >> 5, lane = tid & 31;
    int n0 = blockIdx.x * 128;
    int i0 = blockIdx.y * 16;

    float* s_nf   = (float*)(smem + TP_NF);     // [ii][128]
    float* s_updf = (float*)(smem + TP_UPDF);   // [nl][66]

#pragma unroll
    for (int p = 0; p < 8; p++) {
        int l = p * 256 + tid;
        int nl = l >> 4, ii = l & 15;
        s_nf[ii * 128 + nl] = nfsr[(n0 + nl) * H_ + i0 + ii];
    }
#pragma unroll
    for (int p = 0; p < 32; p++) {
        int l = p * 256 + tid;
        int j = l >> 7, nl = l & 127;
        s_updf[nl * 66 + j] = g_updT[j * N_ + n0 + nl];   // coalesced LDG
    }

    int m0 = wid * 16;
    int rfr = (lane & 7) + ((lane >> 3) & 1) * 8;
    int cfr = (lane >> 4) * 16;
    uint32_t aBase = sb + TP_A + (uint32_t)(m0 + rfr) * RSTRIDE + cfr;
    uint32_t bBase = sb + TP_B + (uint32_t)rfr * RSTRIDE + cfr;

    float acc[8][4];
#pragma unroll
    for (int nt = 0; nt < 8; nt++)
#pragma unroll
        for (int q = 0; q < 4; q++) acc[nt][q] = 0.f;

    int nlb = tid >> 1;
    int j0b = (tid & 1) * 32;
    char* a_dst = smem + TP_A + nlb * RSTRIDE + j0b * 2;

    __syncthreads();

    for (int c = 0; c < 16; c++) {
        // ---- build A tile (fp16) ----
        float a = s_nf[c * 128 + nlb];
#pragma unroll
        for (int q = 0; q < 4; q++) {
            uint32_t hw[4];
#pragma unroll
            for (int w = 0; w < 4; w++) {
                float2 u = *(const float2*)&s_updf[nlb * 66 + j0b + q * 8 + w * 2];
                __half2 h2 = __floats2half2_rn(a * u.x, a * u.y);
                hw[w] = *reinterpret_cast<uint32_t*>(&h2);
            }
            *(uint4*)(a_dst + q * 16) = make_uint4(hw[0], hw[1], hw[2], hw[3]);
        }
        // ---- copy B tile (64 rows x 64 fp16, padded rows) ----
        const uint4* bsrc = (const uint4*)(g_B16 + (i0 + c) * 4096);
#pragma unroll
        for (int p = 0; p < 2; p++) {
            int idx = p * 256 + tid;            // 512 x 16B = 8KB
            int j = idx >> 3, q = idx & 7;
            *(uint4*)(smem + TP_B + j * RSTRIDE + q * 16) = bsrc[idx];
        }
        __syncthreads();

        // ---- MMA: 4 k-steps x 8 n-tiles ----
#pragma unroll
        for (int ks = 0; ks < 4; ks++) {
            uint32_t ah[4];
            LDSM_X4(ah, aBase + ks * 32);
            uint32_t bh[16];
#pragma unroll
            for (int p = 0; p < 4; p++)
                LDSM_X4T(&bh[p * 4], bBase + ks * (16 * RSTRIDE) + p * 32);
#pragma unroll
            for (int nt = 0; nt < 8; nt++)
                mma16816h(acc[nt], ah, &bh[(nt >> 1) * 4 + (nt & 1) * 2]);
        }
        __syncthreads();
    }

    float* part = g_part + blockIdx.y * (N_ * H_);
    int row0 = n0 + m0 + (lane >> 2);
    int colb = 2 * (lane & 3);
#pragma unroll
    for (int nt = 0; nt < 8; nt++) {
        int col = nt * 8 + colb;
        *(float2*)&part[row0 * H_ + col]       = make_float2(acc[nt][0], acc[nt][1]);
        *(float2*)&part[(row0 + 8) * H_ + col] = make_float2(acc[nt][2], acc[nt][3]);
    }
}

// ---------------- K5: sum the four i-quarter partials ----------------
__global__ void k_sum(float* __restrict__ out) {
    int idx = (blockIdx.x * 256 + threadIdx.x) * 4;
    float4 a = *(const float4*)&g_part[idx];
    float4 b = *(const float4*)&g_part[N_ * H_ + idx];
    float4 c = *(const float4*)&g_part[2 * N_ * H_ + idx];
    float4 d = *(const float4*)&g_part[3 * N_ * H_ + idx];
    *(float4*)&out[idx] = make_float4(a.x + b.x + c.x + d.x,
                                      a.y + b.y + c.y + d.y,
                                      a.z + b.z + c.z + d.z,
                                      a.w + b.w + c.w + d.w);
}

// ---------------- launch ----------------
extern "C" void kernel_launch(void* const* d_in, const int* in_sizes, int n_in,
                              void* d_out, int out_size) {
    const float* node_feat    = (const float*)d_in[0];
    const float* node_feat_sr = (const float*)d_in[1];
    const float* positions    = (const float*)d_in[2];
    const float* kvecs        = (const float*)d_in[3];
    const int*   batch        = (const int*)  d_in[4];
    const float* W_readout    = (const float*)d_in[5];
    const float* W_qkv        = (const float*)d_in[6];
    const float* W_tp         = (const float*)d_in[7];
    float* out = (float*)d_out;

    static int attr_done = 0;
    if (!attr_done) {
        cudaFuncSetAttribute(k_tpmma, cudaFuncAttributeMaxDynamicSharedMemorySize, TP_SMEM);
        cudaFuncSetAttribute(k_qkv,   cudaFuncAttributeMaxDynamicSharedMemorySize, QKV_SMEM);
        attr_done = 1;
    }

    k_prep <<<113, 256>>>(W_qkv, W_readout, W_tp, batch);
    k_qkv  <<<N_ / 32, 256, QKV_SMEM>>>(node_feat, positions, kvecs, batch);
    k_kvg  <<<dim3(G_ * T_, 2), 256>>>();
    k_upd  <<<160, 256>>>();
    k_tpmma<<<dim3(N_ / 128, 4), 256, TP_SMEM>>>(node_feat_sr);
    k_sum  <<<(N_ * H_) / (256 * 4), 256>>>(out);
}

// round 6
// speedup vs baseline: 1.8183x; 1.1668x over previous
#include <cuda_runtime.h>
#include <cuda_fp16.h>
#include <math.h>
#include <stdint.h>

#define N_  4096
#define H_  64
#define T_  6
#define G_  16
#define TH_ 192    // 3*H
#define TD_ 384    // T*H

// ---------------- device scratch ----------------
__device__ float g_A[H_ * TH_];            // A[m][r] = Wc[r][m]
__device__ float g_qr[N_ * TD_];           // q (silu+rope+scale), [n][t*64+d]
__device__ float g_kr[N_ * TD_];           // k (silu+rope),       [n][t*64+d]
__device__ float g_v [N_ * H_];            // v [n][e]
__device__ float g_kvg[G_ * TD_ * H_];     // kv_graph [g][t*64+d][e]
__device__ float g_updT[H_ * N_];          // update TRANSPOSED [j][n]
__device__ float g_part[4 * N_ * H_];      // four i-quarter partials
__device__ __half g_B16[H_ * H_ * H_];     // W_tp fp16, [i][j][k]
__device__ int   g_seg[G_ + 1];
__device__ int   g_tblg[256];
__device__ int   g_tbln[256];
__device__ int   g_nblk;

// ---------------- PTX helpers ----------------
__device__ __forceinline__ uint32_t smem_u32(const void* p) {
    uint32_t a;
    asm("{ .reg .u64 t; cvta.to.shared.u64 t, %1; cvt.u32.u64 %0, t; }" : "=r"(a) : "l"(p));
    return a;
}
#define LDSM_X4(r, addr) \
    asm volatile("ldmatrix.sync.aligned.m8n8.x4.shared.b16 {%0,%1,%2,%3}, [%4];" \
        : "=r"((r)[0]), "=r"((r)[1]), "=r"((r)[2]), "=r"((r)[3]) : "r"(addr))
#define LDSM_X4T(r, addr) \
    asm volatile("ldmatrix.sync.aligned.m8n8.x4.trans.shared.b16 {%0,%1,%2,%3}, [%4];" \
        : "=r"((r)[0]), "=r"((r)[1]), "=r"((r)[2]), "=r"((r)[3]) : "r"(addr))

__device__ __forceinline__ void mma16816h(float* d, const uint32_t* a, const uint32_t* b) {
    asm volatile(
        "mma.sync.aligned.m16n8k16.row.col.f32.f16.f16.f32 "
        "{%0,%1,%2,%3}, {%4,%5,%6,%7}, {%8,%9}, {%0,%1,%2,%3};"
        : "+f"(d[0]), "+f"(d[1]), "+f"(d[2]), "+f"(d[3])
        : "r"(a[0]), "r"(a[1]), "r"(a[2]), "r"(a[3]), "r"(b[0]), "r"(b[1]));
}

// ---------------- K0: fused prep ----------------
__global__ void k_prep(const float* __restrict__ Wqkv, const float* __restrict__ Wro,
                       const float* __restrict__ Wtp, const int* __restrict__ batch) {
    int bid = blockIdx.x;
    int tid = threadIdx.x;       // 256
    if (bid < 48) {
        __shared__ float srow[4][64];
        int rr = tid >> 6, m = tid & 63;
        int r = bid * 4 + rr;
        srow[rr][m] = Wqkv[r * H_ + m];
        __syncthreads();
        float s = 0.f;
#pragma unroll 8
        for (int u = 0; u < H_; u++) s += srow[rr][u] * Wro[u * H_ + m];
        g_A[m * TH_ + r] = s;
    } else if (bid < 112) {
        int i = bid - 48;
        __shared__ float s[64 * 65];
#pragma unroll
        for (int p = 0; p < 16; p++) {
            int l = p * 256 + tid;
            int k = l >> 6, j = l & 63;
            s[k * 65 + j] = Wtp[k * 4096 + i * 64 + j];
        }
        __syncthreads();
#pragma unroll
        for (int p = 0; p < 16; p++) {
            int l = p * 256 + tid;
            int j = l >> 6, k = l & 63;
            g_B16[i * 4096 + j * 64 + k] = __float2half_rn(s[k * 65 + j]);
        }
    } else {
        if (tid <= G_) {
            int lo = 0, hi = N_;
            while (lo < hi) {
                int mid = (lo + hi) >> 1;
                if (batch[mid] < tid) lo = mid + 1; else hi = mid;
            }
            g_seg[tid] = lo;
        }
        __syncthreads();
        if (tid == 0) {
            int b = 0;
            for (int gg = 0; gg < G_; gg++)
                for (int s0 = g_seg[gg]; s0 < g_seg[gg + 1]; s0 += 32) {
                    g_tblg[b] = gg; g_tbln[b] = s0; b++;
                }
            g_nblk = b;
        }
    }
}

// ---------------- K1: qkv tiled GEMM (32 nodes/block) + silu + rope -----------
#define QKV_SA   0
#define QKV_NF   49152
#define QKV_QKV  58368
#define QKV_C    83968
#define QKV_S    84992
#define QKV_SMEM 86016

__global__ void __launch_bounds__(256) k_qkv(const float* __restrict__ node_feat,
                                             const float* __restrict__ positions,
                                             const float* __restrict__ kvecs,
                                             const int*   __restrict__ batch) {
    extern __shared__ char sm[];
    float* s_A   = (float*)(sm + QKV_SA);
    float* s_nfT = (float*)(sm + QKV_NF);
    float* s_qkv = (float*)(sm + QKV_QKV);
    float* s_c   = (float*)(sm + QKV_C);
    float* s_s   = (float*)(sm + QKV_S);
    int tid = threadIdx.x;       // 256
    int n0 = blockIdx.x * 32;

#pragma unroll
    for (int p = 0; p < 48; p++) s_A[p * 256 + tid] = g_A[p * 256 + tid];
#pragma unroll
    for (int p = 0; p < 8; p++) {
        int l = p * 256 + tid;
        int nn = l >> 6, k = l & 63;
        s_nfT[k * 36 + nn] = node_feat[(n0 + nn) * H_ + k];
    }
    __syncthreads();

    int tn = tid >> 5, tr = tid & 31;
    float acc[4][6];
#pragma unroll
    for (int nn = 0; nn < 4; nn++)
#pragma unroll
        for (int u = 0; u < 6; u++) acc[nn][u] = 0.f;

#pragma unroll 4
    for (int k = 0; k < 64; k++) {
        float4 nf4 = *(const float4*)&s_nfT[k * 36 + tn * 4];
        float av[6];
#pragma unroll
        for (int u = 0; u < 6; u++) av[u] = s_A[k * 192 + tr + 32 * u];
#pragma unroll
        for (int u = 0; u < 6; u++) {
            acc[0][u] += nf4.x * av[u];
            acc[1][u] += nf4.y * av[u];
            acc[2][u] += nf4.z * av[u];
            acc[3][u] += nf4.w * av[u];
        }
    }
    __syncthreads();

#pragma unroll
    for (int nn = 0; nn < 4; nn++) {
        int node = tn * 4 + nn;
#pragma unroll
        for (int u = 0; u < 6; u++) {
            int r = tr + 32 * u;
            float v = acc[nn][u];
            if (r < 2 * H_) v = v / (1.f + __expf(-v));
            s_qkv[node * 200 + r] = v;
        }
    }
    if (tid < 192) {
        int nn = tid / 6, t = tid % 6;
        int g = batch[n0 + nn];
        const float* kv = kvecs + (g * T_ + t) * 3;
        float ph = positions[(n0 + nn) * 3 + 0] * kv[0]
                 + positions[(n0 + nn) * 3 + 1] * kv[1]
                 + positions[(n0 + nn) * 3 + 2] * kv[2];
        float sv, cv;
        sincosf(ph, &sv, &cv);
        s_c[nn * 8 + t] = cv; s_s[nn * 8 + t] = sv;
    }
    __syncthreads();

#pragma unroll
    for (int p = 0; p < 48; p++) {
        int l = p * 256 + tid;
        int nn = l / 384, idx = l - nn * 384;
        int t = idx >> 6, d = idx & 63;
        int m2 = (d & 31) * 2;
        float c = s_c[nn * 8 + t], sv = s_s[nn * 8 + t];
        float qa = s_qkv[nn * 200 + m2],       qb = s_qkv[nn * 200 + m2 + 1];
        float ka = s_qkv[nn * 200 + 64 + m2],  kb = s_qkv[nn * 200 + 64 + m2 + 1];
        float qv, kvv;
        if (d < 32) { qv = qa * c  - qb * sv;  kvv = ka * c  - kb * sv; }
        else        { qv = qa * sv + qb * c;   kvv = ka * sv + kb * c;  }
        int n = n0 + nn;
        g_qr[n * TD_ + idx] = qv * 0.125f;
        g_kr[n * TD_ + idx] = kvv;
    }
#pragma unroll
    for (int p = 0; p < 8; p++) {
        int l = p * 256 + tid;
        int nn = l >> 6, m = l & 63;
        g_v[(n0 + nn) * H_ + m] = s_qkv[nn * 200 + 128 + m];
    }
}

// ---------------- K2: kv_graph, e-split ----------------
__global__ void k_kvg() {
    int bid = blockIdx.x;
    int g = bid / T_, t = bid % T_;
    int eh = blockIdx.y;
    int tid = threadIdx.x;
    int td = tid >> 4, te = tid & 15;
    int d0 = td * 4, e0 = te * 2;

    __shared__ float s_k[8][64];
    __shared__ float s_v[8][32];

    int s = g_seg[g], e = g_seg[g + 1];
    float acc[4][2];
#pragma unroll
    for (int q = 0; q < 4; q++) { acc[q][0] = 0.f; acc[q][1] = 0.f; }

    for (int nb = s; nb < e; nb += 8) {
        for (int l = tid; l < 512; l += 256) {
            int r = l >> 6, c = l & 63;
            int n = nb + r;
            s_k[r][c] = (n < e) ? g_kr[n * TD_ + t * 64 + c] : 0.f;
        }
        {
            int r = tid >> 5, c = tid & 31;
            int n = nb + r;
            s_v[r][c] = (n < e) ? g_v[n * H_ + eh * 32 + c] : 0.f;
        }
        __syncthreads();
#pragma unroll
        for (int r = 0; r < 8; r++) {
            float4 kd = *(const float4*)&s_k[r][d0];
            float2 ve = *(const float2*)&s_v[r][e0];
            acc[0][0] += kd.x * ve.x; acc[0][1] += kd.x * ve.y;
            acc[1][0] += kd.y * ve.x; acc[1][1] += kd.y * ve.y;
            acc[2][0] += kd.z * ve.x; acc[2][1] += kd.z * ve.y;
            acc[3][0] += kd.w * ve.x; acc[3][1] += kd.w * ve.y;
        }
        __syncthreads();
    }

    float* outb = g_kvg + (g * TD_ + t * 64) * H_ + eh * 32;
#pragma unroll
    for (int q = 0; q < 4; q++)
        *(float2*)&outb[(d0 + q) * H_ + e0] = make_float2(acc[q][0], acc[q][1]);
}

// ---------------- K3: update, double-buffered, 1n x 8e per thread -------------
// smem: q[2][32][66] f32 (8448B each), kv[2][64][64] f32 (16384B each)
#define UQ0 0
#define UQ1 8448
#define UKV0 16896
#define UKV1 33280
#define UPD_SMEM 49664

__global__ void __launch_bounds__(256) k_upd() {
    int b = blockIdx.x;
    if (b >= g_nblk) return;
    int g  = g_tblg[b];
    int ns = g_tbln[b];
    int ne = min(ns + 32, g_seg[g + 1]);

    extern __shared__ char sm[];
    int tid = threadIdx.x;       // 256
    int lane = tid & 31, wid = tid >> 5;
    int e0 = wid * 8;

    const float* kvgc = g_kvg + g * (TD_ * H_);

    // q fill indices: thread -> node row nl, 8 consecutive kk
    int nl = tid >> 3;
    int kq = (tid & 7) * 8;
    int nq = ns + nl;
    bool qok = nq < ne;

    // ---- direct fill chunk 0 ----
    {
        float* q = (float*)(sm + UQ0);
        float4 qa = make_float4(0.f, 0.f, 0.f, 0.f), qb = qa;
        if (qok) {
            qa = *(const float4*)&g_qr[nq * TD_ + kq];
            qb = *(const float4*)&g_qr[nq * TD_ + kq + 4];
        }
        *(float2*)&q[nl * 66 + kq]     = make_float2(qa.x, qa.y);
        *(float2*)&q[nl * 66 + kq + 2] = make_float2(qa.z, qa.w);
        *(float2*)&q[nl * 66 + kq + 4] = make_float2(qb.x, qb.y);
        *(float2*)&q[nl * 66 + kq + 6] = make_float2(qb.z, qb.w);
        float* kv = (float*)(sm + UKV0);
#pragma unroll
        for (int p = 0; p < 4; p++) {
            int idx = p * 256 + tid;
            *(float4*)&kv[idx * 4] = *(const float4*)&kvgc[idx * 4];
        }
    }
    __syncthreads();

    float acc[8];
#pragma unroll
    for (int c = 0; c < 8; c++) acc[c] = 0.f;

    for (int ch = 0; ch < 6; ch++) {
        // prefetch next chunk into registers
        float4 pq0, pq1, pkv[4];
        if (ch < 5) {
            pq0 = make_float4(0.f, 0.f, 0.f, 0.f); pq1 = pq0;
            if (qok) {
                pq0 = *(const float4*)&g_qr[nq * TD_ + (ch + 1) * 64 + kq];
                pq1 = *(const float4*)&g_qr[nq * TD_ + (ch + 1) * 64 + kq + 4];
            }
            const float* kvn = kvgc + (ch + 1) * 4096;
#pragma unroll
            for (int p = 0; p < 4; p++) {
                int idx = p * 256 + tid;
                pkv[p] = *(const float4*)&kvn[idx * 4];
            }
        }

        const float* q  = (const float*)(sm + ((ch & 1) ? UQ1 : UQ0));
        const float* kv = (const float*)(sm + ((ch & 1) ? UKV1 : UKV0));
#pragma unroll 16
        for (int kk = 0; kk < 64; kk++) {
            float qv = q[lane * 66 + kk];
            float4 k0 = *(const float4*)&kv[kk * 64 + e0];
            float4 k1 = *(const float4*)&kv[kk * 64 + e0 + 4];
            acc[0] += qv * k0.x; acc[1] += qv * k0.y;
            acc[2] += qv * k0.z; acc[3] += qv * k0.w;
            acc[4] += qv * k1.x; acc[5] += qv * k1.y;
            acc[6] += qv * k1.z; acc[7] += qv * k1.w;
        }

        if (ch < 5) {
            float* qd  = (float*)(sm + ((ch & 1) ? UQ0 : UQ1));
            float* kvd = (float*)(sm + ((ch & 1) ? UKV0 : UKV1));
            *(float2*)&qd[nl * 66 + kq]     = make_float2(pq0.x, pq0.y);
            *(float2*)&qd[nl * 66 + kq + 2] = make_float2(pq0.z, pq0.w);
            *(float2*)&qd[nl * 66 + kq + 4] = make_float2(pq1.x, pq1.y);
            *(float2*)&qd[nl * 66 + kq + 6] = make_float2(pq1.z, pq1.w);
#pragma unroll
            for (int p = 0; p < 4; p++) {
                int idx = p * 256 + tid;
                *(float4*)&kvd[idx * 4] = pkv[p];
            }
            __syncthreads();
        }
    }

    int n = ns + lane;
    if (n < ne) {
#pragma unroll
        for (int c = 0; c < 8; c++)
            g_updT[(e0 + c) * N_ + n] = acc[c];
    }
}

// ---------------- K4: tensor-product GEMM, A-frags resident, B double-buffered -
// out[n][k] = sum_c nf[n][c] * (upd[n] @ B_c)[k]
// smem: U 0 (128x72 fp16 =18432), B0 18432, B1 27648 (each 64x72 fp16 =9216),
//       NF 36864 (16x128 f32 =8192), UPDF 45056 (128x66 f32 =33792)
#define TP_U    0
#define TP_B0   18432
#define TP_B1   27648
#define TP_NF   36864
#define TP_UPDF 45056
#define TP_SMEM 78848
#define RSTRIDE 144   // 72 fp16 row stride (bytes)

__global__ void __launch_bounds__(256) k_tpmma(const float* __restrict__ nfsr) {
    extern __shared__ char smem[];
    uint32_t sb = smem_u32(smem);
    int tid = threadIdx.x;
    int wid = tid >> 5, lane = tid & 31;
    int n0 = blockIdx.x * 128;
    int i0 = blockIdx.y * 16;

    float* s_nf   = (float*)(smem + TP_NF);     // [c][128]
    float* s_updf = (float*)(smem + TP_UPDF);   // [nl][66]

#pragma unroll
    for (int p = 0; p < 8; p++) {
        int l = p * 256 + tid;
        int nl = l >> 4, ii = l & 15;
        s_nf[ii * 128 + nl] = nfsr[(n0 + nl) * H_ + i0 + ii];
    }
#pragma unroll
    for (int p = 0; p < 32; p++) {
        int l = p * 256 + tid;
        int j = l >> 7, nl = l & 127;
        s_updf[nl * 66 + j] = g_updT[j * N_ + n0 + nl];
    }
    // preload B(0) into buffer 0
    {
        const uint4* bs = (const uint4*)(g_B16 + i0 * 4096);
        uint4 b0 = bs[tid], b1 = bs[tid + 256];
        int q = tid & 7;
        int ja = tid >> 3, jb = (tid + 256) >> 3;
        *(uint4*)(smem + TP_B0 + ja * RSTRIDE + q * 16) = b0;
        *(uint4*)(smem + TP_B0 + jb * RSTRIDE + q * 16) = b1;
    }
    __syncthreads();

    // build fp16 upd tile [128 n][64 j]
    {
        int nlb = tid >> 1, j0b = (tid & 1) * 32;
        char* udst = smem + TP_U + nlb * RSTRIDE + j0b * 2;
#pragma unroll
        for (int q = 0; q < 4; q++) {
            uint32_t hw[4];
#pragma unroll
            for (int w = 0; w < 4; w++) {
                float2 u = *(const float2*)&s_updf[nlb * 66 + j0b + q * 8 + w * 2];
                __half2 h2 = __floats2half2_rn(u.x, u.y);
                hw[w] = *reinterpret_cast<uint32_t*>(&h2);
            }
            *(uint4*)(udst + q * 16) = make_uint4(hw[0], hw[1], hw[2], hw[3]);
        }
    }
    __syncthreads();

    // resident A fragments (upd fp16), all 4 k-steps
    int m0 = wid * 16;
    int rfr = (lane & 7) + ((lane >> 3) & 1) * 8;
    int cfr = (lane >> 4) * 16;
    uint32_t aF[16];
    {
        uint32_t aAddr = sb + TP_U + (uint32_t)(m0 + rfr) * RSTRIDE + cfr;
#pragma unroll
        for (int ks = 0; ks < 4; ks++) LDSM_X4(&aF[ks * 4], aAddr + ks * 32);
    }

    float acc[8][4];
#pragma unroll
    for (int nt = 0; nt < 8; nt++)
#pragma unroll
        for (int q = 0; q < 4; q++) acc[nt][q] = 0.f;

    int rowl = m0 + (lane >> 2);
    int qb8 = tid & 7;
    int ja = tid >> 3, jb = (tid + 256) >> 3;

    for (int c = 0; c < 16; c++) {
        uint4 pfa, pfb;
        if (c < 15) {
            const uint4* bs = (const uint4*)(g_B16 + (i0 + c + 1) * 4096);
            pfa = bs[tid]; pfb = bs[tid + 256];
        }

        uint32_t bBase = sb + ((c & 1) ? TP_B1 : TP_B0) + (uint32_t)rfr * RSTRIDE + cfr;
        float ptmp[8][4];
#pragma unroll
        for (int nt = 0; nt < 8; nt++)
#pragma unroll
            for (int q = 0; q < 4; q++) ptmp[nt][q] = 0.f;

#pragma unroll
        for (int ks = 0; ks < 4; ks++) {
            uint32_t bF[16];
#pragma unroll
            for (int p = 0; p < 4; p++)
                LDSM_X4T(&bF[p * 4], bBase + ks * (16 * RSTRIDE) + p * 32);
#pragma unroll
            for (int nt = 0; nt < 8; nt++)
                mma16816h(ptmp[nt], &aF[ks * 4], &bF[(nt >> 1) * 4 + (nt & 1) * 2]);
        }

        float f0 = s_nf[c * 128 + rowl];
        float f1 = s_nf[c * 128 + rowl + 8];
#pragma unroll
        for (int nt = 0; nt < 8; nt++) {
            acc[nt][0] += f0 * ptmp[nt][0];
            acc[nt][1] += f0 * ptmp[nt][1];
            acc[nt][2] += f1 * ptmp[nt][2];
            acc[nt][3] += f1 * ptmp[nt][3];
        }

        if (c < 15) {
            char* dst = smem + ((c & 1) ? TP_B0 : TP_B1);
            *(uint4*)(dst + ja * RSTRIDE + qb8 * 16) = pfa;
            *(uint4*)(dst + jb * RSTRIDE + qb8 * 16) = pfb;
            __syncthreads();
        }
    }

    float* part = g_part + blockIdx.y * (N_ * H_);
    int row0 = n0 + m0 + (lane >> 2);
    int colb = 2 * (lane & 3);
#pragma unroll
    for (int nt = 0; nt < 8; nt++) {
        int col = nt * 8 + colb;
        *(float2*)&part[row0 * H_ + col]       = make_float2(acc[nt][0], acc[nt][1]);
        *(float2*)&part[(row0 + 8) * H_ + col] = make_float2(acc[nt][2], acc[nt][3]);
    }
}

// ---------------- K5: sum the four i-quarter partials ----------------
__global__ void k_sum(float* __restrict__ out) {
    int idx = (blockIdx.x * 256 + threadIdx.x) * 4;
    float4 a = *(const float4*)&g_part[idx];
    float4 b = *(const float4*)&g_part[N_ * H_ + idx];
    float4 c = *(const float4*)&g_part[2 * N_ * H_ + idx];
    float4 d = *(const float4*)&g_part[3 * N_ * H_ + idx];
    *(float4*)&out[idx] = make_float4(a.x + b.x + c.x + d.x,
                                      a.y + b.y + c.y + d.y,
                                      a.z + b.z + c.z + d.z,
                                      a.w + b.w + c.w + d.w);
}

// ---------------- launch ----------------
extern "C" void kernel_launch(void* const* d_in, const int* in_sizes, int n_in,
                              void* d_out, int out_size) {
    const float* node_feat    = (const float*)d_in[0];
    const float* node_feat_sr = (const float*)d_in[1];
    const float* positions    = (const float*)d_in[2];
    const float* kvecs        = (const float*)d_in[3];
    const int*   batch        = (const int*)  d_in[4];
    const float* W_readout    = (const float*)d_in[5];
    const float* W_qkv        = (const float*)d_in[6];
    const float* W_tp         = (const float*)d_in[7];
    float* out = (float*)d_out;

    static int attr_done = 0;
    if (!attr_done) {
        cudaFuncSetAttribute(k_tpmma, cudaFuncAttributeMaxDynamicSharedMemorySize, TP_SMEM);
        cudaFuncSetAttribute(k_qkv,   cudaFuncAttributeMaxDynamicSharedMemorySize, QKV_SMEM);
        cudaFuncSetAttribute(k_upd,   cudaFuncAttributeMaxDynamicSharedMemorySize, UPD_SMEM);
        attr_done = 1;
    }

    k_prep <<<113, 256>>>(W_qkv, W_readout, W_tp, batch);
    k_qkv  <<<N_ / 32, 256, QKV_SMEM>>>(node_feat, positions, kvecs, batch);
    k_kvg  <<<dim3(G_ * T_, 2), 256>>>();
    k_upd  <<<160, 256, UPD_SMEM>>>();
    k_tpmma<<<dim3(N_ / 128, 4), 256, TP_SMEM>>>(node_feat_sr);
    k_sum  <<<(N_ * H_) / (256 * 4), 256>>>(out);
}

// round 7
// speedup vs baseline: 1.9947x; 1.0970x over previous
#include <cuda_runtime.h>
#include <cuda_fp16.h>
#include <math.h>
#include <stdint.h>

#define N_  4096
#define H_  64
#define T_  6
#define G_  16
#define TH_ 192    // 3*H
#define TD_ 384    // T*H

// ---------------- device scratch ----------------
__device__ float g_A[H_ * TH_];            // A[m][r] = Wc[r][m]
__device__ __align__(16) __half g_qr16[N_ * TD_];       // q fp16 [n][t*64+d]
__device__ float g_kr[N_ * TD_];                        // k fp32 [n][t*64+d]
__device__ float g_v [N_ * H_];                         // v fp32 [n][e]
__device__ __align__(16) __half g_kvg16[G_ * TD_ * H_]; // kv_graph fp16 [g][td][e]
__device__ __align__(16) __half g_upd16[N_ * H_];       // update fp16 [n][j]
__device__ float g_part[4 * N_ * H_];      // four i-quarter partials
__device__ __half g_B16[H_ * H_ * H_];     // W_tp fp16, [i][j][k]
__device__ int   g_seg[G_ + 1];
__device__ int   g_tblg[256];
__device__ int   g_tbln[256];
__device__ int   g_nblk;

// ---------------- PTX helpers ----------------
__device__ __forceinline__ uint32_t smem_u32(const void* p) {
    uint32_t a;
    asm("{ .reg .u64 t; cvta.to.shared.u64 t, %1; cvt.u32.u64 %0, t; }" : "=r"(a) : "l"(p));
    return a;
}
#define LDSM_X4(r, addr) \
    asm volatile("ldmatrix.sync.aligned.m8n8.x4.shared.b16 {%0,%1,%2,%3}, [%4];" \
        : "=r"((r)[0]), "=r"((r)[1]), "=r"((r)[2]), "=r"((r)[3]) : "r"(addr))
#define LDSM_X4T(r, addr) \
    asm volatile("ldmatrix.sync.aligned.m8n8.x4.trans.shared.b16 {%0,%1,%2,%3}, [%4];" \
        : "=r"((r)[0]), "=r"((r)[1]), "=r"((r)[2]), "=r"((r)[3]) : "r"(addr))

__device__ __forceinline__ void mma16816h(float* d, const uint32_t* a, const uint32_t* b) {
    asm volatile(
        "mma.sync.aligned.m16n8k16.row.col.f32.f16.f16.f32 "
        "{%0,%1,%2,%3}, {%4,%5,%6,%7}, {%8,%9}, {%0,%1,%2,%3};"
        : "+f"(d[0]), "+f"(d[1]), "+f"(d[2]), "+f"(d[3])
        : "r"(a[0]), "r"(a[1]), "r"(a[2]), "r"(a[3]), "r"(b[0]), "r"(b[1]));
}

// ---------------- K0: fused prep ----------------
__global__ void k_prep(const float* __restrict__ Wqkv, const float* __restrict__ Wro,
                       const float* __restrict__ Wtp, const int* __restrict__ batch) {
    int bid = blockIdx.x;
    int tid = threadIdx.x;       // 256
    if (bid < 48) {
        __shared__ float srow[4][64];
        int rr = tid >> 6, m = tid & 63;
        int r = bid * 4 + rr;
        srow[rr][m] = Wqkv[r * H_ + m];
        __syncthreads();
        float s = 0.f;
#pragma unroll 8
        for (int u = 0; u < H_; u++) s += srow[rr][u] * Wro[u * H_ + m];
        g_A[m * TH_ + r] = s;
    } else if (bid < 112) {
        int i = bid - 48;
        __shared__ float s[64 * 65];
#pragma unroll
        for (int p = 0; p < 16; p++) {
            int l = p * 256 + tid;
            int k = l >> 6, j = l & 63;
            s[k * 65 + j] = Wtp[k * 4096 + i * 64 + j];
        }
        __syncthreads();
#pragma unroll
        for (int p = 0; p < 16; p++) {
            int l = p * 256 + tid;
            int j = l >> 6, k = l & 63;
            g_B16[i * 4096 + j * 64 + k] = __float2half_rn(s[k * 65 + j]);
        }
    } else {
        if (tid <= G_) {
            int lo = 0, hi = N_;
            while (lo < hi) {
                int mid = (lo + hi) >> 1;
                if (batch[mid] < tid) lo = mid + 1; else hi = mid;
            }
            g_seg[tid] = lo;
        }
        __syncthreads();
        if (tid == 0) {
            int b = 0;
            for (int gg = 0; gg < G_; gg++)
                for (int s0 = g_seg[gg]; s0 < g_seg[gg + 1]; s0 += 32) {
                    g_tblg[b] = gg; g_tbln[b] = s0; b++;
                }
            g_nblk = b;
        }
    }
}

// ---------------- K1: qkv tiled GEMM (32 nodes/block) + silu + rope -----------
#define QKV_SA   0
#define QKV_NF   49152
#define QKV_QKV  58368
#define QKV_C    83968
#define QKV_S    84992
#define QKV_SMEM 86016

__global__ void __launch_bounds__(256) k_qkv(const float* __restrict__ node_feat,
                                             const float* __restrict__ positions,
                                             const float* __restrict__ kvecs,
                                             const int*   __restrict__ batch) {
    extern __shared__ char sm[];
    float* s_A   = (float*)(sm + QKV_SA);
    float* s_nfT = (float*)(sm + QKV_NF);
    float* s_qkv = (float*)(sm + QKV_QKV);
    float* s_c   = (float*)(sm + QKV_C);
    float* s_s   = (float*)(sm + QKV_S);
    int tid = threadIdx.x;       // 256
    int n0 = blockIdx.x * 32;

#pragma unroll
    for (int p = 0; p < 48; p++) s_A[p * 256 + tid] = g_A[p * 256 + tid];
#pragma unroll
    for (int p = 0; p < 8; p++) {
        int l = p * 256 + tid;
        int nn = l >> 6, k = l & 63;
        s_nfT[k * 36 + nn] = node_feat[(n0 + nn) * H_ + k];
    }
    __syncthreads();

    int tn = tid >> 5, tr = tid & 31;
    float acc[4][6];
#pragma unroll
    for (int nn = 0; nn < 4; nn++)
#pragma unroll
        for (int u = 0; u < 6; u++) acc[nn][u] = 0.f;

#pragma unroll 4
    for (int k = 0; k < 64; k++) {
        float4 nf4 = *(const float4*)&s_nfT[k * 36 + tn * 4];
        float av[6];
#pragma unroll
        for (int u = 0; u < 6; u++) av[u] = s_A[k * 192 + tr + 32 * u];
#pragma unroll
        for (int u = 0; u < 6; u++) {
            acc[0][u] += nf4.x * av[u];
            acc[1][u] += nf4.y * av[u];
            acc[2][u] += nf4.z * av[u];
            acc[3][u] += nf4.w * av[u];
        }
    }
    __syncthreads();

#pragma unroll
    for (int nn = 0; nn < 4; nn++) {
        int node = tn * 4 + nn;
#pragma unroll
        for (int u = 0; u < 6; u++) {
            int r = tr + 32 * u;
            float v = acc[nn][u];
            if (r < 2 * H_) v = v / (1.f + __expf(-v));
            s_qkv[node * 200 + r] = v;
        }
    }
    if (tid < 192) {
        int nn = tid / 6, t = tid % 6;
        int g = batch[n0 + nn];
        const float* kv = kvecs + (g * T_ + t) * 3;
        float ph = positions[(n0 + nn) * 3 + 0] * kv[0]
                 + positions[(n0 + nn) * 3 + 1] * kv[1]
                 + positions[(n0 + nn) * 3 + 2] * kv[2];
        float sv, cv;
        sincosf(ph, &sv, &cv);
        s_c[nn * 8 + t] = cv; s_s[nn * 8 + t] = sv;
    }
    __syncthreads();

#pragma unroll
    for (int p = 0; p < 48; p++) {
        int l = p * 256 + tid;
        int nn = l / 384, idx = l - nn * 384;
        int t = idx >> 6, d = idx & 63;
        int m2 = (d & 31) * 2;
        float c = s_c[nn * 8 + t], sv = s_s[nn * 8 + t];
        float qa = s_qkv[nn * 200 + m2],       qb = s_qkv[nn * 200 + m2 + 1];
        float ka = s_qkv[nn * 200 + 64 + m2],  kb = s_qkv[nn * 200 + 64 + m2 + 1];
        float qv, kvv;
        if (d < 32) { qv = qa * c  - qb * sv;  kvv = ka * c  - kb * sv; }
        else        { qv = qa * sv + qb * c;   kvv = ka * sv + kb * c;  }
        int n = n0 + nn;
        g_qr16[n * TD_ + idx] = __float2half_rn(qv * 0.125f);
        g_kr[n * TD_ + idx] = kvv;
    }
#pragma unroll
    for (int p = 0; p < 8; p++) {
        int l = p * 256 + tid;
        int nn = l >> 6, m = l & 63;
        g_v[(n0 + nn) * H_ + m] = s_qkv[nn * 200 + 128 + m];
    }
}

// ---------------- K2: kv_graph, e-split, fp16 output ----------------
__global__ void k_kvg() {
    int bid = blockIdx.x;
    int g = bid / T_, t = bid % T_;
    int eh = blockIdx.y;
    int tid = threadIdx.x;
    int td = tid >> 4, te = tid & 15;
    int d0 = td * 4, e0 = te * 2;

    __shared__ float s_k[8][64];
    __shared__ float s_v[8][32];

    int s = g_seg[g], e = g_seg[g + 1];
    float acc[4][2];
#pragma unroll
    for (int q = 0; q < 4; q++) { acc[q][0] = 0.f; acc[q][1] = 0.f; }

    for (int nb = s; nb < e; nb += 8) {
        for (int l = tid; l < 512; l += 256) {
            int r = l >> 6, c = l & 63;
            int n = nb + r;
            s_k[r][c] = (n < e) ? g_kr[n * TD_ + t * 64 + c] : 0.f;
        }
        {
            int r = tid >> 5, c = tid & 31;
            int n = nb + r;
            s_v[r][c] = (n < e) ? g_v[n * H_ + eh * 32 + c] : 0.f;
        }
        __syncthreads();
#pragma unroll
        for (int r = 0; r < 8; r++) {
            float4 kd = *(const float4*)&s_k[r][d0];
            float2 ve = *(const float2*)&s_v[r][e0];
            acc[0][0] += kd.x * ve.x; acc[0][1] += kd.x * ve.y;
            acc[1][0] += kd.y * ve.x; acc[1][1] += kd.y * ve.y;
            acc[2][0] += kd.z * ve.x; acc[2][1] += kd.z * ve.y;
            acc[3][0] += kd.w * ve.x; acc[3][1] += kd.w * ve.y;
        }
        __syncthreads();
    }

    __half* outb = g_kvg16 + (g * TD_ + t * 64) * H_ + eh * 32;
#pragma unroll
    for (int q = 0; q < 4; q++)
        *(__half2*)(outb + (d0 + q) * H_ + e0) = __floats2half2_rn(acc[q][0], acc[q][1]);
}

// ---------------- K3: update via HMMA: [32 x 384] @ [384 x 64] ----------------
// smem: q 6ch x 32r x 144B = 27648; kv 6ch x 64r x 144B = 55296
#define UPD_Q    0
#define UPD_KV   27648
#define UPD_SMEM 82944
#define RSTRIDE 144   // 72 fp16 row stride (bytes)

__global__ void __launch_bounds__(256) k_upd() {
    int b = blockIdx.x;
    if (b >= g_nblk) return;
    int g  = g_tblg[b];
    int ns = g_tbln[b];
    int ne = min(ns + 32, g_seg[g + 1]);

    extern __shared__ char sm[];
    uint32_t sb = smem_u32(sm);
    int tid = threadIdx.x;       // 256
    int lane = tid & 31, w = tid >> 5;

    // fill q tiles: 32 rows x 384 fp16 -> 6 chunks of [32][64], zero pad rows >= ne
#pragma unroll
    for (int p = 0; p < 6; p++) {
        int idx = p * 256 + tid;            // 0..1535 uint4
        int nl = idx / 48, c8 = idx % 48;
        uint4 val = make_uint4(0u, 0u, 0u, 0u);
        if (ns + nl < ne) val = *(const uint4*)(g_qr16 + (ns + nl) * TD_ + c8 * 8);
        int ch = c8 >> 3, q8 = c8 & 7;
        *(uint4*)(sm + UPD_Q + ch * (32 * RSTRIDE) + nl * RSTRIDE + q8 * 16) = val;
    }
    // fill kv tiles: 384 rows x 64 fp16 -> 6 chunks of [64][64]
    const __half* kvsrc = g_kvg16 + g * (TD_ * H_);
#pragma unroll
    for (int p = 0; p < 12; p++) {
        int idx = p * 256 + tid;            // 0..3071 uint4
        int td = idx >> 3, q8 = idx & 7;
        uint4 val = *(const uint4*)(kvsrc + td * 64 + q8 * 8);
        int ch = td >> 6, r = td & 63;
        *(uint4*)(sm + UPD_KV + ch * (64 * RSTRIDE) + r * RSTRIDE + q8 * 16) = val;
    }
    __syncthreads();

    int wm = w & 1, weg = w >> 1;            // m16 tile, e-group of 16
    int rfr = (lane & 7) + ((lane >> 3) & 1) * 8;
    int cfr = (lane >> 4) * 16;

    float acc[2][4];
#pragma unroll
    for (int nt = 0; nt < 2; nt++)
#pragma unroll
        for (int q = 0; q < 4; q++) acc[nt][q] = 0.f;

#pragma unroll
    for (int ch = 0; ch < 6; ch++) {
        uint32_t aB = sb + UPD_Q  + ch * (32 * RSTRIDE) + (uint32_t)(wm * 16 + rfr) * RSTRIDE + cfr;
        uint32_t bB = sb + UPD_KV + ch * (64 * RSTRIDE) + (uint32_t)rfr * RSTRIDE + cfr + weg * 32;
#pragma unroll
        for (int ks = 0; ks < 4; ks++) {
            uint32_t aF[4], bF[4];
            LDSM_X4(aF, aB + ks * 32);
            LDSM_X4T(bF, bB + ks * (16 * RSTRIDE));
            mma16816h(acc[0], aF, &bF[0]);
            mma16816h(acc[1], aF, &bF[2]);
        }
    }

    int r0 = wm * 16 + (lane >> 2);
    int cb = 2 * (lane & 3);
#pragma unroll
    for (int nt = 0; nt < 2; nt++) {
        int e = weg * 16 + nt * 8 + cb;
        int n = ns + r0;
        if (n < ne)
            *(__half2*)(g_upd16 + n * H_ + e) = __floats2half2_rn(acc[nt][0], acc[nt][1]);
        if (n + 8 < ne)
            *(__half2*)(g_upd16 + (n + 8) * H_ + e) = __floats2half2_rn(acc[nt][2], acc[nt][3]);
    }
}

// ---------------- K4: tensor-product GEMM, A-frags resident, B double-buffered -
// smem: U 0 (128x72 fp16 =18432), B0 18432, B1 27648 (each 9216), NF 36864 (8192)
#define TP_U    0
#define TP_B0   18432
#define TP_B1   27648
#define TP_NF   36864
#define TP_SMEM 45056

__global__ void __launch_bounds__(256) k_tpmma(const float* __restrict__ nfsr) {
    extern __shared__ char smem[];
    uint32_t sb = smem_u32(smem);
    int tid = threadIdx.x;
    int wid = tid >> 5, lane = tid & 31;
    int n0 = blockIdx.x * 128;
    int i0 = blockIdx.y * 16;

    float* s_nf = (float*)(smem + TP_NF);     // [c][128]

#pragma unroll
    for (int p = 0; p < 8; p++) {
        int l = p * 256 + tid;
        int nl = l >> 4, ii = l & 15;
        s_nf[ii * 128 + nl] = nfsr[(n0 + nl) * H_ + i0 + ii];
    }
    // load fp16 upd tile [128 n][64 j] directly
#pragma unroll
    for (int p = 0; p < 4; p++) {
        int idx = p * 256 + tid;              // 0..1023 uint4
        int n = idx >> 3, q8 = idx & 7;
        *(uint4*)(smem + TP_U + n * RSTRIDE + q8 * 16) =
            *(const uint4*)(g_upd16 + (n0 + n) * H_ + q8 * 8);
    }
    // preload B(0) into buffer 0
    {
        const uint4* bs = (const uint4*)(g_B16 + i0 * 4096);
        uint4 b0 = bs[tid], b1 = bs[tid + 256];
        int q = tid & 7;
        int ja = tid >> 3, jb = (tid + 256) >> 3;
        *(uint4*)(smem + TP_B0 + ja * RSTRIDE + q * 16) = b0;
        *(uint4*)(smem + TP_B0 + jb * RSTRIDE + q * 16) = b1;
    }
    __syncthreads();

    int m0 = wid * 16;
    int rfr = (lane & 7) + ((lane >> 3) & 1) * 8;
    int cfr = (lane >> 4) * 16;
    uint32_t aF[16];
    {
        uint32_t aAddr = sb + TP_U + (uint32_t)(m0 + rfr) * RSTRIDE + cfr;
#pragma unroll
        for (int ks = 0; ks < 4; ks++) LDSM_X4(&aF[ks * 4], aAddr + ks * 32);
    }

    float acc[8][4];
#pragma unroll
    for (int nt = 0; nt < 8; nt++)
#pragma unroll
        for (int q = 0; q < 4; q++) acc[nt][q] = 0.f;

    int rowl = m0 + (lane >> 2);
    int qb8 = tid & 7;
    int ja = tid >> 3, jb = (tid + 256) >> 3;

    for (int c = 0; c < 16; c++) {
        uint4 pfa, pfb;
        if (c < 15) {
            const uint4* bs = (const uint4*)(g_B16 + (i0 + c + 1) * 4096);
            pfa = bs[tid]; pfb = bs[tid + 256];
        }

        uint32_t bBase = sb + ((c & 1) ? TP_B1 : TP_B0) + (uint32_t)rfr * RSTRIDE + cfr;
        float ptmp[8][4];
#pragma unroll
        for (int nt = 0; nt < 8; nt++)
#pragma unroll
            for (int q = 0; q < 4; q++) ptmp[nt][q] = 0.f;

#pragma unroll
        for (int ks = 0; ks < 4; ks++) {
            uint32_t bF[16];
#pragma unroll
            for (int p = 0; p < 4; p++)
                LDSM_X4T(&bF[p * 4], bBase + ks * (16 * RSTRIDE) + p * 32);
#pragma unroll
            for (int nt = 0; nt < 8; nt++)
                mma16816h(ptmp[nt], &aF[ks * 4], &bF[(nt >> 1) * 4 + (nt & 1) * 2]);
        }

        float f0 = s_nf[c * 128 + rowl];
        float f1 = s_nf[c * 128 + rowl + 8];
#pragma unroll
        for (int nt = 0; nt < 8; nt++) {
            acc[nt][0] += f0 * ptmp[nt][0];
            acc[nt][1] += f0 * ptmp[nt][1];
            acc[nt][2] += f1 * ptmp[nt][2];
            acc[nt][3] += f1 * ptmp[nt][3];
        }

        if (c < 15) {
            char* dst = smem + ((c & 1) ? TP_B0 : TP_B1);
            *(uint4*)(dst + ja * RSTRIDE + qb8 * 16) = pfa;
            *(uint4*)(dst + jb * RSTRIDE + qb8 * 16) = pfb;
            __syncthreads();
        }
    }

    float* part = g_part + blockIdx.y * (N_ * H_);
    int row0 = n0 + m0 + (lane >> 2);
    int colb = 2 * (lane & 3);
#pragma unroll
    for (int nt = 0; nt < 8; nt++) {
        int col = nt * 8 + colb;
        *(float2*)&part[row0 * H_ + col]       = make_float2(acc[nt][0], acc[nt][1]);
        *(float2*)&part[(row0 + 8) * H_ + col] = make_float2(acc[nt][2], acc[nt][3]);
    }
}

// ---------------- K5: sum the four i-quarter partials ----------------
__global__ void k_sum(float* __restrict__ out) {
    int idx = (blockIdx.x * 256 + threadIdx.x) * 4;
    float4 a = *(const float4*)&g_part[idx];
    float4 b = *(const float4*)&g_part[N_ * H_ + idx];
    float4 c = *(const float4*)&g_part[2 * N_ * H_ + idx];
    float4 d = *(const float4*)&g_part[3 * N_ * H_ + idx];
    *(float4*)&out[idx] = make_float4(a.x + b.x + c.x + d.x,
                                      a.y + b.y + c.y + d.y,
                                      a.z + b.z + c.z + d.z,
                                      a.w + b.w + c.w + d.w);
}

// ---------------- launch ----------------
extern "C" void kernel_launch(void* const* d_in, const int* in_sizes, int n_in,
                              void* d_out, int out_size) {
    const float* node_feat    = (const float*)d_in[0];
    const float* node_feat_sr = (const float*)d_in[1];
    const float* positions    = (const float*)d_in[2];
    const float* kvecs        = (const float*)d_in[3];
    const int*   batch        = (const int*)  d_in[4];
    const float* W_readout    = (const float*)d_in[5];
    const float* W_qkv        = (const float*)d_in[6];
    const float* W_tp         = (const float*)d_in[7];
    float* out = (float*)d_out;

    static int attr_done = 0;
    if (!attr_done) {
        cudaFuncSetAttribute(k_qkv, cudaFuncAttributeMaxDynamicSharedMemorySize, QKV_SMEM);
        cudaFuncSetAttribute(k_upd, cudaFuncAttributeMaxDynamicSharedMemorySize, UPD_SMEM);
        attr_done = 1;
    }

    k_prep <<<113, 256>>>(W_qkv, W_readout, W_tp, batch);
    k_qkv  <<<N_ / 32, 256, QKV_SMEM>>>(node_feat, positions, kvecs, batch);
    k_kvg  <<<dim3(G_ * T_, 2), 256>>>();
    k_upd  <<<160, 256, UPD_SMEM>>>();
    k_tpmma<<<dim3(N_ / 128, 4), 256, TP_SMEM>>>(node_feat_sr);
    k_sum  <<<(N_ * H_) / (256 * 4), 256>>>(out);
}

// round 8
// speedup vs baseline: 3.3765x; 1.6928x over previous
#include <cuda_runtime.h>
#include <cuda_fp16.h>
#include <math.h>
#include <stdint.h>

#define N_  4096
#define H_  64
#define T_  6
#define G_  16
#define TH_ 192    // 3*H
#define TD_ 384    // T*H

// ---------------- device scratch ----------------
__device__ float g_A[H_ * TH_];            // A[m][r] = Wc[r][m]
__device__ __align__(16) __half g_qr16[N_ * TD_];       // q fp16 [n][t*64+d]
__device__ __align__(16) __half g_k16 [N_ * TD_];       // k fp16 [n][t*64+d]
__device__ __align__(16) __half g_v16 [N_ * H_];        // v fp16 [n][e]
__device__ __align__(16) __half g_kvg16[G_ * TD_ * H_]; // kv_graph fp16 [g][td][e]
__device__ __align__(16) __half g_upd16[N_ * H_];       // update fp16 [n][j]
__device__ float g_part[4 * N_ * H_];      // four i-quarter partials
__device__ __half g_B16[H_ * H_ * H_];     // W_tp fp16, [i][j][k]
__device__ int   g_seg[G_ + 1];
__device__ int   g_tblg[256];
__device__ int   g_tbln[256];
__device__ int   g_nblk;

// ---------------- PTX helpers ----------------
__device__ __forceinline__ uint32_t smem_u32(const void* p) {
    uint32_t a;
    asm("{ .reg .u64 t; cvta.to.shared.u64 t, %1; cvt.u32.u64 %0, t; }" : "=r"(a) : "l"(p));
    return a;
}
#define LDSM_X4(r, addr) \
    asm volatile("ldmatrix.sync.aligned.m8n8.x4.shared.b16 {%0,%1,%2,%3}, [%4];" \
        : "=r"((r)[0]), "=r"((r)[1]), "=r"((r)[2]), "=r"((r)[3]) : "r"(addr))
#define LDSM_X4T(r, addr) \
    asm volatile("ldmatrix.sync.aligned.m8n8.x4.trans.shared.b16 {%0,%1,%2,%3}, [%4];" \
        : "=r"((r)[0]), "=r"((r)[1]), "=r"((r)[2]), "=r"((r)[3]) : "r"(addr))

__device__ __forceinline__ void mma16816h(float* d, const uint32_t* a, const uint32_t* b) {
    asm volatile(
        "mma.sync.aligned.m16n8k16.row.col.f32.f16.f16.f32 "
        "{%0,%1,%2,%3}, {%4,%5,%6,%7}, {%8,%9}, {%0,%1,%2,%3};"
        : "+f"(d[0]), "+f"(d[1]), "+f"(d[2]), "+f"(d[3])
        : "r"(a[0]), "r"(a[1]), "r"(a[2]), "r"(a[3]), "r"(b[0]), "r"(b[1]));
}

// ---------------- K0: fused prep ----------------
__global__ void k_prep(const float* __restrict__ Wqkv, const float* __restrict__ Wro,
                       const float* __restrict__ Wtp, const int* __restrict__ batch) {
    int bid = blockIdx.x;
    int tid = threadIdx.x;       // 256
    if (bid < 48) {
        __shared__ float srow[4][64];
        int rr = tid >> 6, m = tid & 63;
        int r = bid * 4 + rr;
        srow[rr][m] = Wqkv[r * H_ + m];
        __syncthreads();
        float s = 0.f;
#pragma unroll 8
        for (int u = 0; u < H_; u++) s += srow[rr][u] * Wro[u * H_ + m];
        g_A[m * TH_ + r] = s;
    } else if (bid < 112) {
        int i = bid - 48;
        __shared__ float s[64 * 65];
#pragma unroll
        for (int p = 0; p < 16; p++) {
            int l = p * 256 + tid;
            int k = l >> 6, j = l & 63;
            s[k * 65 + j] = Wtp[k * 4096 + i * 64 + j];
        }
        __syncthreads();
#pragma unroll
        for (int p = 0; p < 16; p++) {
            int l = p * 256 + tid;
            int j = l >> 6, k = l & 63;
            g_B16[i * 4096 + j * 64 + k] = __float2half_rn(s[k * 65 + j]);
        }
    } else {
        if (tid <= G_) {
            int lo = 0, hi = N_;
            while (lo < hi) {
                int mid = (lo + hi) >> 1;
                if (batch[mid] < tid) lo = mid + 1; else hi = mid;
            }
            g_seg[tid] = lo;
        }
        __syncthreads();
        if (tid == 0) {
            int b = 0;
            for (int gg = 0; gg < G_; gg++)
                for (int s0 = g_seg[gg]; s0 < g_seg[gg + 1]; s0 += 64) {
                    g_tblg[b] = gg; g_tbln[b] = s0; b++;
                }
            g_nblk = b;
        }
    }
}

// ---------------- K1: qkv tiled GEMM (32 nodes/block) + silu + rope -----------
#define QKV_SA   0
#define QKV_NF   49152
#define QKV_QKV  58368
#define QKV_C    83968
#define QKV_S    84992
#define QKV_SMEM 86016

__global__ void __launch_bounds__(256) k_qkv(const float* __restrict__ node_feat,
                                             const float* __restrict__ positions,
                                             const float* __restrict__ kvecs,
                                             const int*   __restrict__ batch) {
    extern __shared__ char sm[];
    float* s_A   = (float*)(sm + QKV_SA);
    float* s_nfT = (float*)(sm + QKV_NF);
    float* s_qkv = (float*)(sm + QKV_QKV);
    float* s_c   = (float*)(sm + QKV_C);
    float* s_s   = (float*)(sm + QKV_S);
    int tid = threadIdx.x;       // 256
    int n0 = blockIdx.x * 32;

#pragma unroll
    for (int p = 0; p < 48; p++) s_A[p * 256 + tid] = g_A[p * 256 + tid];
#pragma unroll
    for (int p = 0; p < 8; p++) {
        int l = p * 256 + tid;
        int nn = l >> 6, k = l & 63;
        s_nfT[k * 36 + nn] = node_feat[(n0 + nn) * H_ + k];
    }
    __syncthreads();

    int tn = tid >> 5, tr = tid & 31;
    float acc[4][6];
#pragma unroll
    for (int nn = 0; nn < 4; nn++)
#pragma unroll
        for (int u = 0; u < 6; u++) acc[nn][u] = 0.f;

#pragma unroll 4
    for (int k = 0; k < 64; k++) {
        float4 nf4 = *(const float4*)&s_nfT[k * 36 + tn * 4];
        float av[6];
#pragma unroll
        for (int u = 0; u < 6; u++) av[u] = s_A[k * 192 + tr + 32 * u];
#pragma unroll
        for (int u = 0; u < 6; u++) {
            acc[0][u] += nf4.x * av[u];
            acc[1][u] += nf4.y * av[u];
            acc[2][u] += nf4.z * av[u];
            acc[3][u] += nf4.w * av[u];
        }
    }
    __syncthreads();

#pragma unroll
    for (int nn = 0; nn < 4; nn++) {
        int node = tn * 4 + nn;
#pragma unroll
        for (int u = 0; u < 6; u++) {
            int r = tr + 32 * u;
            float v = acc[nn][u];
            if (r < 2 * H_) v = v / (1.f + __expf(-v));
            s_qkv[node * 200 + r] = v;
        }
    }
    if (tid < 192) {
        int nn = tid / 6, t = tid % 6;
        int g = batch[n0 + nn];
        const float* kv = kvecs + (g * T_ + t) * 3;
        float ph = positions[(n0 + nn) * 3 + 0] * kv[0]
                 + positions[(n0 + nn) * 3 + 1] * kv[1]
                 + positions[(n0 + nn) * 3 + 2] * kv[2];
        float sv, cv;
        sincosf(ph, &sv, &cv);
        s_c[nn * 8 + t] = cv; s_s[nn * 8 + t] = sv;
    }
    __syncthreads();

#pragma unroll
    for (int p = 0; p < 48; p++) {
        int l = p * 256 + tid;
        int nn = l / 384, idx = l - nn * 384;
        int t = idx >> 6, d = idx & 63;
        int m2 = (d & 31) * 2;
        float c = s_c[nn * 8 + t], sv = s_s[nn * 8 + t];
        float qa = s_qkv[nn * 200 + m2],       qb = s_qkv[nn * 200 + m2 + 1];
        float ka = s_qkv[nn * 200 + 64 + m2],  kb = s_qkv[nn * 200 + 64 + m2 + 1];
        float qv, kvv;
        if (d < 32) { qv = qa * c  - qb * sv;  kvv = ka * c  - kb * sv; }
        else        { qv = qa * sv + qb * c;   kvv = ka * sv + kb * c;  }
        int n = n0 + nn;
        g_qr16[n * TD_ + idx] = __float2half_rn(qv * 0.125f);
        g_k16 [n * TD_ + idx] = __float2half_rn(kvv);
    }
#pragma unroll
    for (int p = 0; p < 8; p++) {
        int l = p * 256 + tid;
        int nn = l >> 6, m = l & 63;
        g_v16[(n0 + nn) * H_ + m] = __float2half_rn(s_qkv[nn * 200 + 128 + m]);
    }
}

// ---------------- K2: kv_graph via HMMA: C[64d x 64e] = sum_n k^T v ----------
// per (g,t) block; k transposed in-block with row-granular segment masking.
#define KVG_KT 0       // 64 rows x 80B = 5120
#define KVG_V  5120    // 32 rows x 144B = 4608

__global__ void __launch_bounds__(256) k_kvg() {
    __shared__ __align__(16) char sm[5120 + 4608];
    uint32_t sb = smem_u32(sm);
    int bid = blockIdx.x;
    int g = bid / T_, t = bid % T_;
    int tid = threadIdx.x;
    int lane = tid & 31, w = tid >> 5;
    int wm = w & 3, wn = w >> 2;          // m16 of d, e32 half

    int s = g_seg[g], e = g_seg[g + 1];
    int nb0 = s & ~31;

    int rfr = (lane & 7) + ((lane >> 3) & 1) * 8;
    int cfr = (lane >> 4) * 16;

    float acc[4][4];
#pragma unroll
    for (int nt = 0; nt < 4; nt++)
#pragma unroll
        for (int q = 0; q < 4; q++) acc[nt][q] = 0.f;

    int pp = tid & 15, oo = tid >> 4;     // n-pair, d-quad
    int vr = tid >> 3, vq = tid & 7;      // v fill row / uint4

    for (int nb = nb0; nb < e; nb += 32) {
        // kT fill: transpose k[n][d] -> kT[d][n], rows masked to [s,e)
        int n1 = nb + 2 * pp, n2 = n1 + 1;
        uint2 ra = make_uint2(0u, 0u), rb = make_uint2(0u, 0u);
        if (n1 >= s && n1 < e) ra = *(const uint2*)(g_k16 + n1 * TD_ + t * 64 + oo * 4);
        if (n2 >= s && n2 < e) rb = *(const uint2*)(g_k16 + n2 * TD_ + t * 64 + oo * 4);
        const __half* ah = (const __half*)&ra;
        const __half* bh = (const __half*)&rb;
#pragma unroll
        for (int dd = 0; dd < 4; dd++) {
            __half2 h = __halves2half2(ah[dd], bh[dd]);
            *(__half2*)(sm + KVG_KT + (oo * 4 + dd) * 80 + pp * 4) = h;
        }
        // v fill: rows masked
        {
            int n = nb + vr;
            uint4 val = make_uint4(0u, 0u, 0u, 0u);
            if (n >= s && n < e) val = *(const uint4*)(g_v16 + n * H_ + vq * 8);
            *(uint4*)(sm + KVG_V + vr * 144 + vq * 16) = val;
        }
        __syncthreads();

#pragma unroll
        for (int ks = 0; ks < 2; ks++) {
            uint32_t aF[4], bF[8];
            LDSM_X4(aF, sb + KVG_KT + (uint32_t)(wm * 16 + rfr) * 80 + cfr + ks * 32);
            LDSM_X4T(&bF[0], sb + KVG_V + (uint32_t)(ks * 16 + rfr) * 144 + wn * 64 + cfr);
            LDSM_X4T(&bF[4], sb + KVG_V + (uint32_t)(ks * 16 + rfr) * 144 + wn * 64 + 32 + cfr);
            mma16816h(acc[0], aF, &bF[0]);
            mma16816h(acc[1], aF, &bF[2]);
            mma16816h(acc[2], aF, &bF[4]);
            mma16816h(acc[3], aF, &bF[6]);
        }
        __syncthreads();
    }

    __half* outb = g_kvg16 + (g * TD_ + t * 64) * H_;
    int d0 = wm * 16 + (lane >> 2);
    int cb = 2 * (lane & 3);
#pragma unroll
    for (int nt = 0; nt < 4; nt++) {
        int ec = wn * 32 + nt * 8 + cb;
        *(__half2*)(outb + d0 * H_ + ec)       = __floats2half2_rn(acc[nt][0], acc[nt][1]);
        *(__half2*)(outb + (d0 + 8) * H_ + ec) = __floats2half2_rn(acc[nt][2], acc[nt][3]);
    }
}

// ---------------- K3: update via HMMA: [64 x 384] @ [384 x 64], 512 thr -------
#define UPD_Q    0
#define UPD_KV   55296
#define UPD_SMEM 110592
#define RSTRIDE 144   // 72 fp16 row stride (bytes)

__global__ void __launch_bounds__(512) k_upd() {
    int b = blockIdx.x;
    if (b >= g_nblk) return;
    int g  = g_tblg[b];
    int ns = g_tbln[b];
    int ne = min(ns + 64, g_seg[g + 1]);

    extern __shared__ char sm[];
    uint32_t sb = smem_u32(sm);
    int tid = threadIdx.x;       // 512
    int lane = tid & 31, w = tid >> 5;

    // q fill: 64 rows x 384 fp16, zero pad rows >= ne
#pragma unroll
    for (int p = 0; p < 6; p++) {
        int idx = p * 512 + tid;            // 0..3071 uint4
        int nl = idx / 48, c8 = idx % 48;
        uint4 val = make_uint4(0u, 0u, 0u, 0u);
        if (ns + nl < ne) val = *(const uint4*)(g_qr16 + (ns + nl) * TD_ + c8 * 8);
        int ch = c8 >> 3, q8 = c8 & 7;
        *(uint4*)(sm + UPD_Q + ch * (64 * RSTRIDE) + nl * RSTRIDE + q8 * 16) = val;
    }
    // kv fill: 384 rows x 64 fp16
    const __half* kvsrc = g_kvg16 + g * (TD_ * H_);
#pragma unroll
    for (int p = 0; p < 6; p++) {
        int idx = p * 512 + tid;            // 0..3071 uint4
        int td = idx >> 3, q8 = idx & 7;
        uint4 val = *(const uint4*)(kvsrc + td * 64 + q8 * 8);
        int ch = td >> 6, r = td & 63;
        *(uint4*)(sm + UPD_KV + ch * (64 * RSTRIDE) + r * RSTRIDE + q8 * 16) = val;
    }
    __syncthreads();

    int wm = w & 3, weg = w >> 2;            // m16 tile of 64 nodes, e-group of 16
    int rfr = (lane & 7) + ((lane >> 3) & 1) * 8;
    int cfr = (lane >> 4) * 16;

    float acc[2][4];
#pragma unroll
    for (int nt = 0; nt < 2; nt++)
#pragma unroll
        for (int q = 0; q < 4; q++) acc[nt][q] = 0.f;

#pragma unroll
    for (int ch = 0; ch < 6; ch++) {
        uint32_t aB = sb + UPD_Q  + ch * (64 * RSTRIDE) + (uint32_t)(wm * 16 + rfr) * RSTRIDE + cfr;
        uint32_t bB = sb + UPD_KV + ch * (64 * RSTRIDE) + (uint32_t)rfr * RSTRIDE + cfr + weg * 32;
#pragma unroll
        for (int ks = 0; ks < 4; ks++) {
            uint32_t aF[4], bF[4];
            LDSM_X4(aF, aB + ks * 32);
            LDSM_X4T(bF, bB + ks * (16 * RSTRIDE));
            mma16816h(acc[0], aF, &bF[0]);
            mma16816h(acc[1], aF, &bF[2]);
        }
    }

    int r0 = wm * 16 + (lane >> 2);
    int cb = 2 * (lane & 3);
#pragma unroll
    for (int nt = 0; nt < 2; nt++) {
        int e = weg * 16 + nt * 8 + cb;
        int n = ns + r0;
        if (n < ne)
            *(__half2*)(g_upd16 + n * H_ + e) = __floats2half2_rn(acc[nt][0], acc[nt][1]);
        if (n + 8 < ne)
            *(__half2*)(g_upd16 + (n + 8) * H_ + e) = __floats2half2_rn(acc[nt][2], acc[nt][3]);
    }
}

// ---------------- K4: tensor-product GEMM, A-frags resident, B double-buffered -
#define TP_U    0
#define TP_B0   18432
#define TP_B1   27648
#define TP_NF   36864
#define TP_SMEM 45056

__global__ void __launch_bounds__(256) k_tpmma(const float* __restrict__ nfsr) {
    extern __shared__ char smem[];
    uint32_t sb = smem_u32(smem);
    int tid = threadIdx.x;
    int wid = tid >> 5, lane = tid & 31;
    int n0 = blockIdx.x * 128;
    int i0 = blockIdx.y * 16;

    float* s_nf = (float*)(smem + TP_NF);     // [c][128]

#pragma unroll
    for (int p = 0; p < 8; p++) {
        int l = p * 256 + tid;
        int nl = l >> 4, ii = l & 15;
        s_nf[ii * 128 + nl] = nfsr[(n0 + nl) * H_ + i0 + ii];
    }
#pragma unroll
    for (int p = 0; p < 4; p++) {
        int idx = p * 256 + tid;              // 0..1023 uint4
        int n = idx >> 3, q8 = idx & 7;
        *(uint4*)(smem + TP_U + n * RSTRIDE + q8 * 16) =
            *(const uint4*)(g_upd16 + (n0 + n) * H_ + q8 * 8);
    }
    {
        const uint4* bs = (const uint4*)(g_B16 + i0 * 4096);
        uint4 b0 = bs[tid], b1 = bs[tid + 256];
        int q = tid & 7;
        int ja = tid >> 3, jb = (tid + 256) >> 3;
        *(uint4*)(smem + TP_B0 + ja * RSTRIDE + q * 16) = b0;
        *(uint4*)(smem + TP_B0 + jb * RSTRIDE + q * 16) = b1;
    }
    __syncthreads();

    int m0 = wid * 16;
    int rfr = (lane & 7) + ((lane >> 3) & 1) * 8;
    int cfr = (lane >> 4) * 16;
    uint32_t aF[16];
    {
        uint32_t aAddr = sb + TP_U + (uint32_t)(m0 + rfr) * RSTRIDE + cfr;
#pragma unroll
        for (int ks = 0; ks < 4; ks++) LDSM_X4(&aF[ks * 4], aAddr + ks * 32);
    }

    float acc[8][4];
#pragma unroll
    for (int nt = 0; nt < 8; nt++)
#pragma unroll
        for (int q = 0; q < 4; q++) acc[nt][q] = 0.f;

    int rowl = m0 + (lane >> 2);
    int qb8 = tid & 7;
    int ja = tid >> 3, jb = (tid + 256) >> 3;

    for (int c = 0; c < 16; c++) {
        uint4 pfa, pfb;
        if (c < 15) {
            const uint4* bs = (const uint4*)(g_B16 + (i0 + c + 1) * 4096);
            pfa = bs[tid]; pfb = bs[tid + 256];
        }

        uint32_t bBase = sb + ((c & 1) ? TP_B1 : TP_B0) + (uint32_t)rfr * RSTRIDE + cfr;
        float ptmp[8][4];
#pragma unroll
        for (int nt = 0; nt < 8; nt++)
#pragma unroll
            for (int q = 0; q < 4; q++) ptmp[nt][q] = 0.f;

#pragma unroll
        for (int ks = 0; ks < 4; ks++) {
            uint32_t bF[16];
#pragma unroll
            for (int p = 0; p < 4; p++)
                LDSM_X4T(&bF[p * 4], bBase + ks * (16 * RSTRIDE) + p * 32);
#pragma unroll
            for (int nt = 0; nt < 8; nt++)
                mma16816h(ptmp[nt], &aF[ks * 4], &bF[(nt >> 1) * 4 + (nt & 1) * 2]);
        }

        float f0 = s_nf[c * 128 + rowl];
        float f1 = s_nf[c * 128 + rowl + 8];
#pragma unroll
        for (int nt = 0; nt < 8; nt++) {
            acc[nt][0] += f0 * ptmp[nt][0];
            acc[nt][1] += f0 * ptmp[nt][1];
            acc[nt][2] += f1 * ptmp[nt][2];
            acc[nt][3] += f1 * ptmp[nt][3];
        }

        if (c < 15) {
            char* dst = smem + ((c & 1) ? TP_B0 : TP_B1);
            *(uint4*)(dst + ja * RSTRIDE + qb8 * 16) = pfa;
            *(uint4*)(dst + jb * RSTRIDE + qb8 * 16) = pfb;
            __syncthreads();
        }
    }

    float* part = g_part + blockIdx.y * (N_ * H_);
    int row0 = n0 + m0 + (lane >> 2);
    int colb = 2 * (lane & 3);
#pragma unroll
    for (int nt = 0; nt < 8; nt++) {
        int col = nt * 8 + colb;
        *(float2*)&part[row0 * H_ + col]       = make_float2(acc[nt][0], acc[nt][1]);
        *(float2*)&part[(row0 + 8) * H_ + col] = make_float2(acc[nt][2], acc[nt][3]);
    }
}

// ---------------- K5: sum the four i-quarter partials ----------------
__global__ void k_sum(float* __restrict__ out) {
    int idx = (blockIdx.x * 256 + threadIdx.x) * 4;
    float4 a = *(const float4*)&g_part[idx];
    float4 b = *(const float4*)&g_part[N_ * H_ + idx];
    float4 c = *(const float4*)&g_part[2 * N_ * H_ + idx];
    float4 d = *(const float4*)&g_part[3 * N_ * H_ + idx];
    *(float4*)&out[idx] = make_float4(a.x + b.x + c.x + d.x,
                                      a.y + b.y + c.y + d.y,
                                      a.z + b.z + c.z + d.z,
                                      a.w + b.w + c.w + d.w);
}

// ---------------- launch ----------------
extern "C" void kernel_launch(void* const* d_in, const int* in_sizes, int n_in,
                              void* d_out, int out_size) {
    const float* node_feat    = (const float*)d_in[0];
    const float* node_feat_sr = (const float*)d_in[1];
    const float* positions    = (const float*)d_in[2];
    const float* kvecs        = (const float*)d_in[3];
    const int*   batch        = (const int*)  d_in[4];
    const float* W_readout    = (const float*)d_in[5];
    const float* W_qkv        = (const float*)d_in[6];
    const float* W_tp         = (const float*)d_in[7];
    float* out = (float*)d_out;

    static int attr_done = 0;
    if (!attr_done) {
        cudaFuncSetAttribute(k_qkv, cudaFuncAttributeMaxDynamicSharedMemorySize, QKV_SMEM);
        cudaFuncSetAttribute(k_upd, cudaFuncAttributeMaxDynamicSharedMemorySize, UPD_SMEM);
        attr_done = 1;
    }

    k_prep <<<113, 256>>>(W_qkv, W_readout, W_tp, batch);
    k_qkv  <<<N_ / 32, 256, QKV_SMEM>>>(node_feat, positions, kvecs, batch);
    k_kvg  <<<G_ * T_, 256>>>();
    k_upd  <<<96, 512, UPD_SMEM>>>();
    k_tpmma<<<dim3(N_ / 128, 4), 256, TP_SMEM>>>(node_feat_sr);
    k_sum  <<<(N_ * H_) / (256 * 4), 256>>>(out);
}

// round 9
// speedup vs baseline: 3.5187x; 1.0421x over previous
#include <cuda_runtime.h>
#include <cuda_fp16.h>
#include <math.h>
#include <stdint.h>

#define N_  4096
#define H_  64
#define T_  6
#define G_  16
#define TH_ 192    // 3*H
#define TD_ 384    // T*H

// ---------------- device scratch ----------------
__device__ float g_A[H_ * TH_];            // A[m][r] = Wc[r][m]
__device__ __align__(16) __half g_qr16[N_ * TD_];       // q fp16 [n][t*64+d]
__device__ __align__(16) __half g_k16 [N_ * TD_];       // k fp16 [n][t*64+d]
__device__ __align__(16) __half g_v16 [N_ * H_];        // v fp16 [n][e]
__device__ __align__(16) __half g_kvg16[G_ * TD_ * H_]; // kv_graph fp16 [g][td][e]
__device__ __align__(16) float  g_updf[N_ * H_];        // update fp32 [n][e] (atomic)
__device__ __half g_B16[H_ * H_ * H_];     // W_tp fp16, [i][j][k]
__device__ int   g_seg[G_ + 1];
__device__ int   g_tblg[256];
__device__ int   g_tbln[256];
__device__ int   g_nblk;

#define RSTRIDE 144   // 72 fp16 row stride (bytes)

// ---------------- PTX helpers ----------------
__device__ __forceinline__ uint32_t smem_u32(const void* p) {
    uint32_t a;
    asm("{ .reg .u64 t; cvta.to.shared.u64 t, %1; cvt.u32.u64 %0, t; }" : "=r"(a) : "l"(p));
    return a;
}
#define LDSM_X4(r, addr) \
    asm volatile("ldmatrix.sync.aligned.m8n8.x4.shared.b16 {%0,%1,%2,%3}, [%4];" \
        : "=r"((r)[0]), "=r"((r)[1]), "=r"((r)[2]), "=r"((r)[3]) : "r"(addr))
#define LDSM_X4T(r, addr) \
    asm volatile("ldmatrix.sync.aligned.m8n8.x4.trans.shared.b16 {%0,%1,%2,%3}, [%4];" \
        : "=r"((r)[0]), "=r"((r)[1]), "=r"((r)[2]), "=r"((r)[3]) : "r"(addr))

__device__ __forceinline__ void mma16816h(float* d, const uint32_t* a, const uint32_t* b) {
    asm volatile(
        "mma.sync.aligned.m16n8k16.row.col.f32.f16.f16.f32 "
        "{%0,%1,%2,%3}, {%4,%5,%6,%7}, {%8,%9}, {%0,%1,%2,%3};"
        : "+f"(d[0]), "+f"(d[1]), "+f"(d[2]), "+f"(d[3])
        : "r"(a[0]), "r"(a[1]), "r"(a[2]), "r"(a[3]), "r"(b[0]), "r"(b[1]));
}

// ---------------- K0: fused prep (+ zeroing of g_updf and d_out) --------------
__global__ void k_prep(const float* __restrict__ Wqkv, const float* __restrict__ Wro,
                       const float* __restrict__ Wtp, const int* __restrict__ batch,
                       float* __restrict__ out) {
    int bid = blockIdx.x;
    int tid = threadIdx.x;       // 256
    if (bid < 48) {
        __shared__ float srow[4][64];
        int rr = tid >> 6, m = tid & 63;
        int r = bid * 4 + rr;
        srow[rr][m] = Wqkv[r * H_ + m];
        __syncthreads();
        float s = 0.f;
#pragma unroll 8
        for (int u = 0; u < H_; u++) s += srow[rr][u] * Wro[u * H_ + m];
        g_A[m * TH_ + r] = s;
    } else if (bid < 112) {
        int i = bid - 48;
        __shared__ float s[64 * 65];
#pragma unroll
        for (int p = 0; p < 16; p++) {
            int l = p * 256 + tid;
            int k = l >> 6, j = l & 63;
            s[k * 65 + j] = Wtp[k * 4096 + i * 64 + j];
        }
        __syncthreads();
#pragma unroll
        for (int p = 0; p < 16; p++) {
            int l = p * 256 + tid;
            int j = l >> 6, k = l & 63;
            g_B16[i * 4096 + j * 64 + k] = __float2half_rn(s[k * 65 + j]);
        }
    } else if (bid == 112) {
        if (tid <= G_) {
            int lo = 0, hi = N_;
            while (lo < hi) {
                int mid = (lo + hi) >> 1;
                if (batch[mid] < tid) lo = mid + 1; else hi = mid;
            }
            g_seg[tid] = lo;
        }
        __syncthreads();
        if (tid == 0) {
            int b = 0;
            for (int gg = 0; gg < G_; gg++)
                for (int s0 = g_seg[gg]; s0 < g_seg[gg + 1]; s0 += 64) {
                    g_tblg[b] = gg; g_tbln[b] = s0; b++;
                }
            g_nblk = b;
        }
    } else if (bid < 129) {
        // zero g_updf: 262144 floats / 16 blocks = 4096 float4 each
        float4* dst = (float4*)g_updf + (bid - 113) * 4096;
#pragma unroll
        for (int p = 0; p < 16; p++) dst[p * 256 + tid] = make_float4(0.f, 0.f, 0.f, 0.f);
    } else {
        // zero d_out
        float4* dst = (float4*)out + (bid - 129) * 4096;
#pragma unroll
        for (int p = 0; p < 16; p++) dst[p * 256 + tid] = make_float4(0.f, 0.f, 0.f, 0.f);
    }
}

// ---------------- K1: qkv tiled GEMM (32 nodes/block) + silu + rope -----------
#define QKV_SA   0
#define QKV_NF   49152
#define QKV_QKV  58368
#define QKV_C    83968
#define QKV_S    84992
#define QKV_SMEM 86016

__global__ void __launch_bounds__(256) k_qkv(const float* __restrict__ node_feat,
                                             const float* __restrict__ positions,
                                             const float* __restrict__ kvecs,
                                             const int*   __restrict__ batch) {
    extern __shared__ char sm[];
    float* s_A   = (float*)(sm + QKV_SA);
    float* s_nfT = (float*)(sm + QKV_NF);
    float* s_qkv = (float*)(sm + QKV_QKV);
    float* s_c   = (float*)(sm + QKV_C);
    float* s_s   = (float*)(sm + QKV_S);
    int tid = threadIdx.x;       // 256
    int n0 = blockIdx.x * 32;

#pragma unroll
    for (int p = 0; p < 48; p++) s_A[p * 256 + tid] = g_A[p * 256 + tid];
#pragma unroll
    for (int p = 0; p < 8; p++) {
        int l = p * 256 + tid;
        int nn = l >> 6, k = l & 63;
        s_nfT[k * 36 + nn] = node_feat[(n0 + nn) * H_ + k];
    }
    __syncthreads();

    int tn = tid >> 5, tr = tid & 31;
    float acc[4][6];
#pragma unroll
    for (int nn = 0; nn < 4; nn++)
#pragma unroll
        for (int u = 0; u < 6; u++) acc[nn][u] = 0.f;

#pragma unroll 4
    for (int k = 0; k < 64; k++) {
        float4 nf4 = *(const float4*)&s_nfT[k * 36 + tn * 4];
        float av[6];
#pragma unroll
        for (int u = 0; u < 6; u++) av[u] = s_A[k * 192 + tr + 32 * u];
#pragma unroll
        for (int u = 0; u < 6; u++) {
            acc[0][u] += nf4.x * av[u];
            acc[1][u] += nf4.y * av[u];
            acc[2][u] += nf4.z * av[u];
            acc[3][u] += nf4.w * av[u];
        }
    }
    __syncthreads();

#pragma unroll
    for (int nn = 0; nn < 4; nn++) {
        int node = tn * 4 + nn;
#pragma unroll
        for (int u = 0; u < 6; u++) {
            int r = tr + 32 * u;
            float v = acc[nn][u];
            if (r < 2 * H_) v = v / (1.f + __expf(-v));
            s_qkv[node * 200 + r] = v;
        }
    }
    if (tid < 192) {
        int nn = tid / 6, t = tid % 6;
        int g = batch[n0 + nn];
        const float* kv = kvecs + (g * T_ + t) * 3;
        float ph = positions[(n0 + nn) * 3 + 0] * kv[0]
                 + positions[(n0 + nn) * 3 + 1] * kv[1]
                 + positions[(n0 + nn) * 3 + 2] * kv[2];
        float sv, cv;
        sincosf(ph, &sv, &cv);
        s_c[nn * 8 + t] = cv; s_s[nn * 8 + t] = sv;
    }
    __syncthreads();

#pragma unroll
    for (int p = 0; p < 48; p++) {
        int l = p * 256 + tid;
        int nn = l / 384, idx = l - nn * 384;
        int t = idx >> 6, d = idx & 63;
        int m2 = (d & 31) * 2;
        float c = s_c[nn * 8 + t], sv = s_s[nn * 8 + t];
        float qa = s_qkv[nn * 200 + m2],       qb = s_qkv[nn * 200 + m2 + 1];
        float ka = s_qkv[nn * 200 + 64 + m2],  kb = s_qkv[nn * 200 + 64 + m2 + 1];
        float qv, kvv;
        if (d < 32) { qv = qa * c  - qb * sv;  kvv = ka * c  - kb * sv; }
        else        { qv = qa * sv + qb * c;   kvv = ka * sv + kb * c;  }
        int n = n0 + nn;
        g_qr16[n * TD_ + idx] = __float2half_rn(qv * 0.125f);
        g_k16 [n * TD_ + idx] = __float2half_rn(kvv);
    }
#pragma unroll
    for (int p = 0; p < 8; p++) {
        int l = p * 256 + tid;
        int nn = l >> 6, m = l & 63;
        g_v16[(n0 + nn) * H_ + m] = __float2half_rn(s_qkv[nn * 200 + 128 + m]);
    }
}

// ---------------- K2: kv_graph via HMMA: C[64d x 64e] = sum_n k^T v ----------
#define KVG_KT 0       // 64 rows x 80B = 5120
#define KVG_V  5120    // 32 rows x 144B = 4608

__global__ void __launch_bounds__(256) k_kvg() {
    __shared__ __align__(16) char sm[5120 + 4608];
    uint32_t sb = smem_u32(sm);
    int bid = blockIdx.x;
    int g = bid / T_, t = bid % T_;
    int tid = threadIdx.x;
    int lane = tid & 31, w = tid >> 5;
    int wm = w & 3, wn = w >> 2;          // m16 of d, e32 half

    int s = g_seg[g], e = g_seg[g + 1];
    int nb0 = s & ~31;

    int rfr = (lane & 7) + ((lane >> 3) & 1) * 8;
    int cfr = (lane >> 4) * 16;

    float acc[4][4];
#pragma unroll
    for (int nt = 0; nt < 4; nt++)
#pragma unroll
        for (int q = 0; q < 4; q++) acc[nt][q] = 0.f;

    int pp = tid & 15, oo = tid >> 4;     // n-pair, d-quad
    int vr = tid >> 3, vq = tid & 7;      // v fill row / uint4

    for (int nb = nb0; nb < e; nb += 32) {
        int n1 = nb + 2 * pp, n2 = n1 + 1;
        uint2 ra = make_uint2(0u, 0u), rb = make_uint2(0u, 0u);
        if (n1 >= s && n1 < e) ra = *(const uint2*)(g_k16 + n1 * TD_ + t * 64 + oo * 4);
        if (n2 >= s && n2 < e) rb = *(const uint2*)(g_k16 + n2 * TD_ + t * 64 + oo * 4);
        const __half* ah = (const __half*)&ra;
        const __half* bh = (const __half*)&rb;
#pragma unroll
        for (int dd = 0; dd < 4; dd++) {
            __half2 h = __halves2half2(ah[dd], bh[dd]);
            *(__half2*)(sm + KVG_KT + (oo * 4 + dd) * 80 + pp * 4) = h;
        }
        {
            int n = nb + vr;
            uint4 val = make_uint4(0u, 0u, 0u, 0u);
            if (n >= s && n < e) val = *(const uint4*)(g_v16 + n * H_ + vq * 8);
            *(uint4*)(sm + KVG_V + vr * 144 + vq * 16) = val;
        }
        __syncthreads();

#pragma unroll
        for (int ks = 0; ks < 2; ks++) {
            uint32_t aF[4], bF[8];
            LDSM_X4(aF, sb + KVG_KT + (uint32_t)(wm * 16 + rfr) * 80 + cfr + ks * 32);
            LDSM_X4T(&bF[0], sb + KVG_V + (uint32_t)(ks * 16 + rfr) * 144 + wn * 64 + cfr);
            LDSM_X4T(&bF[4], sb + KVG_V + (uint32_t)(ks * 16 + rfr) * 144 + wn * 64 + 32 + cfr);
            mma16816h(acc[0], aF, &bF[0]);
            mma16816h(acc[1], aF, &bF[2]);
            mma16816h(acc[2], aF, &bF[4]);
            mma16816h(acc[3], aF, &bF[6]);
        }
        __syncthreads();
    }

    __half* outb = g_kvg16 + (g * TD_ + t * 64) * H_;
    int d0 = wm * 16 + (lane >> 2);
    int cb = 2 * (lane & 3);
#pragma unroll
    for (int nt = 0; nt < 4; nt++) {
        int ec = wn * 32 + nt * 8 + cb;
        *(__half2*)(outb + d0 * H_ + ec)       = __floats2half2_rn(acc[nt][0], acc[nt][1]);
        *(__half2*)(outb + (d0 + 8) * H_ + ec) = __floats2half2_rn(acc[nt][2], acc[nt][3]);
    }
}

// ---------------- K3: update partial via HMMA, t-split, atomic fp32 -----------
// block (seg-block, t): [64n x 64k] @ [64k x 64e] += into g_updf
#define U2_Q  0
#define U2_KV 9216

__global__ void __launch_bounds__(256) k_upd2() {
    int sbi = blockIdx.x;
    if (sbi >= g_nblk) return;
    int t = blockIdx.y;
    int g  = g_tblg[sbi];
    int ns = g_tbln[sbi];
    int ne = min(ns + 64, g_seg[g + 1]);

    __shared__ __align__(16) char sm[18432];
    uint32_t sbm = smem_u32(sm);
    int tid = threadIdx.x;       // 256
    int lane = tid & 31, w = tid >> 5;

    // q fill: 64 rows x 64 halves, zero rows >= ne
#pragma unroll
    for (int p = 0; p < 2; p++) {
        int idx = p * 256 + tid;            // 0..511
        int nl = idx >> 3, q8 = idx & 7;
        uint4 val = make_uint4(0u, 0u, 0u, 0u);
        if (ns + nl < ne) val = *(const uint4*)(g_qr16 + (ns + nl) * TD_ + t * 64 + q8 * 8);
        *(uint4*)(sm + U2_Q + nl * RSTRIDE + q8 * 16) = val;
    }
    // kvg slice fill: 64 rows x 64 halves
    const __half* kvsrc = g_kvg16 + (g * TD_ + t * 64) * H_;
#pragma unroll
    for (int p = 0; p < 2; p++) {
        int idx = p * 256 + tid;
        int r = idx >> 3, q8 = idx & 7;
        *(uint4*)(sm + U2_KV + r * RSTRIDE + q8 * 16) = *(const uint4*)(kvsrc + r * 64 + q8 * 8);
    }
    __syncthreads();

    int wm = w & 3, weg = w >> 2;            // m16 tile, e32 half
    int rfr = (lane & 7) + ((lane >> 3) & 1) * 8;
    int cfr = (lane >> 4) * 16;

    float acc[4][4];
#pragma unroll
    for (int nt = 0; nt < 4; nt++)
#pragma unroll
        for (int q = 0; q < 4; q++) acc[nt][q] = 0.f;

    uint32_t aB = sbm + U2_Q  + (uint32_t)(wm * 16 + rfr) * RSTRIDE + cfr;
    uint32_t bB = sbm + U2_KV + (uint32_t)rfr * RSTRIDE + weg * 64 + cfr;
#pragma unroll
    for (int ks = 0; ks < 4; ks++) {
        uint32_t aF[4], bF[8];
        LDSM_X4(aF, aB + ks * 32);
        LDSM_X4T(&bF[0], bB + ks * (16 * RSTRIDE));
        LDSM_X4T(&bF[4], bB + ks * (16 * RSTRIDE) + 32);
        mma16816h(acc[0], aF, &bF[0]);
        mma16816h(acc[1], aF, &bF[2]);
        mma16816h(acc[2], aF, &bF[4]);
        mma16816h(acc[3], aF, &bF[6]);
    }

    int r0 = wm * 16 + (lane >> 2);
    int cb = 2 * (lane & 3);
    int n1 = ns + r0, n2 = n1 + 8;
#pragma unroll
    for (int nt = 0; nt < 4; nt++) {
        int e = weg * 32 + nt * 8 + cb;
        if (n1 < ne) {
            atomicAdd(&g_updf[n1 * H_ + e],     acc[nt][0]);
            atomicAdd(&g_updf[n1 * H_ + e + 1], acc[nt][1]);
        }
        if (n2 < ne) {
            atomicAdd(&g_updf[n2 * H_ + e],     acc[nt][2]);
            atomicAdd(&g_updf[n2 * H_ + e + 1], acc[nt][3]);
        }
    }
}

// ---------------- K4: tensor-product GEMM, atomic output ----------------------
#define TP_U    0
#define TP_B0   18432
#define TP_B1   27648
#define TP_NF   36864
#define TP_SMEM 45056

__global__ void __launch_bounds__(256) k_tpmma(const float* __restrict__ nfsr,
                                               float* __restrict__ out) {
    extern __shared__ char smem[];
    uint32_t sb = smem_u32(smem);
    int tid = threadIdx.x;
    int wid = tid >> 5, lane = tid & 31;
    int n0 = blockIdx.x * 128;
    int i0 = blockIdx.y * 16;

    float* s_nf = (float*)(smem + TP_NF);     // [c][128]

#pragma unroll
    for (int p = 0; p < 8; p++) {
        int l = p * 256 + tid;
        int nl = l >> 4, ii = l & 15;
        s_nf[ii * 128 + nl] = nfsr[(n0 + nl) * H_ + i0 + ii];
    }
    // build fp16 U tile from fp32 g_updf
#pragma unroll
    for (int p = 0; p < 4; p++) {
        int idx = p * 256 + tid;              // 0..1023
        int n = idx >> 3, q8 = idx & 7;
        const float4* src = (const float4*)(g_updf + (n0 + n) * H_ + q8 * 8);
        float4 u0 = src[0], u1 = src[1];
        __half2 h0 = __floats2half2_rn(u0.x, u0.y);
        __half2 h1 = __floats2half2_rn(u0.z, u0.w);
        __half2 h2 = __floats2half2_rn(u1.x, u1.y);
        __half2 h3 = __floats2half2_rn(u1.z, u1.w);
        uint4 val = make_uint4(*(uint32_t*)&h0, *(uint32_t*)&h1,
                               *(uint32_t*)&h2, *(uint32_t*)&h3);
        *(uint4*)(smem + TP_U + n * RSTRIDE + q8 * 16) = val;
    }
    {
        const uint4* bs = (const uint4*)(g_B16 + i0 * 4096);
        uint4 b0 = bs[tid], b1 = bs[tid + 256];
        int q = tid & 7;
        int ja = tid >> 3, jb = (tid + 256) >> 3;
        *(uint4*)(smem + TP_B0 + ja * RSTRIDE + q * 16) = b0;
        *(uint4*)(smem + TP_B0 + jb * RSTRIDE + q * 16) = b1;
    }
    __syncthreads();

    int m0 = wid * 16;
    int rfr = (lane & 7) + ((lane >> 3) & 1) * 8;
    int cfr = (lane >> 4) * 16;
    uint32_t aF[16];
    {
        uint32_t aAddr = sb + TP_U + (uint32_t)(m0 + rfr) * RSTRIDE + cfr;
#pragma unroll
        for (int ks = 0; ks < 4; ks++) LDSM_X4(&aF[ks * 4], aAddr + ks * 32);
    }

    float acc[8][4];
#pragma unroll
    for (int nt = 0; nt < 8; nt++)
#pragma unroll
        for (int q = 0; q < 4; q++) acc[nt][q] = 0.f;

    int rowl = m0 + (lane >> 2);
    int qb8 = tid & 7;
    int ja = tid >> 3, jb = (tid + 256) >> 3;

    for (int c = 0; c < 16; c++) {
        uint4 pfa, pfb;
        if (c < 15) {
            const uint4* bs = (const uint4*)(g_B16 + (i0 + c + 1) * 4096);
            pfa = bs[tid]; pfb = bs[tid + 256];
        }

        uint32_t bBase = sb + ((c & 1) ? TP_B1 : TP_B0) + (uint32_t)rfr * RSTRIDE + cfr;
        float ptmp[8][4];
#pragma unroll
        for (int nt = 0; nt < 8; nt++)
#pragma unroll
            for (int q = 0; q < 4; q++) ptmp[nt][q] = 0.f;

#pragma unroll
        for (int ks = 0; ks < 4; ks++) {
            uint32_t bF[16];
#pragma unroll
            for (int p = 0; p < 4; p++)
                LDSM_X4T(&bF[p * 4], bBase + ks * (16 * RSTRIDE) + p * 32);
#pragma unroll
            for (int nt = 0; nt < 8; nt++)
                mma16816h(ptmp[nt], &aF[ks * 4], &bF[(nt >> 1) * 4 + (nt & 1) * 2]);
        }

        float f0 = s_nf[c * 128 + rowl];
        float f1 = s_nf[c * 128 + rowl + 8];
#pragma unroll
        for (int nt = 0; nt < 8; nt++) {
            acc[nt][0] += f0 * ptmp[nt][0];
            acc[nt][1] += f0 * ptmp[nt][1];
            acc[nt][2] += f1 * ptmp[nt][2];
            acc[nt][3] += f1 * ptmp[nt][3];
        }

        if (c < 15) {
            char* dst = smem + ((c & 1) ? TP_B0 : TP_B1);
            *(uint4*)(dst + ja * RSTRIDE + qb8 * 16) = pfa;
            *(uint4*)(dst + jb * RSTRIDE + qb8 * 16) = pfb;
            __syncthreads();
        }
    }

    int row0 = n0 + m0 + (lane >> 2);
    int colb = 2 * (lane & 3);
#pragma unroll
    for (int nt = 0; nt < 8; nt++) {
        int col = nt * 8 + colb;
        atomicAdd(&out[row0 * H_ + col],           acc[nt][0]);
        atomicAdd(&out[row0 * H_ + col + 1],       acc[nt][1]);
        atomicAdd(&out[(row0 + 8) * H_ + col],     acc[nt][2]);
        atomicAdd(&out[(row0 + 8) * H_ + col + 1], acc[nt][3]);
    }
}

// ---------------- launch ----------------
extern "C" void kernel_launch(void* const* d_in, const int* in_sizes, int n_in,
                              void* d_out, int out_size) {
    const float* node_feat    = (const float*)d_in[0];
    const float* node_feat_sr = (const float*)d_in[1];
    const float* positions    = (const float*)d_in[2];
    const float* kvecs        = (const float*)d_in[3];
    const int*   batch        = (const int*)  d_in[4];
    const float* W_readout    = (const float*)d_in[5];
    const float* W_qkv        = (const float*)d_in[6];
    const float* W_tp         = (const float*)d_in[7];
    float* out = (float*)d_out;

    static int attr_done = 0;
    if (!attr_done) {
        cudaFuncSetAttribute(k_qkv, cudaFuncAttributeMaxDynamicSharedMemorySize, QKV_SMEM);
        attr_done = 1;
    }

    k_prep <<<145, 256>>>(W_qkv, W_readout, W_tp, batch, out);
    k_qkv  <<<N_ / 32, 256, QKV_SMEM>>>(node_feat, positions, kvecs, batch);
    k_kvg  <<<G_ * T_, 256>>>();
    k_upd2 <<<dim3(96, 6), 256>>>();
    k_tpmma<<<dim3(N_ / 128, 4), 256, TP_SMEM>>>(node_feat_sr, out);
}

// round 10
// speedup vs baseline: 3.8592x; 1.0968x over previous
#include <cuda_runtime.h>
#include <cuda_fp16.h>
#include <math.h>
#include <stdint.h>

#define N_  4096
#define H_  64
#define T_  6
#define G_  16
#define TH_ 192    // 3*H
#define TD_ 384    // T*H

// ---------------- device scratch ----------------
__device__ float g_A[H_ * TH_];            // A[m][r] = Wc[r][m]
__device__ __align__(16) __half g_qr16[N_ * TD_];       // q fp16 [n][t*64+d]
__device__ __align__(16) __half g_k16 [N_ * TD_];       // k fp16 [n][t*64+d]
__device__ __align__(16) __half g_v16 [N_ * H_];        // v fp16 [n][e]
__device__ __align__(16) __half g_kvg16[G_ * TD_ * H_]; // kv_graph fp16 [g][td][e]
__device__ __align__(16) float  g_updf[N_ * H_];        // update fp32 [n][e] (atomic)
__device__ __half g_B16[H_ * H_ * H_];     // W_tp fp16, [i][j][k]
__device__ int   g_seg[G_ + 1];
__device__ int   g_tblg[256];
__device__ int   g_tbln[256];
__device__ int   g_nblk;

#define RSTRIDE 144   // 72 fp16 row stride (bytes)

// ---------------- PTX helpers ----------------
__device__ __forceinline__ uint32_t smem_u32(const void* p) {
    uint32_t a;
    asm("{ .reg .u64 t; cvta.to.shared.u64 t, %1; cvt.u32.u64 %0, t; }" : "=r"(a) : "l"(p));
    return a;
}
#define LDSM_X4(r, addr) \
    asm volatile("ldmatrix.sync.aligned.m8n8.x4.shared.b16 {%0,%1,%2,%3}, [%4];" \
        : "=r"((r)[0]), "=r"((r)[1]), "=r"((r)[2]), "=r"((r)[3]) : "r"(addr))
#define LDSM_X4T(r, addr) \
    asm volatile("ldmatrix.sync.aligned.m8n8.x4.trans.shared.b16 {%0,%1,%2,%3}, [%4];" \
        : "=r"((r)[0]), "=r"((r)[1]), "=r"((r)[2]), "=r"((r)[3]) : "r"(addr))

__device__ __forceinline__ void mma16816h(float* d, const uint32_t* a, const uint32_t* b) {
    asm volatile(
        "mma.sync.aligned.m16n8k16.row.col.f32.f16.f16.f32 "
        "{%0,%1,%2,%3}, {%4,%5,%6,%7}, {%8,%9}, {%0,%1,%2,%3};"
        : "+f"(d[0]), "+f"(d[1]), "+f"(d[2]), "+f"(d[3])
        : "r"(a[0]), "r"(a[1]), "r"(a[2]), "r"(a[3]), "r"(b[0]), "r"(b[1]));
}

// ---------------- K0: fused prep (+ zeroing of g_updf and d_out) --------------
__global__ void k_prep(const float* __restrict__ Wqkv, const float* __restrict__ Wro,
                       const float* __restrict__ Wtp, const int* __restrict__ batch,
                       float* __restrict__ out) {
    int bid = blockIdx.x;
    int tid = threadIdx.x;       // 256
    if (bid < 48) {
        __shared__ float srow[4][64];
        int rr = tid >> 6, m = tid & 63;
        int r = bid * 4 + rr;
        srow[rr][m] = Wqkv[r * H_ + m];
        __syncthreads();
        float s = 0.f;
#pragma unroll 8
        for (int u = 0; u < H_; u++) s += srow[rr][u] * Wro[u * H_ + m];
        g_A[m * TH_ + r] = s;
    } else if (bid < 112) {
        int i = bid - 48;
        __shared__ float s[64 * 65];
#pragma unroll
        for (int p = 0; p < 16; p++) {
            int l = p * 256 + tid;
            int k = l >> 6, j = l & 63;
            s[k * 65 + j] = Wtp[k * 4096 + i * 64 + j];
        }
        __syncthreads();
#pragma unroll
        for (int p = 0; p < 16; p++) {
            int l = p * 256 + tid;
            int j = l >> 6, k = l & 63;
            g_B16[i * 4096 + j * 64 + k] = __float2half_rn(s[k * 65 + j]);
        }
    } else if (bid == 112) {
        if (tid <= G_) {
            int lo = 0, hi = N_;
            while (lo < hi) {
                int mid = (lo + hi) >> 1;
                if (batch[mid] < tid) lo = mid + 1; else hi = mid;
            }
            g_seg[tid] = lo;
        }
        __syncthreads();
        if (tid == 0) {
            int b = 0;
            for (int gg = 0; gg < G_; gg++)
                for (int s0 = g_seg[gg]; s0 < g_seg[gg + 1]; s0 += 64) {
                    g_tblg[b] = gg; g_tbln[b] = s0; b++;
                }
            g_nblk = b;
        }
    } else if (bid < 129) {
        float4* dst = (float4*)g_updf + (bid - 113) * 4096;
#pragma unroll
        for (int p = 0; p < 16; p++) dst[p * 256 + tid] = make_float4(0.f, 0.f, 0.f, 0.f);
    } else {
        float4* dst = (float4*)out + (bid - 129) * 4096;
#pragma unroll
        for (int p = 0; p < 16; p++) dst[p * 256 + tid] = make_float4(0.f, 0.f, 0.f, 0.f);
    }
}

// ---------------- K1: qkv tiled GEMM (32 nodes/block) + silu + rope -----------
#define QKV_SA   0
#define QKV_NF   49152
#define QKV_QKV  58368
#define QKV_C    83968
#define QKV_S    84992
#define QKV_SMEM 86016

__global__ void __launch_bounds__(256) k_qkv(const float* __restrict__ node_feat,
                                             const float* __restrict__ positions,
                                             const float* __restrict__ kvecs,
                                             const int*   __restrict__ batch) {
    extern __shared__ char sm[];
    float* s_A   = (float*)(sm + QKV_SA);
    float* s_nfT = (float*)(sm + QKV_NF);
    float* s_qkv = (float*)(sm + QKV_QKV);
    float* s_c   = (float*)(sm + QKV_C);
    float* s_s   = (float*)(sm + QKV_S);
    int tid = threadIdx.x;       // 256
    int n0 = blockIdx.x * 32;

#pragma unroll
    for (int p = 0; p < 48; p++) s_A[p * 256 + tid] = g_A[p * 256 + tid];
#pragma unroll
    for (int p = 0; p < 8; p++) {
        int l = p * 256 + tid;
        int nn = l >> 6, k = l & 63;
        s_nfT[k * 36 + nn] = node_feat[(n0 + nn) * H_ + k];
    }
    __syncthreads();

    int tn = tid >> 5, tr = tid & 31;
    float acc[4][6];
#pragma unroll
    for (int nn = 0; nn < 4; nn++)
#pragma unroll
        for (int u = 0; u < 6; u++) acc[nn][u] = 0.f;

#pragma unroll 4
    for (int k = 0; k < 64; k++) {
        float4 nf4 = *(const float4*)&s_nfT[k * 36 + tn * 4];
        float av[6];
#pragma unroll
        for (int u = 0; u < 6; u++) av[u] = s_A[k * 192 + tr + 32 * u];
#pragma unroll
        for (int u = 0; u < 6; u++) {
            acc[0][u] += nf4.x * av[u];
            acc[1][u] += nf4.y * av[u];
            acc[2][u] += nf4.z * av[u];
            acc[3][u] += nf4.w * av[u];
        }
    }
    __syncthreads();

#pragma unroll
    for (int nn = 0; nn < 4; nn++) {
        int node = tn * 4 + nn;
#pragma unroll
        for (int u = 0; u < 6; u++) {
            int r = tr + 32 * u;
            float v = acc[nn][u];
            if (r < 2 * H_) v = v / (1.f + __expf(-v));
            s_qkv[node * 200 + r] = v;
        }
    }
    if (tid < 192) {
        int nn = tid / 6, t = tid % 6;
        int g = batch[n0 + nn];
        const float* kv = kvecs + (g * T_ + t) * 3;
        float ph = positions[(n0 + nn) * 3 + 0] * kv[0]
                 + positions[(n0 + nn) * 3 + 1] * kv[1]
                 + positions[(n0 + nn) * 3 + 2] * kv[2];
        float sv, cv;
        sincosf(ph, &sv, &cv);
        s_c[nn * 8 + t] = cv; s_s[nn * 8 + t] = sv;
    }
    __syncthreads();

#pragma unroll
    for (int p = 0; p < 48; p++) {
        int l = p * 256 + tid;
        int nn = l / 384, idx = l - nn * 384;
        int t = idx >> 6, d = idx & 63;
        int m2 = (d & 31) * 2;
        float c = s_c[nn * 8 + t], sv = s_s[nn * 8 + t];
        float qa = s_qkv[nn * 200 + m2],       qb = s_qkv[nn * 200 + m2 + 1];
        float ka = s_qkv[nn * 200 + 64 + m2],  kb = s_qkv[nn * 200 + 64 + m2 + 1];
        float qv, kvv;
        if (d < 32) { qv = qa * c  - qb * sv;  kvv = ka * c  - kb * sv; }
        else        { qv = qa * sv + qb * c;   kvv = ka * sv + kb * c;  }
        int n = n0 + nn;
        g_qr16[n * TD_ + idx] = __float2half_rn(qv * 0.125f);
        g_k16 [n * TD_ + idx] = __float2half_rn(kvv);
    }
#pragma unroll
    for (int p = 0; p < 8; p++) {
        int l = p * 256 + tid;
        int nn = l >> 6, m = l & 63;
        g_v16[(n0 + nn) * H_ + m] = __float2half_rn(s_qkv[nn * 200 + 128 + m]);
    }
}

// ---------------- K2: kv_graph via HMMA, 64-node chunks ----------------------
// C[64d x 64e] = sum_n k^T v per (g,t) block
#define KVG_KT 0        // 64 rows x 144B = 9216
#define KVG_V  9216     // 64 rows x 144B = 9216

__global__ void __launch_bounds__(256) k_kvg() {
    __shared__ __align__(16) char sm[18432];
    uint32_t sb = smem_u32(sm);
    int bid = blockIdx.x;
    int g = bid / T_, t = bid % T_;
    int tid = threadIdx.x;
    int lane = tid & 31, w = tid >> 5;
    int wm = w & 3, wn = w >> 2;          // m16 of d, e32 half

    int s = g_seg[g], e = g_seg[g + 1];
    int nb0 = s & ~63;

    int rfr = (lane & 7) + ((lane >> 3) & 1) * 8;
    int cfr = (lane >> 4) * 16;

    float acc[4][4];
#pragma unroll
    for (int nt = 0; nt < 4; nt++)
#pragma unroll
        for (int q = 0; q < 4; q++) acc[nt][q] = 0.f;

    int pp = tid & 31, oo = tid >> 5;     // n-pair 0..31, d-oct 0..7

    for (int nb = nb0; nb < e; nb += 64) {
        // kT fill: transpose k[n][d] -> kT[d][n], rows masked to [s,e)
        int n1 = nb + 2 * pp, n2 = n1 + 1;
        uint4 ra = make_uint4(0u,0u,0u,0u), rb = ra;
        if (n1 >= s && n1 < e) ra = *(const uint4*)(g_k16 + n1 * TD_ + t * 64 + oo * 8);
        if (n2 >= s && n2 < e) rb = *(const uint4*)(g_k16 + n2 * TD_ + t * 64 + oo * 8);
        const __half* ah = (const __half*)&ra;
        const __half* bh = (const __half*)&rb;
#pragma unroll
        for (int dd = 0; dd < 8; dd++) {
            __half2 h = __halves2half2(ah[dd], bh[dd]);
            *(__half2*)(sm + KVG_KT + (oo * 8 + dd) * RSTRIDE + pp * 4) = h;
        }
        // v fill: 64 rows masked
#pragma unroll
        for (int p = 0; p < 2; p++) {
            int idx = p * 256 + tid;          // 0..511
            int r = idx >> 3, q8 = idx & 7;
            int n = nb + r;
            uint4 val = make_uint4(0u, 0u, 0u, 0u);
            if (n >= s && n < e) val = *(const uint4*)(g_v16 + n * H_ + q8 * 8);
            *(uint4*)(sm + KVG_V + r * RSTRIDE + q8 * 16) = val;
        }
        __syncthreads();

#pragma unroll
        for (int ks = 0; ks < 4; ks++) {
            uint32_t aF[4], bF[8];
            LDSM_X4(aF, sb + KVG_KT + (uint32_t)(wm * 16 + rfr) * RSTRIDE + cfr + ks * 32);
            LDSM_X4T(&bF[0], sb + KVG_V + (uint32_t)(ks * 16 + rfr) * RSTRIDE + wn * 64 + cfr);
            LDSM_X4T(&bF[4], sb + KVG_V + (uint32_t)(ks * 16 + rfr) * RSTRIDE + wn * 64 + 32 + cfr);
            mma16816h(acc[0], aF, &bF[0]);
            mma16816h(acc[1], aF, &bF[2]);
            mma16816h(acc[2], aF, &bF[4]);
            mma16816h(acc[3], aF, &bF[6]);
        }
        __syncthreads();
    }

    __half* outb = g_kvg16 + (g * TD_ + t * 64) * H_;
    int d0 = wm * 16 + (lane >> 2);
    int cb = 2 * (lane & 3);
#pragma unroll
    for (int nt = 0; nt < 4; nt++) {
        int ec = wn * 32 + nt * 8 + cb;
        *(__half2*)(outb + d0 * H_ + ec)       = __floats2half2_rn(acc[nt][0], acc[nt][1]);
        *(__half2*)(outb + (d0 + 8) * H_ + ec) = __floats2half2_rn(acc[nt][2], acc[nt][3]);
    }
}

// ---------------- K3: update partial via HMMA, 2 t-slices per block -----------
#define U2_Q  0        // 2 x 9216
#define U2_KV 18432    // 2 x 9216

__global__ void __launch_bounds__(256) k_upd2() {
    int sbi = blockIdx.x;
    if (sbi >= g_nblk) return;
    int t0 = blockIdx.y * 2;
    int g  = g_tblg[sbi];
    int ns = g_tbln[sbi];
    int ne = min(ns + 64, g_seg[g + 1]);

    __shared__ __align__(16) char sm[36864];
    uint32_t sbm = smem_u32(sm);
    int tid = threadIdx.x;       // 256
    int lane = tid & 31, w = tid >> 5;

#pragma unroll
    for (int sl = 0; sl < 2; sl++) {
        int t = t0 + sl;
        // q fill: 64 rows x 64 halves, zero rows >= ne
#pragma unroll
        for (int p = 0; p < 2; p++) {
            int idx = p * 256 + tid;
            int nl = idx >> 3, q8 = idx & 7;
            uint4 val = make_uint4(0u, 0u, 0u, 0u);
            if (ns + nl < ne) val = *(const uint4*)(g_qr16 + (ns + nl) * TD_ + t * 64 + q8 * 8);
            *(uint4*)(sm + U2_Q + sl * 9216 + nl * RSTRIDE + q8 * 16) = val;
        }
        const __half* kvsrc = g_kvg16 + (g * TD_ + t * 64) * H_;
#pragma unroll
        for (int p = 0; p < 2; p++) {
            int idx = p * 256 + tid;
            int r = idx >> 3, q8 = idx & 7;
            *(uint4*)(sm + U2_KV + sl * 9216 + r * RSTRIDE + q8 * 16) =
                *(const uint4*)(kvsrc + r * 64 + q8 * 8);
        }
    }
    __syncthreads();

    int wm = w & 3, weg = w >> 2;            // m16 tile, e32 half
    int rfr = (lane & 7) + ((lane >> 3) & 1) * 8;
    int cfr = (lane >> 4) * 16;

    float acc[4][4];
#pragma unroll
    for (int nt = 0; nt < 4; nt++)
#pragma unroll
        for (int q = 0; q < 4; q++) acc[nt][q] = 0.f;

#pragma unroll
    for (int sl = 0; sl < 2; sl++) {
        uint32_t aB = sbm + U2_Q  + sl * 9216 + (uint32_t)(wm * 16 + rfr) * RSTRIDE + cfr;
        uint32_t bB = sbm + U2_KV + sl * 9216 + (uint32_t)rfr * RSTRIDE + weg * 64 + cfr;
#pragma unroll
        for (int ks = 0; ks < 4; ks++) {
            uint32_t aF[4], bF[8];
            LDSM_X4(aF, aB + ks * 32);
            LDSM_X4T(&bF[0], bB + ks * (16 * RSTRIDE));
            LDSM_X4T(&bF[4], bB + ks * (16 * RSTRIDE) + 32);
            mma16816h(acc[0], aF, &bF[0]);
            mma16816h(acc[1], aF, &bF[2]);
            mma16816h(acc[2], aF, &bF[4]);
            mma16816h(acc[3], aF, &bF[6]);
        }
    }

    int r0 = wm * 16 + (lane >> 2);
    int cb = 2 * (lane & 3);
    int n1 = ns + r0, n2 = n1 + 8;
#pragma unroll
    for (int nt = 0; nt < 4; nt++) {
        int e = weg * 32 + nt * 8 + cb;
        if (n1 < ne) {
            atomicAdd(&g_updf[n1 * H_ + e],     acc[nt][0]);
            atomicAdd(&g_updf[n1 * H_ + e + 1], acc[nt][1]);
        }
        if (n2 < ne) {
            atomicAdd(&g_updf[n2 * H_ + e],     acc[nt][2]);
            atomicAdd(&g_updf[n2 * H_ + e + 1], acc[nt][3]);
        }
    }
}

// ---------------- K4: tensor-product GEMM, i-split x8, atomic output ----------
#define TP_U    0
#define TP_B0   18432
#define TP_B1   27648
#define TP_NF   36864
#define TP_SMEM 41984

__global__ void __launch_bounds__(256) k_tpmma(const float* __restrict__ nfsr,
                                               float* __restrict__ out) {
    extern __shared__ char smem[];
    uint32_t sb = smem_u32(smem);
    int tid = threadIdx.x;
    int wid = tid >> 5, lane = tid & 31;
    int n0 = blockIdx.x * 128;
    int i0 = blockIdx.y * 8;

    float* s_nf = (float*)(smem + TP_NF);     // [c][128], c<8

#pragma unroll
    for (int p = 0; p < 4; p++) {
        int l = p * 256 + tid;                 // 0..1023
        int nl = l >> 3, ii = l & 7;
        s_nf[ii * 128 + nl] = nfsr[(n0 + nl) * H_ + i0 + ii];
    }
    // build fp16 U tile from fp32 g_updf
#pragma unroll
    for (int p = 0; p < 4; p++) {
        int idx = p * 256 + tid;              // 0..1023
        int n = idx >> 3, q8 = idx & 7;
        const float4* src = (const float4*)(g_updf + (n0 + n) * H_ + q8 * 8);
        float4 u0 = src[0], u1 = src[1];
        __half2 h0 = __floats2half2_rn(u0.x, u0.y);
        __half2 h1 = __floats2half2_rn(u0.z, u0.w);
        __half2 h2 = __floats2half2_rn(u1.x, u1.y);
        __half2 h3 = __floats2half2_rn(u1.z, u1.w);
        uint4 val = make_uint4(*(uint32_t*)&h0, *(uint32_t*)&h1,
                               *(uint32_t*)&h2, *(uint32_t*)&h3);
        *(uint4*)(smem + TP_U + n * RSTRIDE + q8 * 16) = val;
    }
    {
        const uint4* bs = (const uint4*)(g_B16 + i0 * 4096);
        uint4 b0 = bs[tid], b1 = bs[tid + 256];
        int q = tid & 7;
        int ja = tid >> 3, jb = (tid + 256) >> 3;
        *(uint4*)(smem + TP_B0 + ja * RSTRIDE + q * 16) = b0;
        *(uint4*)(smem + TP_B0 + jb * RSTRIDE + q * 16) = b1;
    }
    __syncthreads();

    int m0 = wid * 16;
    int rfr = (lane & 7) + ((lane >> 3) & 1) * 8;
    int cfr = (lane >> 4) * 16;
    uint32_t aF[16];
    {
        uint32_t aAddr = sb + TP_U + (uint32_t)(m0 + rfr) * RSTRIDE + cfr;
#pragma unroll
        for (int ks = 0; ks < 4; ks++) LDSM_X4(&aF[ks * 4], aAddr + ks * 32);
    }

    float acc[8][4];
#pragma unroll
    for (int nt = 0; nt < 8; nt++)
#pragma unroll
        for (int q = 0; q < 4; q++) acc[nt][q] = 0.f;

    int rowl = m0 + (lane >> 2);
    int qb8 = tid & 7;
    int ja = tid >> 3, jb = (tid + 256) >> 3;

    for (int c = 0; c < 8; c++) {
        uint4 pfa, pfb;
        if (c < 7) {
            const uint4* bs = (const uint4*)(g_B16 + (i0 + c + 1) * 4096);
            pfa = bs[tid]; pfb = bs[tid + 256];
        }

        uint32_t bBase = sb + ((c & 1) ? TP_B1 : TP_B0) + (uint32_t)rfr * RSTRIDE + cfr;
        float ptmp[8][4];
#pragma unroll
        for (int nt = 0; nt < 8; nt++)
#pragma unroll
            for (int q = 0; q < 4; q++) ptmp[nt][q] = 0.f;

#pragma unroll
        for (int ks = 0; ks < 4; ks++) {
            uint32_t bF[16];
#pragma unroll
            for (int p = 0; p < 4; p++)
                LDSM_X4T(&bF[p * 4], bBase + ks * (16 * RSTRIDE) + p * 32);
#pragma unroll
            for (int nt = 0; nt < 8; nt++)
                mma16816h(ptmp[nt], &aF[ks * 4], &bF[(nt >> 1) * 4 + (nt & 1) * 2]);
        }

        float f0 = s_nf[c * 128 + rowl];
        float f1 = s_nf[c * 128 + rowl + 8];
#pragma unroll
        for (int nt = 0; nt < 8; nt++) {
            acc[nt][0] += f0 * ptmp[nt][0];
            acc[nt][1] += f0 * ptmp[nt][1];
            acc[nt][2] += f1 * ptmp[nt][2];
            acc[nt][3] += f1 * ptmp[nt][3];
        }

        if (c < 7) {
            char* dst = smem + ((c & 1) ? TP_B0 : TP_B1);
            *(uint4*)(dst + ja * RSTRIDE + qb8 * 16) = pfa;
            *(uint4*)(dst + jb * RSTRIDE + qb8 * 16) = pfb;
            __syncthreads();
        }
    }

    int row0 = n0 + m0 + (lane >> 2);
    int colb = 2 * (lane & 3);
#pragma unroll
    for (int nt = 0; nt < 8; nt++) {
        int col = nt * 8 + colb;
        atomicAdd(&out[row0 * H_ + col],           acc[nt][0]);
        atomicAdd(&out[row0 * H_ + col + 1],       acc[nt][1]);
        atomicAdd(&out[(row0 + 8) * H_ + col],     acc[nt][2]);
        atomicAdd(&out[(row0 + 8) * H_ + col + 1], acc[nt][3]);
    }
}

// ---------------- launch ----------------
extern "C" void kernel_launch(void* const* d_in, const int* in_sizes, int n_in,
                              void* d_out, int out_size) {
    const float* node_feat    = (const float*)d_in[0];
    const float* node_feat_sr = (const float*)d_in[1];
    const float* positions    = (const float*)d_in[2];
    const float* kvecs        = (const float*)d_in[3];
    const int*   batch        = (const int*)  d_in[4];
    const float* W_readout    = (const float*)d_in[5];
    const float* W_qkv        = (const float*)d_in[6];
    const float* W_tp         = (const float*)d_in[7];
    float* out = (float*)d_out;

    static int attr_done = 0;
    if (!attr_done) {
        cudaFuncSetAttribute(k_qkv, cudaFuncAttributeMaxDynamicSharedMemorySize, QKV_SMEM);
        attr_done = 1;
    }

    k_prep <<<145, 256>>>(W_qkv, W_readout, W_tp, batch, out);
    k_qkv  <<<N_ / 32, 256, QKV_SMEM>>>(node_feat, positions, kvecs, batch);
    k_kvg  <<<G_ * T_, 256>>>();
    k_upd2 <<<dim3(96, 3), 256>>>();
    k_tpmma<<<dim3(N_ / 128, 8), 256, TP_SMEM>>>(node_feat_sr, out);
}

// round 11
// speedup vs baseline: 4.2762x; 1.1080x over previous
#include <cuda_runtime.h>
#include <cuda_fp16.h>
#include <math.h>
#include <stdint.h>

#define N_  4096
#define H_  64
#define T_  6
#define G_  16
#define TH_ 192    // 3*H
#define TD_ 384    // T*H

// ---------------- device scratch ----------------
__device__ float g_A[H_ * TH_];            // A[m][r] = Wc[r][m]
__device__ __align__(16) __half g_qr16[N_ * TD_];       // q fp16 [n][t*64+d]
__device__ __align__(16) __half g_k16 [N_ * TD_];       // k fp16 [n][t*64+d]
__device__ __align__(16) __half g_v16 [N_ * H_];        // v fp16 [n][e]
__device__ __align__(16) float  g_updf[N_ * H_];        // update fp32 [n][e] (atomic)
__device__ __half g_B16[H_ * H_ * H_];     // W_tp fp16, [i][j][k]
__device__ int   g_seg[G_ + 1];

#define RSTRIDE 144   // 72 fp16 row stride (bytes)

// ---------------- PTX helpers ----------------
__device__ __forceinline__ uint32_t smem_u32(const void* p) {
    uint32_t a;
    asm("{ .reg .u64 t; cvta.to.shared.u64 t, %1; cvt.u32.u64 %0, t; }" : "=r"(a) : "l"(p));
    return a;
}
#define LDSM_X4(r, addr) \
    asm volatile("ldmatrix.sync.aligned.m8n8.x4.shared.b16 {%0,%1,%2,%3}, [%4];" \
        : "=r"((r)[0]), "=r"((r)[1]), "=r"((r)[2]), "=r"((r)[3]) : "r"(addr))
#define LDSM_X4T(r, addr) \
    asm volatile("ldmatrix.sync.aligned.m8n8.x4.trans.shared.b16 {%0,%1,%2,%3}, [%4];" \
        : "=r"((r)[0]), "=r"((r)[1]), "=r"((r)[2]), "=r"((r)[3]) : "r"(addr))

__device__ __forceinline__ void mma16816h(float* d, const uint32_t* a, const uint32_t* b) {
    asm volatile(
        "mma.sync.aligned.m16n8k16.row.col.f32.f16.f16.f32 "
        "{%0,%1,%2,%3}, {%4,%5,%6,%7}, {%8,%9}, {%0,%1,%2,%3};"
        : "+f"(d[0]), "+f"(d[1]), "+f"(d[2]), "+f"(d[3])
        : "r"(a[0]), "r"(a[1]), "r"(a[2]), "r"(a[3]), "r"(b[0]), "r"(b[1]));
}

// ---------------- K0: fused prep (+ zeroing of g_updf and d_out) --------------
__global__ void k_prep(const float* __restrict__ Wqkv, const float* __restrict__ Wro,
                       const float* __restrict__ Wtp, const int* __restrict__ batch,
                       float* __restrict__ out) {
    int bid = blockIdx.x;
    int tid = threadIdx.x;       // 256
    if (bid < 48) {
        __shared__ float srow[4][64];
        int rr = tid >> 6, m = tid & 63;
        int r = bid * 4 + rr;
        srow[rr][m] = Wqkv[r * H_ + m];
        __syncthreads();
        float s = 0.f;
#pragma unroll 8
        for (int u = 0; u < H_; u++) s += srow[rr][u] * Wro[u * H_ + m];
        g_A[m * TH_ + r] = s;
    } else if (bid < 112) {
        int i = bid - 48;
        __shared__ float s[64 * 65];
#pragma unroll
        for (int p = 0; p < 16; p++) {
            int l = p * 256 + tid;
            int k = l >> 6, j = l & 63;
            s[k * 65 + j] = Wtp[k * 4096 + i * 64 + j];
        }
        __syncthreads();
#pragma unroll
        for (int p = 0; p < 16; p++) {
            int l = p * 256 + tid;
            int j = l >> 6, k = l & 63;
            g_B16[i * 4096 + j * 64 + k] = __float2half_rn(s[k * 65 + j]);
        }
    } else if (bid == 112) {
        if (tid <= G_) {
            int lo = 0, hi = N_;
            while (lo < hi) {
                int mid = (lo + hi) >> 1;
                if (batch[mid] < tid) lo = mid + 1; else hi = mid;
            }
            g_seg[tid] = lo;
        }
    } else if (bid < 129) {
        float4* dst = (float4*)g_updf + (bid - 113) * 4096;
#pragma unroll
        for (int p = 0; p < 16; p++) dst[p * 256 + tid] = make_float4(0.f, 0.f, 0.f, 0.f);
    } else {
        float4* dst = (float4*)out + (bid - 129) * 4096;
#pragma unroll
        for (int p = 0; p < 16; p++) dst[p * 256 + tid] = make_float4(0.f, 0.f, 0.f, 0.f);
    }
}

// ---------------- K1: qkv tiled GEMM (32 nodes/block) + silu + rope -----------
#define QKV_SA   0
#define QKV_NF   49152
#define QKV_QKV  58368
#define QKV_C    83968
#define QKV_S    84992
#define QKV_SMEM 86016

__global__ void __launch_bounds__(256) k_qkv(const float* __restrict__ node_feat,
                                             const float* __restrict__ positions,
                                             const float* __restrict__ kvecs,
                                             const int*   __restrict__ batch) {
    extern __shared__ char sm[];
    float* s_A   = (float*)(sm + QKV_SA);
    float* s_nfT = (float*)(sm + QKV_NF);
    float* s_qkv = (float*)(sm + QKV_QKV);
    float* s_c   = (float*)(sm + QKV_C);
    float* s_s   = (float*)(sm + QKV_S);
    int tid = threadIdx.x;       // 256
    int n0 = blockIdx.x * 32;

#pragma unroll
    for (int p = 0; p < 48; p++) s_A[p * 256 + tid] = g_A[p * 256 + tid];
#pragma unroll
    for (int p = 0; p < 8; p++) {
        int l = p * 256 + tid;
        int nn = l >> 6, k = l & 63;
        s_nfT[k * 36 + nn] = node_feat[(n0 + nn) * H_ + k];
    }
    __syncthreads();

    int tn = tid >> 5, tr = tid & 31;
    float acc[4][6];
#pragma unroll
    for (int nn = 0; nn < 4; nn++)
#pragma unroll
        for (int u = 0; u < 6; u++) acc[nn][u] = 0.f;

#pragma unroll 4
    for (int k = 0; k < 64; k++) {
        float4 nf4 = *(const float4*)&s_nfT[k * 36 + tn * 4];
        float av[6];
#pragma unroll
        for (int u = 0; u < 6; u++) av[u] = s_A[k * 192 + tr + 32 * u];
#pragma unroll
        for (int u = 0; u < 6; u++) {
            acc[0][u] += nf4.x * av[u];
            acc[1][u] += nf4.y * av[u];
            acc[2][u] += nf4.z * av[u];
            acc[3][u] += nf4.w * av[u];
        }
    }
    __syncthreads();

#pragma unroll
    for (int nn = 0; nn < 4; nn++) {
        int node = tn * 4 + nn;
#pragma unroll
        for (int u = 0; u < 6; u++) {
            int r = tr + 32 * u;
            float v = acc[nn][u];
            if (r < 2 * H_) v = v / (1.f + __expf(-v));
            s_qkv[node * 200 + r] = v;
        }
    }
    if (tid < 192) {
        int nn = tid / 6, t = tid % 6;
        int g = batch[n0 + nn];
        const float* kv = kvecs + (g * T_ + t) * 3;
        float ph = positions[(n0 + nn) * 3 + 0] * kv[0]
                 + positions[(n0 + nn) * 3 + 1] * kv[1]
                 + positions[(n0 + nn) * 3 + 2] * kv[2];
        float sv, cv;
        sincosf(ph, &sv, &cv);
        s_c[nn * 8 + t] = cv; s_s[nn * 8 + t] = sv;
    }
    __syncthreads();

#pragma unroll
    for (int p = 0; p < 48; p++) {
        int l = p * 256 + tid;
        int nn = l / 384, idx = l - nn * 384;
        int t = idx >> 6, d = idx & 63;
        int m2 = (d & 31) * 2;
        float c = s_c[nn * 8 + t], sv = s_s[nn * 8 + t];
        float qa = s_qkv[nn * 200 + m2],       qb = s_qkv[nn * 200 + m2 + 1];
        float ka = s_qkv[nn * 200 + 64 + m2],  kb = s_qkv[nn * 200 + 64 + m2 + 1];
        float qv, kvv;
        if (d < 32) { qv = qa * c  - qb * sv;  kvv = ka * c  - kb * sv; }
        else        { qv = qa * sv + qb * c;   kvv = ka * sv + kb * c;  }
        int n = n0 + nn;
        g_qr16[n * TD_ + idx] = __float2half_rn(qv * 0.125f);
        g_k16 [n * TD_ + idx] = __float2half_rn(kvv);
    }
#pragma unroll
    for (int p = 0; p < 8; p++) {
        int l = p * 256 + tid;
        int nn = l >> 6, m = l & 63;
        g_v16[(n0 + nn) * H_ + m] = __float2half_rn(s_qkv[nn * 200 + 128 + m]);
    }
}

// ---------------- K2: FUSED kv_graph + update, per (g,t) block ----------------
// Phase 1: C[64d x 64e] = sum_n k[n,t,d] v[n,e]  (HMMA over 64-node chunks)
// tile -> smem fp16; Phase 2: updf[n,e] += q[n,t,:] @ C  (HMMA, atomic out)
#define KU_KT   0        // phase1 kT: 64 x 144 = 9216 ; phase2: reused as TILE
#define KU_V    9216     // phase1 v : 64 x 144 = 9216 ; phase2: reused as Q
#define KU_SMEM 18432

__global__ void __launch_bounds__(256) k_kvgupd() {
    __shared__ __align__(16) char sm[KU_SMEM];
    uint32_t sb = smem_u32(sm);
    int bid = blockIdx.x;
    int g = bid / T_, t = bid % T_;
    int tid = threadIdx.x;
    int lane = tid & 31, w = tid >> 5;
    int wm = w & 3, wn = w >> 2;          // phase1: m16 of d, e32 half

    int s = g_seg[g], e = g_seg[g + 1];
    int nb0 = s & ~63;

    int rfr = (lane & 7) + ((lane >> 3) & 1) * 8;
    int cfr = (lane >> 4) * 16;

    float acc[4][4];
#pragma unroll
    for (int nt = 0; nt < 4; nt++)
#pragma unroll
        for (int q = 0; q < 4; q++) acc[nt][q] = 0.f;

    int pp = tid & 31, oo = tid >> 5;     // n-pair 0..31, d-oct 0..7

    // ===== Phase 1: kv_graph tile =====
    for (int nb = nb0; nb < e; nb += 64) {
        int n1 = nb + 2 * pp, n2 = n1 + 1;
        uint4 ra = make_uint4(0u,0u,0u,0u), rb = ra;
        if (n1 >= s && n1 < e) ra = *(const uint4*)(g_k16 + n1 * TD_ + t * 64 + oo * 8);
        if (n2 >= s && n2 < e) rb = *(const uint4*)(g_k16 + n2 * TD_ + t * 64 + oo * 8);
        const __half* ah = (const __half*)&ra;
        const __half* bh = (const __half*)&rb;
#pragma unroll
        for (int dd = 0; dd < 8; dd++) {
            __half2 h = __halves2half2(ah[dd], bh[dd]);
            *(__half2*)(sm + KU_KT + (oo * 8 + dd) * RSTRIDE + pp * 4) = h;
        }
#pragma unroll
        for (int p = 0; p < 2; p++) {
            int idx = p * 256 + tid;
            int r = idx >> 3, q8 = idx & 7;
            int n = nb + r;
            uint4 val = make_uint4(0u, 0u, 0u, 0u);
            if (n >= s && n < e) val = *(const uint4*)(g_v16 + n * H_ + q8 * 8);
            *(uint4*)(sm + KU_V + r * RSTRIDE + q8 * 16) = val;
        }
        __syncthreads();

#pragma unroll
        for (int ks = 0; ks < 4; ks++) {
            uint32_t aF[4], bF[8];
            LDSM_X4(aF, sb + KU_KT + (uint32_t)(wm * 16 + rfr) * RSTRIDE + cfr + ks * 32);
            LDSM_X4T(&bF[0], sb + KU_V + (uint32_t)(ks * 16 + rfr) * RSTRIDE + wn * 64 + cfr);
            LDSM_X4T(&bF[4], sb + KU_V + (uint32_t)(ks * 16 + rfr) * RSTRIDE + wn * 64 + 32 + cfr);
            mma16816h(acc[0], aF, &bF[0]);
            mma16816h(acc[1], aF, &bF[2]);
            mma16816h(acc[2], aF, &bF[4]);
            mma16816h(acc[3], aF, &bF[6]);
        }
        __syncthreads();
    }

    // ===== write tile to smem fp16 (reuse KU_KT region: [64 d rows][64 e]) =====
    {
        int d0 = wm * 16 + (lane >> 2);
        int cb = 2 * (lane & 3);
#pragma unroll
        for (int nt = 0; nt < 4; nt++) {
            int ec = wn * 32 + nt * 8 + cb;
            *(__half2*)(sm + KU_KT + d0 * RSTRIDE + ec * 2) =
                __floats2half2_rn(acc[nt][0], acc[nt][1]);
            *(__half2*)(sm + KU_KT + (d0 + 8) * RSTRIDE + ec * 2) =
                __floats2half2_rn(acc[nt][2], acc[nt][3]);
        }
    }
    __syncthreads();

    // ===== Phase 2: updf[n,e] += q[n, t*64: ] @ tile, per 64-node chunk =====
    // warps: wm = n m16-tile (4), weg = e32 half (2)
    int weg = wn;
    for (int nb = nb0; nb < e; nb += 64) {
        // fill Q rows [64 x 64] masked (into KU_V region)
#pragma unroll
        for (int p = 0; p < 2; p++) {
            int idx = p * 256 + tid;
            int nl = idx >> 3, q8 = idx & 7;
            int n = nb + nl;
            uint4 val = make_uint4(0u, 0u, 0u, 0u);
            if (n >= s && n < e) val = *(const uint4*)(g_qr16 + n * TD_ + t * 64 + q8 * 8);
            *(uint4*)(sm + KU_V + nl * RSTRIDE + q8 * 16) = val;
        }
        __syncthreads();

        float pacc[4][4];
#pragma unroll
        for (int nt = 0; nt < 4; nt++)
#pragma unroll
            for (int q = 0; q < 4; q++) pacc[nt][q] = 0.f;

        uint32_t aB = sb + KU_V  + (uint32_t)(wm * 16 + rfr) * RSTRIDE + cfr;
        uint32_t bB = sb + KU_KT + (uint32_t)rfr * RSTRIDE + weg * 64 + cfr;
#pragma unroll
        for (int ks = 0; ks < 4; ks++) {
            uint32_t aF[4], bF[8];
            LDSM_X4(aF, aB + ks * 32);
            LDSM_X4T(&bF[0], bB + ks * (16 * RSTRIDE));
            LDSM_X4T(&bF[4], bB + ks * (16 * RSTRIDE) + 32);
            mma16816h(pacc[0], aF, &bF[0]);
            mma16816h(pacc[1], aF, &bF[2]);
            mma16816h(pacc[2], aF, &bF[4]);
            mma16816h(pacc[3], aF, &bF[6]);
        }

        int r0 = wm * 16 + (lane >> 2);
        int cb = 2 * (lane & 3);
        int n1 = nb + r0, n2 = n1 + 8;
#pragma unroll
        for (int nt = 0; nt < 4; nt++) {
            int ec = weg * 32 + nt * 8 + cb;
            if (n1 >= s && n1 < e) {
                atomicAdd(&g_updf[n1 * H_ + ec],     pacc[nt][0]);
                atomicAdd(&g_updf[n1 * H_ + ec + 1], pacc[nt][1]);
            }
            if (n2 >= s && n2 < e) {
                atomicAdd(&g_updf[n2 * H_ + ec],     pacc[nt][2]);
                atomicAdd(&g_updf[n2 * H_ + ec + 1], pacc[nt][3]);
            }
        }
        __syncthreads();
    }
}

// ---------------- K3: tensor-product GEMM, i-split x8, atomic output ----------
#define TP_U    0
#define TP_B0   18432
#define TP_B1   27648
#define TP_NF   36864
#define TP_SMEM 41984

__global__ void __launch_bounds__(256) k_tpmma(const float* __restrict__ nfsr,
                                               float* __restrict__ out) {
    extern __shared__ char smem[];
    uint32_t sb = smem_u32(smem);
    int tid = threadIdx.x;
    int wid = tid >> 5, lane = tid & 31;
    int n0 = blockIdx.x * 128;
    int i0 = blockIdx.y * 8;

    float* s_nf = (float*)(smem + TP_NF);     // [c][128], c<8

#pragma unroll
    for (int p = 0; p < 4; p++) {
        int l = p * 256 + tid;                 // 0..1023
        int nl = l >> 3, ii = l & 7;
        s_nf[ii * 128 + nl] = nfsr[(n0 + nl) * H_ + i0 + ii];
    }
    // build fp16 U tile from fp32 g_updf
#pragma unroll
    for (int p = 0; p < 4; p++) {
        int idx = p * 256 + tid;              // 0..1023
        int n = idx >> 3, q8 = idx & 7;
        const float4* src = (const float4*)(g_updf + (n0 + n) * H_ + q8 * 8);
        float4 u0 = src[0], u1 = src[1];
        __half2 h0 = __floats2half2_rn(u0.x, u0.y);
        __half2 h1 = __floats2half2_rn(u0.z, u0.w);
        __half2 h2 = __floats2half2_rn(u1.x, u1.y);
        __half2 h3 = __floats2half2_rn(u1.z, u1.w);
        uint4 val = make_uint4(*(uint32_t*)&h0, *(uint32_t*)&h1,
                               *(uint32_t*)&h2, *(uint32_t*)&h3);
        *(uint4*)(smem + TP_U + n * RSTRIDE + q8 * 16) = val;
    }
    {
        const uint4* bs = (const uint4*)(g_B16 + i0 * 4096);
        uint4 b0 = bs[tid], b1 = bs[tid + 256];
        int q = tid & 7;
        int ja = tid >> 3, jb = (tid + 256) >> 3;
        *(uint4*)(smem + TP_B0 + ja * RSTRIDE + q * 16) = b0;
        *(uint4*)(smem + TP_B0 + jb * RSTRIDE + q * 16) = b1;
    }
    __syncthreads();

    int m0 = wid * 16;
    int rfr = (lane & 7) + ((lane >> 3) & 1) * 8;
    int cfr = (lane >> 4) * 16;
    uint32_t aF[16];
    {
        uint32_t aAddr = sb + TP_U + (uint32_t)(m0 + rfr) * RSTRIDE + cfr;
#pragma unroll
        for (int ks = 0; ks < 4; ks++) LDSM_X4(&aF[ks * 4], aAddr + ks * 32);
    }

    float acc[8][4];
#pragma unroll
    for (int nt = 0; nt < 8; nt++)
#pragma unroll
        for (int q = 0; q < 4; q++) acc[nt][q] = 0.f;

    int rowl = m0 + (lane >> 2);
    int qb8 = tid & 7;
    int ja = tid >> 3, jb = (tid + 256) >> 3;

    for (int c = 0; c < 8; c++) {
        uint4 pfa, pfb;
        if (c < 7) {
            const uint4* bs = (const uint4*)(g_B16 + (i0 + c + 1) * 4096);
            pfa = bs[tid]; pfb = bs[tid + 256];
        }

        uint32_t bBase = sb + ((c & 1) ? TP_B1 : TP_B0) + (uint32_t)rfr * RSTRIDE + cfr;
        float ptmp[8][4];
#pragma unroll
        for (int nt = 0; nt < 8; nt++)
#pragma unroll
            for (int q = 0; q < 4; q++) ptmp[nt][q] = 0.f;

#pragma unroll
        for (int ks = 0; ks < 4; ks++) {
            uint32_t bF[16];
#pragma unroll
            for (int p = 0; p < 4; p++)
                LDSM_X4T(&bF[p * 4], bBase + ks * (16 * RSTRIDE) + p * 32);
#pragma unroll
            for (int nt = 0; nt < 8; nt++)
                mma16816h(ptmp[nt], &aF[ks * 4], &bF[(nt >> 1) * 4 + (nt & 1) * 2]);
        }

        float f0 = s_nf[c * 128 + rowl];
        float f1 = s_nf[c * 128 + rowl + 8];
#pragma unroll
        for (int nt = 0; nt < 8; nt++) {
            acc[nt][0] += f0 * ptmp[nt][0];
            acc[nt][1] += f0 * ptmp[nt][1];
            acc[nt][2] += f1 * ptmp[nt][2];
            acc[nt][3] += f1 * ptmp[nt][3];
        }

        if (c < 7) {
            char* dst = smem + ((c & 1) ? TP_B0 : TP_B1);
            *(uint4*)(dst + ja * RSTRIDE + qb8 * 16) = pfa;
            *(uint4*)(dst + jb * RSTRIDE + qb8 * 16) = pfb;
            __syncthreads();
        }
    }

    int row0 = n0 + m0 + (lane >> 2);
    int colb = 2 * (lane & 3);
#pragma unroll
    for (int nt = 0; nt < 8; nt++) {
        int col = nt * 8 + colb;
        atomicAdd(&out[row0 * H_ + col],           acc[nt][0]);
        atomicAdd(&out[row0 * H_ + col + 1],       acc[nt][1]);
        atomicAdd(&out[(row0 + 8) * H_ + col],     acc[nt][2]);
        atomicAdd(&out[(row0 + 8) * H_ + col + 1], acc[nt][3]);
    }
}

// ---------------- launch ----------------
extern "C" void kernel_launch(void* const* d_in, const int* in_sizes, int n_in,
                              void* d_out, int out_size) {
    const float* node_feat    = (const float*)d_in[0];
    const float* node_feat_sr = (const float*)d_in[1];
    const float* positions    = (const float*)d_in[2];
    const float* kvecs        = (const float*)d_in[3];
    const int*   batch        = (const int*)  d_in[4];
    const float* W_readout    = (const float*)d_in[5];
    const float* W_qkv        = (const float*)d_in[6];
    const float* W_tp         = (const float*)d_in[7];
    float* out = (float*)d_out;

    static int attr_done = 0;
    if (!attr_done) {
        cudaFuncSetAttribute(k_qkv, cudaFuncAttributeMaxDynamicSharedMemorySize, QKV_SMEM);
        attr_done = 1;
    }

    k_prep   <<<145, 256>>>(W_qkv, W_readout, W_tp, batch, out);
    k_qkv    <<<N_ / 32, 256, QKV_SMEM>>>(node_feat, positions, kvecs, batch);
    k_kvgupd <<<G_ * T_, 256>>>();
    k_tpmma  <<<dim3(N_ / 128, 8), 256, TP_SMEM>>>(node_feat_sr, out);
}